// round 1
// baseline (speedup 1.0000x reference)
#include <cuda_runtime.h>
#include <math.h>

// Fixed problem shapes
#define BB 2
#define SS 2048
#define DD 1024
#define HH 16
#define DK 64
#define DFF 4096
#define ROWS (BB*SS)          // 4096
#define ZTOT (BB*HH)          // 32

// ---------------- scratch (device globals; no allocation allowed) ----------
__device__ float g_q  [ROWS*DD];
__device__ float g_k  [ROWS*DD];
__device__ float g_v  [ROWS*DD];
__device__ float g_ctx[ROWS*DD];
__device__ float g_t0 [ROWS*DD];
__device__ float g_x1 [ROWS*DD];
__device__ float g_ff1[ROWS*DFF];
__device__ float g_gate[ZTOT*SS];
__device__ float g_scores[(long long)ZTOT*SS*SS]; // 512 MB

// ---------------- generic tiled GEMM -----------------
// C[M,N] = A[M,K] @ B[K,N] (or A @ B^T if TRANSB, with B[N,K])
// Batched over blockIdx.z: z -> (zb = z/H, zh = z%H), per-operand strides.
// EPI: 0 = +bias (if non-null), 1 = +bias then exact GELU,
//      2 = scores epilogue: v/temp, mask==0 -> -1e9, then *gate[row]
#define Bb 64
#define Bn 64
#define Bk 16

template<int EPI, bool TRANSB>
__global__ void __launch_bounds__(256)
gemm64(const float* __restrict__ A, const float* __restrict__ B, float* __restrict__ C,
       int M, int N, int K, int lda, int ldb, int ldc,
       long long sAb, long long sAh, long long sBb, long long sBh,
       long long sCb, long long sCh, int H,
       const float* __restrict__ bias,
       const int* __restrict__ mask, const float* __restrict__ gate,
       const float* __restrict__ temp, int S)
{
    int z  = blockIdx.z;
    int zb = z / H, zh = z % H;
    A += zb * sAb + zh * sAh;
    B += zb * sBb + zh * sBh;
    C += zb * sCb + zh * sCh;
    const float* gaterow = (EPI == 2) ? gate + (long long)z * S : nullptr;

    __shared__ float As[Bk][Bb];
    __shared__ float Bs[Bk][Bn];

    int t  = threadIdx.x;
    int tx = t & 15, ty = t >> 4;
    int m0 = blockIdx.y * Bb, n0 = blockIdx.x * Bn;

    float acc[4][4] = {};

    for (int k0 = 0; k0 < K; k0 += Bk) {
        // A tile -> As[k][m] (transposed store for contiguous compute reads)
        {
            int ar = t >> 2, akq = (t & 3) * 4;
            float4 av = *reinterpret_cast<const float4*>(
                &A[(long long)(m0 + ar) * lda + k0 + akq]);
            As[akq + 0][ar] = av.x; As[akq + 1][ar] = av.y;
            As[akq + 2][ar] = av.z; As[akq + 3][ar] = av.w;
        }
        if (TRANSB) {
            int bn = t >> 2, bkq = (t & 3) * 4;
            float4 bv = *reinterpret_cast<const float4*>(
                &B[(long long)(n0 + bn) * ldb + k0 + bkq]);
            Bs[bkq + 0][bn] = bv.x; Bs[bkq + 1][bn] = bv.y;
            Bs[bkq + 2][bn] = bv.z; Bs[bkq + 3][bn] = bv.w;
        } else {
            int bk = t >> 4, bnq = (t & 15) * 4;
            *reinterpret_cast<float4*>(&Bs[bk][bnq]) =
                *reinterpret_cast<const float4*>(
                    &B[(long long)(k0 + bk) * ldb + n0 + bnq]);
        }
        __syncthreads();

        #pragma unroll
        for (int kk = 0; kk < Bk; kk++) {
            float4 a4 = *reinterpret_cast<const float4*>(&As[kk][ty * 4]);
            float4 b4 = *reinterpret_cast<const float4*>(&Bs[kk][tx * 4]);
            float av[4] = {a4.x, a4.y, a4.z, a4.w};
            float bv[4] = {b4.x, b4.y, b4.z, b4.w};
            #pragma unroll
            for (int i = 0; i < 4; i++)
                #pragma unroll
                for (int j = 0; j < 4; j++)
                    acc[i][j] += av[i] * bv[j];
        }
        __syncthreads();
    }

    float invT = (EPI == 2) ? (1.0f / temp[0]) : 1.0f;
    #pragma unroll
    for (int i = 0; i < 4; i++) {
        int row = m0 + ty * 4 + i;
        #pragma unroll
        for (int j = 0; j < 4; j++) {
            int col = n0 + tx * 4 + j;
            float v = acc[i][j];
            if (EPI == 0 || EPI == 1) { if (bias) v += bias[col]; }
            if (EPI == 1) v = 0.5f * v * (1.0f + erff(v * 0.70710678118654752f));
            if (EPI == 2) {
                v *= invT;
                if (mask[(long long)row * S + col] == 0) v = -1e9f;
                v *= gaterow[row];
            }
            C[(long long)row * ldc + col] = v;
        }
    }
}

// ---------------- Q += time_weights; gate = sigmoid(q . gateW + gateb) ------
__global__ void add_time_gate(float* __restrict__ q, const float* __restrict__ tw,
                              const float* __restrict__ gW, const float* __restrict__ gb,
                              float* __restrict__ gate)
{
    int warp = (blockIdx.x * blockDim.x + threadIdx.x) >> 5; // one warp per (b,s,h)
    int lane = threadIdx.x & 31;
    if (warp >= ROWS * HH) return;
    int bs = warp >> 4;     // b*S + s
    int h  = warp & 15;
    long long base = (long long)bs * DD + h * DK;
    float q0 = q[base + lane]      + tw[h * DK + lane];
    float q1 = q[base + lane + 32] + tw[h * DK + lane + 32];
    q[base + lane]      = q0;
    q[base + lane + 32] = q1;
    float s = q0 * gW[lane] + q1 * gW[lane + 32];
    #pragma unroll
    for (int o = 16; o; o >>= 1) s += __shfl_xor_sync(0xffffffffu, s, o);
    if (lane == 0) {
        int b = bs / SS, srow = bs % SS;
        gate[((long long)(b * HH + h)) * SS + srow] = 1.0f / (1.0f + expf(-(s + gb[0])));
    }
}

// ---------------- row softmax (2048-wide rows, 256 threads) -----------------
__device__ __forceinline__ float warpMax(float v) {
    #pragma unroll
    for (int o = 16; o; o >>= 1) v = fmaxf(v, __shfl_xor_sync(0xffffffffu, v, o));
    return v;
}
__device__ __forceinline__ float warpSum(float v) {
    #pragma unroll
    for (int o = 16; o; o >>= 1) v += __shfl_xor_sync(0xffffffffu, v, o);
    return v;
}

__global__ void __launch_bounds__(256) softmax_rows(float* __restrict__ p)
{
    long long row = blockIdx.x;
    float* r = p + row * SS;
    int t = threadIdx.x, lane = t & 31, wid = t >> 5;
    __shared__ float sred[8];
    __shared__ float sbc;

    float e[8];
    float m = -3.4e38f;
    #pragma unroll
    for (int i = 0; i < 8; i++) { e[i] = r[t + i * 256]; m = fmaxf(m, e[i]); }
    m = warpMax(m);
    if (lane == 0) sred[wid] = m;
    __syncthreads();
    if (wid == 0) {
        float x = (lane < 8) ? sred[lane] : -3.4e38f;
        x = warpMax(x);
        if (lane == 0) sbc = x;
    }
    __syncthreads();
    m = sbc;

    float s = 0.f;
    #pragma unroll
    for (int i = 0; i < 8; i++) { e[i] = __expf(e[i] - m); s += e[i]; }
    s = warpSum(s);
    __syncthreads();                 // protect sbc read above before rewrite
    if (lane == 0) sred[wid] = s;
    __syncthreads();
    if (wid == 0) {
        float x = (lane < 8) ? sred[lane] : 0.f;
        x = warpSum(x);
        if (lane == 0) sbc = x;
    }
    __syncthreads();
    float inv = 1.0f / sbc;
    #pragma unroll
    for (int i = 0; i < 8; i++) r[t + i * 256] = e[i] * inv;
}

// ---------------- LayerNorm over D=1024 (optional fused residual) -----------
__global__ void __launch_bounds__(256)
layernorm_k(const float* __restrict__ a, const float* __restrict__ resid,
            const float* __restrict__ g, const float* __restrict__ b,
            float* __restrict__ out)
{
    long long row = blockIdx.x;
    const float* pa = a + row * DD;
    const float* pr = resid ? resid + row * DD : nullptr;
    int t = threadIdx.x, lane = t & 31, wid = t >> 5;
    __shared__ float sh_s[8], sh_s2[8];
    __shared__ float bc_mean, bc_rstd;

    float v[4], s = 0.f, s2 = 0.f;
    #pragma unroll
    for (int i = 0; i < 4; i++) {
        int d = t + i * 256;
        float x = pa[d] + (pr ? pr[d] : 0.f);
        v[i] = x; s += x; s2 += x * x;
    }
    s = warpSum(s); s2 = warpSum(s2);
    if (lane == 0) { sh_s[wid] = s; sh_s2[wid] = s2; }
    __syncthreads();
    if (wid == 0) {
        float xs  = (lane < 8) ? sh_s[lane]  : 0.f;
        float xs2 = (lane < 8) ? sh_s2[lane] : 0.f;
        xs = warpSum(xs); xs2 = warpSum(xs2);
        if (lane == 0) {
            float mean = xs * (1.0f / DD);
            float var  = fmaxf(xs2 * (1.0f / DD) - mean * mean, 0.f);
            bc_mean = mean;
            bc_rstd = rsqrtf(var + 1e-5f);
        }
    }
    __syncthreads();
    float mean = bc_mean, rstd = bc_rstd;
    #pragma unroll
    for (int i = 0; i < 4; i++) {
        int d = t + i * 256;
        out[row * DD + d] = (v[i] - mean) * rstd * g[d] + b[d];
    }
}

// ---------------- launch --------------------------------------------------
extern "C" void kernel_launch(void* const* d_in, const int* in_sizes, int n_in,
                              void* d_out, int out_size)
{
    const float* x    = (const float*)d_in[0];
    const int*   mask = (const int*)  d_in[1];
    const float* Wq   = (const float*)d_in[2];  const float* bq  = (const float*)d_in[3];
    const float* Wk   = (const float*)d_in[4];  const float* bk  = (const float*)d_in[5];
    const float* Wv   = (const float*)d_in[6];  const float* bv  = (const float*)d_in[7];
    const float* Wo   = (const float*)d_in[8];  const float* bo  = (const float*)d_in[9];
    const float* temp = (const float*)d_in[10];
    const float* tw   = (const float*)d_in[11];
    const float* gW   = (const float*)d_in[12]; const float* gb  = (const float*)d_in[13];
    const float* lag  = (const float*)d_in[14]; const float* lab = (const float*)d_in[15];
    const float* f1W  = (const float*)d_in[16]; const float* f1b = (const float*)d_in[17];
    const float* f2W  = (const float*)d_in[18]; const float* f2b = (const float*)d_in[19];
    const float* n1g  = (const float*)d_in[20]; const float* n1b = (const float*)d_in[21];
    const float* n2g  = (const float*)d_in[22]; const float* n2b = (const float*)d_in[23];
    float* out = (float*)d_out;

    float *q, *k, *v, *ctx, *t0, *x1, *ff1, *gate, *sc;
    cudaGetSymbolAddress((void**)&q,   g_q);
    cudaGetSymbolAddress((void**)&k,   g_k);
    cudaGetSymbolAddress((void**)&v,   g_v);
    cudaGetSymbolAddress((void**)&ctx, g_ctx);
    cudaGetSymbolAddress((void**)&t0,  g_t0);
    cudaGetSymbolAddress((void**)&x1,  g_x1);
    cudaGetSymbolAddress((void**)&ff1, g_ff1);
    cudaGetSymbolAddress((void**)&gate,g_gate);
    cudaGetSymbolAddress((void**)&sc,  g_scores);

    const long long SD  = (long long)SS * DD;        // per-batch stride in q/k/v/ctx
    const long long SSS = (long long)SS * SS;        // per-head score stride

    // Q/K/V projections: [4096,1024] = x @ W + b
    dim3 gProj(DD / Bn, ROWS / Bb, 1);
    gemm64<0,false><<<gProj, 256>>>(x, Wq, q, ROWS, DD, DD, DD, DD, DD,
                                    0,0,0,0,0,0, 1, bq, nullptr, nullptr, nullptr, 0);
    gemm64<0,false><<<gProj, 256>>>(x, Wk, k, ROWS, DD, DD, DD, DD, DD,
                                    0,0,0,0,0,0, 1, bk, nullptr, nullptr, nullptr, 0);
    gemm64<0,false><<<gProj, 256>>>(x, Wv, v, ROWS, DD, DD, DD, DD, DD,
                                    0,0,0,0,0,0, 1, bv, nullptr, nullptr, nullptr, 0);

    // Q += time_weights; gate = sigmoid(q @ gateW + gateb)
    add_time_gate<<<(ROWS * HH) / 8, 256>>>(q, tw, gW, gb, gate);

    // scores[z] = gate * mask(QK^T / temp), z = b*H + h
    dim3 gScore(SS / Bn, SS / Bb, ZTOT);
    gemm64<2,true><<<gScore, 256>>>(q, k, sc, SS, SS, DK, DD, DD, SS,
                                    SD, DK, SD, DK, (long long)HH * SSS, SSS, HH,
                                    nullptr, mask, gate, temp, SS);

    // row softmax over 65536 rows
    softmax_rows<<<ZTOT * SS, 256>>>(sc);

    // ctx[z] = probs @ V_head, written back in [B,S,D] layout
    dim3 gCtx(1, SS / Bb, ZTOT);
    gemm64<0,false><<<gCtx, 256>>>(sc, v, ctx, SS, DK, SS, SS, DD, DD,
                                   (long long)HH * SSS, SSS, SD, DK, SD, DK, HH,
                                   nullptr, nullptr, nullptr, nullptr, 0);

    // attn projection + LN
    gemm64<0,false><<<gProj, 256>>>(ctx, Wo, t0, ROWS, DD, DD, DD, DD, DD,
                                    0,0,0,0,0,0, 1, bo, nullptr, nullptr, nullptr, 0);
    layernorm_k<<<ROWS, 256>>>(t0, nullptr, lag, lab, ctx);   // attn_out -> ctx
    layernorm_k<<<ROWS, 256>>>(x, ctx, n1g, n1b, x1);          // x1 = LN(x + attn_out)

    // FFN
    dim3 gFc1(DFF / Bn, ROWS / Bb, 1);
    gemm64<1,false><<<gFc1, 256>>>(x1, f1W, ff1, ROWS, DFF, DD, DD, DFF, DFF,
                                   0,0,0,0,0,0, 1, f1b, nullptr, nullptr, nullptr, 0);
    gemm64<0,false><<<gProj, 256>>>(ff1, f2W, t0, ROWS, DD, DFF, DFF, DD, DD,
                                    0,0,0,0,0,0, 1, f2b, nullptr, nullptr, nullptr, 0);

    // out = LN(x1 + ff)
    layernorm_k<<<ROWS, 256>>>(x1, t0, n2g, n2b, out);
}

// round 2
// speedup vs baseline: 1.6226x; 1.6226x over previous
#include <cuda_runtime.h>
#include <math.h>

// Fixed problem shapes
#define BB 2
#define SS 2048
#define DD 1024
#define HH 16
#define DK 64
#define DFF 4096
#define ROWS (BB*SS)          // 4096
#define ZTOT (BB*HH)          // 32

// ---------------- scratch (device globals; no allocation allowed) ----------
__device__ float g_q  [ROWS*DD];
__device__ float g_k  [ROWS*DD];
__device__ float g_v  [ROWS*DD];
__device__ float g_ctx[ROWS*DD];
__device__ float g_t0 [ROWS*DD];
__device__ float g_x1 [ROWS*DD];
__device__ float g_ff1[ROWS*DFF];
__device__ float g_gate[ZTOT*SS];
__device__ float g_scores[(long long)ZTOT*SS*SS]; // 512 MB

// ---------------- generic tiled GEMM -----------------
// C[M,N] = A[M,K] @ B[K,N] (or A @ B^T if TRANSB, with B[N,K])
// Batched over blockIdx.z: z -> (zb = z/H, zh = z%H), per-operand strides.
// EPI: 0 = +bias (if non-null), 1 = +bias then exact GELU,
//      2 = scores epilogue: v/temp, mask==0 -> -1e9, then *gate[row]
#define Bb 64
#define Bn 64
#define Bk 16

template<int EPI, bool TRANSB>
__global__ void __launch_bounds__(256)
gemm64(const float* __restrict__ A, const float* __restrict__ B, float* __restrict__ C,
       int M, int N, int K, int lda, int ldb, int ldc,
       long long sAb, long long sAh, long long sBb, long long sBh,
       long long sCb, long long sCh, int H,
       const float* __restrict__ bias,
       const int* __restrict__ mask, const float* __restrict__ gate,
       const float* __restrict__ temp, int S)
{
    int z  = blockIdx.z;
    int zb = z / H, zh = z % H;
    A += zb * sAb + zh * sAh;
    B += zb * sBb + zh * sBh;
    C += zb * sCb + zh * sCh;
    const float* gaterow = (EPI == 2) ? gate + (long long)z * S : nullptr;

    __shared__ float As[Bk][Bb];
    __shared__ float Bs[Bk][Bn];

    int t  = threadIdx.x;
    int tx = t & 15, ty = t >> 4;
    int m0 = blockIdx.y * Bb, n0 = blockIdx.x * Bn;

    float acc[4][4] = {};

    for (int k0 = 0; k0 < K; k0 += Bk) {
        // A tile -> As[k][m] (transposed store for contiguous compute reads)
        {
            int ar = t >> 2, akq = (t & 3) * 4;
            float4 av = *reinterpret_cast<const float4*>(
                &A[(long long)(m0 + ar) * lda + k0 + akq]);
            As[akq + 0][ar] = av.x; As[akq + 1][ar] = av.y;
            As[akq + 2][ar] = av.z; As[akq + 3][ar] = av.w;
        }
        if (TRANSB) {
            int bn = t >> 2, bkq = (t & 3) * 4;
            float4 bv = *reinterpret_cast<const float4*>(
                &B[(long long)(n0 + bn) * ldb + k0 + bkq]);
            Bs[bkq + 0][bn] = bv.x; Bs[bkq + 1][bn] = bv.y;
            Bs[bkq + 2][bn] = bv.z; Bs[bkq + 3][bn] = bv.w;
        } else {
            int bk = t >> 4, bnq = (t & 15) * 4;
            *reinterpret_cast<float4*>(&Bs[bk][bnq]) =
                *reinterpret_cast<const float4*>(
                    &B[(long long)(k0 + bk) * ldb + n0 + bnq]);
        }
        __syncthreads();

        #pragma unroll
        for (int kk = 0; kk < Bk; kk++) {
            float4 a4 = *reinterpret_cast<const float4*>(&As[kk][ty * 4]);
            float4 b4 = *reinterpret_cast<const float4*>(&Bs[kk][tx * 4]);
            float av[4] = {a4.x, a4.y, a4.z, a4.w};
            float bv[4] = {b4.x, b4.y, b4.z, b4.w};
            #pragma unroll
            for (int i = 0; i < 4; i++)
                #pragma unroll
                for (int j = 0; j < 4; j++)
                    acc[i][j] += av[i] * bv[j];
        }
        __syncthreads();
    }

    float invT = (EPI == 2) ? (1.0f / temp[0]) : 1.0f;
    #pragma unroll
    for (int i = 0; i < 4; i++) {
        int row = m0 + ty * 4 + i;
        #pragma unroll
        for (int j = 0; j < 4; j++) {
            int col = n0 + tx * 4 + j;
            float v = acc[i][j];
            if (EPI == 0 || EPI == 1) { if (bias) v += bias[col]; }
            if (EPI == 1) v = 0.5f * v * (1.0f + erff(v * 0.70710678118654752f));
            if (EPI == 2) {
                v *= invT;
                if (mask[(long long)row * S + col] == 0) v = -1e9f;
                v *= gaterow[row];
            }
            C[(long long)row * ldc + col] = v;
        }
    }
}

// ---------------- Q += time_weights; gate = sigmoid(q . gateW + gateb) ------
__global__ void add_time_gate(float* __restrict__ q, const float* __restrict__ tw,
                              const float* __restrict__ gW, const float* __restrict__ gb,
                              float* __restrict__ gate)
{
    int warp = (blockIdx.x * blockDim.x + threadIdx.x) >> 5; // one warp per (b,s,h)
    int lane = threadIdx.x & 31;
    if (warp >= ROWS * HH) return;
    int bs = warp >> 4;     // b*S + s
    int h  = warp & 15;
    long long base = (long long)bs * DD + h * DK;
    float q0 = q[base + lane]      + tw[h * DK + lane];
    float q1 = q[base + lane + 32] + tw[h * DK + lane + 32];
    q[base + lane]      = q0;
    q[base + lane + 32] = q1;
    float s = q0 * gW[lane] + q1 * gW[lane + 32];
    #pragma unroll
    for (int o = 16; o; o >>= 1) s += __shfl_xor_sync(0xffffffffu, s, o);
    if (lane == 0) {
        int b = bs / SS, srow = bs % SS;
        gate[((long long)(b * HH + h)) * SS + srow] = 1.0f / (1.0f + expf(-(s + gb[0])));
    }
}

// ---------------- row softmax (2048-wide rows, 256 threads) -----------------
__device__ __forceinline__ float warpMax(float v) {
    #pragma unroll
    for (int o = 16; o; o >>= 1) v = fmaxf(v, __shfl_xor_sync(0xffffffffu, v, o));
    return v;
}
__device__ __forceinline__ float warpSum(float v) {
    #pragma unroll
    for (int o = 16; o; o >>= 1) v += __shfl_xor_sync(0xffffffffu, v, o);
    return v;
}

__global__ void __launch_bounds__(256) softmax_rows(float* __restrict__ p)
{
    long long row = blockIdx.x;
    float* r = p + row * SS;
    int t = threadIdx.x, lane = t & 31, wid = t >> 5;
    __shared__ float sred[8];
    __shared__ float sbc;

    float e[8];
    float m = -3.4e38f;
    #pragma unroll
    for (int i = 0; i < 8; i++) { e[i] = r[t + i * 256]; m = fmaxf(m, e[i]); }
    m = warpMax(m);
    if (lane == 0) sred[wid] = m;
    __syncthreads();
    if (wid == 0) {
        float x = (lane < 8) ? sred[lane] : -3.4e38f;
        x = warpMax(x);
        if (lane == 0) sbc = x;
    }
    __syncthreads();
    m = sbc;

    float s = 0.f;
    #pragma unroll
    for (int i = 0; i < 8; i++) { e[i] = __expf(e[i] - m); s += e[i]; }
    s = warpSum(s);
    __syncthreads();                 // protect sbc read above before rewrite
    if (lane == 0) sred[wid] = s;
    __syncthreads();
    if (wid == 0) {
        float x = (lane < 8) ? sred[lane] : 0.f;
        x = warpSum(x);
        if (lane == 0) sbc = x;
    }
    __syncthreads();
    float inv = 1.0f / sbc;
    #pragma unroll
    for (int i = 0; i < 8; i++) r[t + i * 256] = e[i] * inv;
}

// ---------------- LayerNorm over D=1024 (optional fused residual) -----------
__global__ void __launch_bounds__(256)
layernorm_k(const float* __restrict__ a, const float* __restrict__ resid,
            const float* __restrict__ g, const float* __restrict__ b,
            float* __restrict__ out)
{
    long long row = blockIdx.x;
    const float* pa = a + row * DD;
    const float* pr = resid ? resid + row * DD : nullptr;
    int t = threadIdx.x, lane = t & 31, wid = t >> 5;
    __shared__ float sh_s[8], sh_s2[8];
    __shared__ float bc_mean, bc_rstd;

    float v[4], s = 0.f, s2 = 0.f;
    #pragma unroll
    for (int i = 0; i < 4; i++) {
        int d = t + i * 256;
        float x = pa[d] + (pr ? pr[d] : 0.f);
        v[i] = x; s += x; s2 += x * x;
    }
    s = warpSum(s); s2 = warpSum(s2);
    if (lane == 0) { sh_s[wid] = s; sh_s2[wid] = s2; }
    __syncthreads();
    if (wid == 0) {
        float xs  = (lane < 8) ? sh_s[lane]  : 0.f;
        float xs2 = (lane < 8) ? sh_s2[lane] : 0.f;
        xs = warpSum(xs); xs2 = warpSum(xs2);
        if (lane == 0) {
            float mean = xs * (1.0f / DD);
            float var  = fmaxf(xs2 * (1.0f / DD) - mean * mean, 0.f);
            bc_mean = mean;
            bc_rstd = rsqrtf(var + 1e-5f);
        }
    }
    __syncthreads();
    float mean = bc_mean, rstd = bc_rstd;
    #pragma unroll
    for (int i = 0; i < 4; i++) {
        int d = t + i * 256;
        out[row * DD + d] = (v[i] - mean) * rstd * g[d] + b[d];
    }
}

// ---------------- launch --------------------------------------------------
extern "C" void kernel_launch(void* const* d_in, const int* in_sizes, int n_in,
                              void* d_out, int out_size)
{
    const float* x    = (const float*)d_in[0];
    const int*   mask = (const int*)  d_in[1];
    const float* Wq   = (const float*)d_in[2];  const float* bq  = (const float*)d_in[3];
    const float* Wk   = (const float*)d_in[4];  const float* bk  = (const float*)d_in[5];
    const float* Wv   = (const float*)d_in[6];  const float* bv  = (const float*)d_in[7];
    const float* Wo   = (const float*)d_in[8];  const float* bo  = (const float*)d_in[9];
    const float* temp = (const float*)d_in[10];
    const float* tw   = (const float*)d_in[11];
    const float* gW   = (const float*)d_in[12]; const float* gb  = (const float*)d_in[13];
    const float* lag  = (const float*)d_in[14]; const float* lab = (const float*)d_in[15];
    const float* f1W  = (const float*)d_in[16]; const float* f1b = (const float*)d_in[17];
    const float* f2W  = (const float*)d_in[18]; const float* f2b = (const float*)d_in[19];
    const float* n1g  = (const float*)d_in[20]; const float* n1b = (const float*)d_in[21];
    const float* n2g  = (const float*)d_in[22]; const float* n2b = (const float*)d_in[23];
    float* out = (float*)d_out;

    float *q, *k, *v, *ctx, *t0, *x1, *ff1, *gate, *sc;
    cudaGetSymbolAddress((void**)&q,   g_q);
    cudaGetSymbolAddress((void**)&k,   g_k);
    cudaGetSymbolAddress((void**)&v,   g_v);
    cudaGetSymbolAddress((void**)&ctx, g_ctx);
    cudaGetSymbolAddress((void**)&t0,  g_t0);
    cudaGetSymbolAddress((void**)&x1,  g_x1);
    cudaGetSymbolAddress((void**)&ff1, g_ff1);
    cudaGetSymbolAddress((void**)&gate,g_gate);
    cudaGetSymbolAddress((void**)&sc,  g_scores);

    const long long SD  = (long long)SS * DD;        // per-batch stride in q/k/v/ctx
    const long long SSS = (long long)SS * SS;        // per-head score stride

    // Q/K/V projections: [4096,1024] = x @ W + b
    dim3 gProj(DD / Bn, ROWS / Bb, 1);
    gemm64<0,false><<<gProj, 256>>>(x, Wq, q, ROWS, DD, DD, DD, DD, DD,
                                    0,0,0,0,0,0, 1, bq, nullptr, nullptr, nullptr, 0);
    gemm64<0,false><<<gProj, 256>>>(x, Wk, k, ROWS, DD, DD, DD, DD, DD,
                                    0,0,0,0,0,0, 1, bk, nullptr, nullptr, nullptr, 0);
    gemm64<0,false><<<gProj, 256>>>(x, Wv, v, ROWS, DD, DD, DD, DD, DD,
                                    0,0,0,0,0,0, 1, bv, nullptr, nullptr, nullptr, 0);

    // Q += time_weights; gate = sigmoid(q @ gateW + gateb)
    add_time_gate<<<(ROWS * HH) / 8, 256>>>(q, tw, gW, gb, gate);

    // scores[z] = gate * mask(QK^T / temp), z = b*H + h
    dim3 gScore(SS / Bn, SS / Bb, ZTOT);
    gemm64<2,true><<<gScore, 256>>>(q, k, sc, SS, SS, DK, DD, DD, SS,
                                    SD, DK, SD, DK, (long long)HH * SSS, SSS, HH,
                                    nullptr, mask, gate, temp, SS);

    // row softmax over 65536 rows
    softmax_rows<<<ZTOT * SS, 256>>>(sc);

    // ctx[z] = probs @ V_head, written back in [B,S,D] layout
    dim3 gCtx(1, SS / Bb, ZTOT);
    gemm64<0,false><<<gCtx, 256>>>(sc, v, ctx, SS, DK, SS, SS, DD, DD,
                                   (long long)HH * SSS, SSS, SD, DK, SD, DK, HH,
                                   nullptr, nullptr, nullptr, nullptr, 0);

    // attn projection + LN
    gemm64<0,false><<<gProj, 256>>>(ctx, Wo, t0, ROWS, DD, DD, DD, DD, DD,
                                    0,0,0,0,0,0, 1, bo, nullptr, nullptr, nullptr, 0);
    layernorm_k<<<ROWS, 256>>>(t0, nullptr, lag, lab, ctx);   // attn_out -> ctx
    layernorm_k<<<ROWS, 256>>>(x, ctx, n1g, n1b, x1);          // x1 = LN(x + attn_out)

    // FFN
    dim3 gFc1(DFF / Bn, ROWS / Bb, 1);
    gemm64<1,false><<<gFc1, 256>>>(x1, f1W, ff1, ROWS, DFF, DD, DD, DFF, DFF,
                                   0,0,0,0,0,0, 1, f1b, nullptr, nullptr, nullptr, 0);
    gemm64<0,false><<<gProj, 256>>>(ff1, f2W, t0, ROWS, DD, DFF, DFF, DD, DD,
                                    0,0,0,0,0,0, 1, f2b, nullptr, nullptr, nullptr, 0);

    // out = LN(x1 + ff)
    layernorm_k<<<ROWS, 256>>>(x1, t0, n2g, n2b, out);
}

// round 4
// speedup vs baseline: 3.9819x; 2.4540x over previous
#include <cuda_runtime.h>
#include <cuda_bf16.h>
#include <math.h>
#include <stdint.h>

#define SSEQ 2048
#define DMODEL 1024
#define NHEADS 16
#define DKH 64
#define DFF 4096
#define ROWS 4096
#define ZTOT 32
#define SD ((long long)SSEQ*DMODEL)
#define SSS ((long long)SSEQ*SSEQ)
typedef __nv_bfloat16 bf16;

// ---------------- scratch ----------------
__device__ __align__(256) float g_t0[ROWS*DMODEL];
__device__ __align__(256) float g_x1[ROWS*DMODEL];
__device__ __align__(256) float g_attn[ROWS*DMODEL];
__device__ __align__(256) float g_gate[ZTOT*SSEQ];
__device__ __align__(256) float g_sc[(long long)ZTOT*SSS];
__device__ __align__(256) bf16 g_xh[ROWS*DMODEL], g_xl[ROWS*DMODEL];
__device__ __align__(256) bf16 g_qh[ROWS*DMODEL], g_ql[ROWS*DMODEL];
__device__ __align__(256) bf16 g_kh[ROWS*DMODEL], g_kl[ROWS*DMODEL];
__device__ __align__(256) bf16 g_vh[ROWS*DMODEL], g_vl[ROWS*DMODEL]; // [z][dk][s]
__device__ __align__(256) bf16 g_ch[ROWS*DMODEL], g_cl[ROWS*DMODEL];
__device__ __align__(256) bf16 g_yh[ROWS*DMODEL], g_yl[ROWS*DMODEL];
__device__ __align__(256) bf16 g_fh[ROWS*DFF], g_fl[ROWS*DFF];
__device__ __align__(256) bf16 g_ph[(long long)ZTOT*SSS], g_pl[(long long)ZTOT*SSS];
__device__ __align__(256) bf16 g_wqh[DMODEL*DMODEL], g_wql[DMODEL*DMODEL];
__device__ __align__(256) bf16 g_wkh[DMODEL*DMODEL], g_wkl[DMODEL*DMODEL];
__device__ __align__(256) bf16 g_wvh[DMODEL*DMODEL], g_wvl[DMODEL*DMODEL];
__device__ __align__(256) bf16 g_woh[DMODEL*DMODEL], g_wol[DMODEL*DMODEL];
__device__ __align__(256) bf16 g_w1h[DMODEL*DFF], g_w1l[DMODEL*DFF];
__device__ __align__(256) bf16 g_w2h[DMODEL*DFF], g_w2l[DMODEL*DFF];

// ---------------- helpers ----------------
__device__ __forceinline__ uint32_t su32(const void* p){uint32_t a;
    asm("{.reg .u64 t; cvta.to.shared.u64 t,%1; cvt.u32.u64 %0,t;}":"=r"(a):"l"(p));return a;}
__device__ __forceinline__ void cpa(uint32_t d,const void*s){
    asm volatile("cp.async.cg.shared.global [%0],[%1],16;"::"r"(d),"l"(s));}
#define CPCOMMIT() asm volatile("cp.async.commit_group;":::"memory")
#define LDM4(f,a) asm volatile("ldmatrix.sync.aligned.m8n8.x4.shared.b16 {%0,%1,%2,%3},[%4];" \
    :"=r"((f)[0]),"=r"((f)[1]),"=r"((f)[2]),"=r"((f)[3]):"r"(a))
#define LDM4B(b0,b1,b2,b3,a) asm volatile("ldmatrix.sync.aligned.m8n8.x4.shared.b16 {%0,%1,%2,%3},[%4];" \
    :"=r"(b0),"=r"(b1),"=r"(b2),"=r"(b3):"r"(a))
#define MMA(c,A,B) asm volatile( \
    "mma.sync.aligned.m16n8k16.row.col.f32.bf16.bf16.f32 {%0,%1,%2,%3},{%4,%5,%6,%7},{%8,%9},{%0,%1,%2,%3};" \
    :"+f"((c)[0]),"+f"((c)[1]),"+f"((c)[2]),"+f"((c)[3]) \
    :"r"((A)[0]),"r"((A)[1]),"r"((A)[2]),"r"((A)[3]),"r"((B)[0]),"r"((B)[1]))

// ---------------- bf16-split HMMA GEMM ----------------
// C = (Ah+Al)[M,K] @ (Bh+Bl)[N,K]^T via 3 products, 128xTN tile, BK=32, 2 stages.
// epi: 0 bias(+bias2), 1 bias+GELU, 2 scores(/T, mask, *gate)
// outm: 0 fp32, 1 bf16 split, 2 transposed-V split
template<int TN>
__global__ __launch_bounds__(256,2) void hgemm(
    const bf16* __restrict__ Ah_, const bf16* __restrict__ Al_,
    const bf16* __restrict__ Bh_, const bf16* __restrict__ Bl_,
    int K, int lda, int ldb, int ldc,
    long long sAb, long long sAh2, long long sBb, long long sBh2,
    long long sCb, long long sCh2,
    float* __restrict__ Cf, bf16* __restrict__ Ch, bf16* __restrict__ Cl,
    const float* __restrict__ bias, const float* __restrict__ bias2,
    const int* __restrict__ mask, const float* __restrict__ gate,
    const float* __restrict__ temp, int epi, int outm)
{
    constexpr int WM = (TN==128)?64:32;       // warp M extent
    constexpr int NWM = 128/WM;               // warps along M
    constexpr int MT = WM/16;                 // m16 tiles per warp
    constexpr int TBB = TN*80;                // B buffer bytes
    constexpr int STG = 2*10240 + 2*TBB;      // stage bytes
    extern __shared__ char smraw[];
    uint32_t su = su32(smraw);
    int tid = threadIdx.x, wid = tid>>5, lane = tid&31;
    int wm = wid%NWM, wn = wid/NWM;
    int z = blockIdx.z, zb = z>>4, zh = z&15;
    int m0 = blockIdx.y*128, n0 = blockIdx.x*TN;

    const bf16* pAh = Ah_ + zb*sAb + zh*sAh2 + (long long)m0*lda;
    const bf16* pAl = Al_ + zb*sAb + zh*sAh2 + (long long)m0*lda;
    const bf16* pBh = Bh_ + zb*sBb + zh*sBh2 + (long long)n0*ldb;
    const bf16* pBl = Bl_ + zb*sBb + zh*sBh2 + (long long)n0*ldb;
    int nk = K>>5;

    int r = tid>>2, sg = tid&3;
    auto loadstage = [&](int ci, int st){
        uint32_t b = su + (uint32_t)st*STG;
        int k0 = ci<<5;
        #pragma unroll
        for(int p=0;p<2;p++){
            int rr = r + p*64;
            uint32_t so = b + rr*80 + sg*16;
            cpa(so,       pAh + (long long)rr*lda + k0 + sg*8);
            cpa(so+10240, pAl + (long long)rr*lda + k0 + sg*8);
        }
        #pragma unroll
        for(int p=0;p<TN/64;p++){
            int rr = r + p*64;
            uint32_t so = b + 20480 + rr*80 + sg*16;
            cpa(so,     pBh + (long long)rr*ldb + k0 + sg*8);
            cpa(so+TBB, pBl + (long long)rr*ldb + k0 + sg*8);
        }
        CPCOMMIT();
    };

    float acc[MT][4][4];
    #pragma unroll
    for(int a=0;a<MT;a++)
        #pragma unroll
        for(int b=0;b<4;b++)
            #pragma unroll
            for(int c=0;c<4;c++) acc[a][b][c]=0.f;

    int quad = lane>>3, lq = lane&7;
    uint32_t aoff = (uint32_t)((wm*WM + (quad&1)*8 + lq)*80 + (quad>>1)*16);
    uint32_t boff = (uint32_t)(20480 + (wn*32 + (quad>>1)*8 + lq)*80 + (quad&1)*16);

    loadstage(0,0);
    if(nk>1) loadstage(1,1);

    for(int i=0;i<nk;i++){
        if(i+1<nk) asm volatile("cp.async.wait_group 1;":::"memory");
        else       asm volatile("cp.async.wait_group 0;":::"memory");
        __syncthreads();
        uint32_t sb = su + (uint32_t)(i&1)*STG;
        uint32_t pa_h = sb + aoff, pa_l = pa_h + 10240;
        uint32_t pb_h = sb + boff, pb_l = pb_h + TBB;
        uint32_t Af[MT][4], Bf[4][2], Bt[4][2];
        #pragma unroll
        for(int ks=0;ks<2;ks++){
            uint32_t kso = ks*32;
            #pragma unroll
            for(int mt=0;mt<MT;mt++) LDM4(Af[mt], pa_h + mt*1280 + kso);
            #pragma unroll
            for(int np=0;np<2;np++)
                LDM4B(Bf[2*np][0],Bf[2*np][1],Bf[2*np+1][0],Bf[2*np+1][1], pb_h + np*1280 + kso);
            #pragma unroll
            for(int mt=0;mt<MT;mt++)
                #pragma unroll
                for(int nt=0;nt<4;nt++) MMA(acc[mt][nt],Af[mt],Bf[nt]);
            #pragma unroll
            for(int np=0;np<2;np++)
                LDM4B(Bt[2*np][0],Bt[2*np][1],Bt[2*np+1][0],Bt[2*np+1][1], pb_l + np*1280 + kso);
            #pragma unroll
            for(int mt=0;mt<MT;mt++)
                #pragma unroll
                for(int nt=0;nt<4;nt++) MMA(acc[mt][nt],Af[mt],Bt[nt]);
            #pragma unroll
            for(int mt=0;mt<MT;mt++) LDM4(Af[mt], pa_l + mt*1280 + kso);
            #pragma unroll
            for(int mt=0;mt<MT;mt++)
                #pragma unroll
                for(int nt=0;nt<4;nt++) MMA(acc[mt][nt],Af[mt],Bf[nt]);
        }
        __syncthreads();
        if(i+2<nk) loadstage(i+2, i&1);
    }

    float invT = (epi==2)? 1.f/temp[0] : 0.f;
    auto store2 = [&](int row,int col,float v0,float v1){
        if(epi<2){
            if(bias){ v0+=bias[col]; v1+=bias[col+1]; }
            if(bias2){ v0+=bias2[col]; v1+=bias2[col+1]; }
            if(epi==1){
                v0 = 0.5f*v0*(1.0f+erff(v0*0.70710678118654752f));
                v1 = 0.5f*v1*(1.0f+erff(v1*0.70710678118654752f));
            }
        } else {
            int2 mm = *(const int2*)&mask[(long long)row*SSEQ+col];
            float g = gate[(long long)z*SSEQ+row];
            v0*=invT; v1*=invT;
            if(mm.x==0) v0=-1e9f;
            if(mm.y==0) v1=-1e9f;
            v0*=g; v1*=g;
        }
        if(outm==0){
            *(float2*)&Cf[zb*sCb+zh*sCh2+(long long)row*ldc+col] = make_float2(v0,v1);
        } else if(outm==1){
            long long ix = zb*sCb+zh*sCh2+(long long)row*ldc+col;
            bf16 h0=__float2bfloat16(v0), h1=__float2bfloat16(v1);
            __nv_bfloat162 hp,lp; hp.x=h0; hp.y=h1;
            lp.x=__float2bfloat16(v0-__bfloat162float(h0));
            lp.y=__float2bfloat16(v1-__bfloat162float(h1));
            *(__nv_bfloat162*)(Ch+ix)=hp; *(__nv_bfloat162*)(Cl+ix)=lp;
        } else {
            float vv[2]={v0,v1};
            #pragma unroll
            for(int e=0;e<2;e++){
                int c2=col+e;
                long long ix = (long long)((row>>11)*NHEADS+(c2>>6))*(64LL*SSEQ)
                             + (long long)(c2&63)*SSEQ + (row&2047);
                bf16 h=__float2bfloat16(vv[e]);
                Ch[ix]=h; Cl[ix]=__float2bfloat16(vv[e]-__bfloat162float(h));
            }
        }
    };
    #pragma unroll
    for(int mt=0;mt<MT;mt++){
        #pragma unroll
        for(int nt=0;nt<4;nt++){
            int row0 = m0 + wm*WM + mt*16 + (lane>>2);
            int col  = n0 + wn*32 + nt*8 + ((lane&3)<<1);
            store2(row0,   col, acc[mt][nt][0], acc[mt][nt][1]);
            store2(row0+8, col, acc[mt][nt][2], acc[mt][nt][3]);
        }
    }
}

// ---------------- support kernels ----------------
__global__ void split_vk(const float* __restrict__ in, bf16* __restrict__ hi,
                         bf16* __restrict__ lo, int n4){
    int i=blockIdx.x*blockDim.x+threadIdx.x; if(i>=n4)return;
    float4 v=((const float4*)in)[i];
    bf16 h0=__float2bfloat16(v.x),h1=__float2bfloat16(v.y),h2=__float2bfloat16(v.z),h3=__float2bfloat16(v.w);
    __nv_bfloat162 a,b,c,d; a.x=h0;a.y=h1;b.x=h2;b.y=h3;
    c.x=__float2bfloat16(v.x-__bfloat162float(h0)); c.y=__float2bfloat16(v.y-__bfloat162float(h1));
    d.x=__float2bfloat16(v.z-__bfloat162float(h2)); d.y=__float2bfloat16(v.w-__bfloat162float(h3));
    ((__nv_bfloat162*)hi)[2*i]=a; ((__nv_bfloat162*)hi)[2*i+1]=b;
    ((__nv_bfloat162*)lo)[2*i]=c; ((__nv_bfloat162*)lo)[2*i+1]=d;
}
__global__ void split_T(const float* __restrict__ W, bf16* __restrict__ hi,
                        bf16* __restrict__ lo, int R, int C){
    __shared__ float t[32][33];
    int c0=blockIdx.x*32, r0=blockIdx.y*32, tx=threadIdx.x, ty=threadIdx.y;
    for(int i=ty;i<32;i+=8) t[i][tx]=W[(long long)(r0+i)*C+c0+tx];
    __syncthreads();
    for(int i=ty;i<32;i+=8){
        float v=t[tx][i]; long long ix=(long long)(c0+i)*R+r0+tx;
        bf16 h=__float2bfloat16(v); hi[ix]=h; lo[ix]=__float2bfloat16(v-__bfloat162float(h));
    }
}
__global__ void gatek(const bf16* __restrict__ qh,const bf16* __restrict__ ql,
                      const float* __restrict__ gW,const float* __restrict__ gb,
                      float* __restrict__ gate){
    int warp=(blockIdx.x*blockDim.x+threadIdx.x)>>5, lane=threadIdx.x&31;
    if(warp>=ROWS*NHEADS)return;
    int bs=warp>>4,h=warp&15;
    long long base=(long long)bs*DMODEL+h*DKH;
    float q0=__bfloat162float(qh[base+lane])+__bfloat162float(ql[base+lane]);
    float q1=__bfloat162float(qh[base+lane+32])+__bfloat162float(ql[base+lane+32]);
    float s=q0*gW[lane]+q1*gW[lane+32];
    #pragma unroll
    for(int o=16;o;o>>=1)s+=__shfl_xor_sync(~0u,s,o);
    if(lane==0){int b=bs>>11,sr=bs&2047;
        gate[(long long)(b*NHEADS+h)*SSEQ+sr]=1.f/(1.f+expf(-(s+gb[0])));}
}
__device__ __forceinline__ float wMax(float v){
    #pragma unroll
    for(int o=16;o;o>>=1)v=fmaxf(v,__shfl_xor_sync(~0u,v,o)); return v;}
__device__ __forceinline__ float wSum(float v){
    #pragma unroll
    for(int o=16;o;o>>=1)v+=__shfl_xor_sync(~0u,v,o); return v;}

__global__ void __launch_bounds__(256) softmax_split(const float* __restrict__ sc,
    bf16* __restrict__ ph, bf16* __restrict__ pl){
    long long row=blockIdx.x;
    const float* rp=sc+row*SSEQ;
    int t=threadIdx.x,lane=t&31,wid=t>>5;
    __shared__ float sr[8]; __shared__ float sb;
    float e[8],m=-3.4e38f;
    #pragma unroll
    for(int i=0;i<8;i++){e[i]=rp[t+i*256];m=fmaxf(m,e[i]);}
    m=wMax(m); if(lane==0)sr[wid]=m; __syncthreads();
    if(wid==0){float x=(lane<8)?sr[lane]:-3.4e38f;x=wMax(x);if(lane==0)sb=x;}
    __syncthreads(); m=sb;
    float s=0.f;
    #pragma unroll
    for(int i=0;i<8;i++){e[i]=__expf(e[i]-m);s+=e[i];}
    s=wSum(s); __syncthreads();
    if(lane==0)sr[wid]=s; __syncthreads();
    if(wid==0){float x=(lane<8)?sr[lane]:0.f;x=wSum(x);if(lane==0)sb=x;}
    __syncthreads();
    float inv=1.f/sb;
    #pragma unroll
    for(int i=0;i<8;i++){
        float v=e[i]*inv; long long ix=row*SSEQ+t+i*256;
        bf16 h=__float2bfloat16(v); ph[ix]=h; pl[ix]=__float2bfloat16(v-__bfloat162float(h));
    }
}
__global__ void __launch_bounds__(256) layernorm_k(const float* __restrict__ a,
    const float* __restrict__ resid, const float* __restrict__ g, const float* __restrict__ b,
    float* __restrict__ outf, bf16* __restrict__ oh, bf16* __restrict__ ol){
    long long row=blockIdx.x;
    const float* pa=a+row*DMODEL;
    const float* pr=resid?resid+row*DMODEL:nullptr;
    int t=threadIdx.x,lane=t&31,wid=t>>5;
    __shared__ float s1[8],s2a[8]; __shared__ float bm,brs;
    float v[4],s=0.f,s2=0.f;
    #pragma unroll
    for(int i=0;i<4;i++){int d=t+i*256;float x=pa[d]+(pr?pr[d]:0.f);v[i]=x;s+=x;s2+=x*x;}
    s=wSum(s);s2=wSum(s2);
    if(lane==0){s1[wid]=s;s2a[wid]=s2;} __syncthreads();
    if(wid==0){float xs=(lane<8)?s1[lane]:0.f,x2=(lane<8)?s2a[lane]:0.f;
        xs=wSum(xs);x2=wSum(x2);
        if(lane==0){float mean=xs*(1.f/DMODEL);float var=fmaxf(x2*(1.f/DMODEL)-mean*mean,0.f);
            bm=mean;brs=rsqrtf(var+1e-5f);}}
    __syncthreads();
    float mean=bm,rstd=brs;
    #pragma unroll
    for(int i=0;i<4;i++){int d=t+i*256;float y=(v[i]-mean)*rstd*g[d]+b[d];
        if(outf)outf[row*DMODEL+d]=y;
        if(oh){bf16 h=__float2bfloat16(y);oh[row*DMODEL+d]=h;
               ol[row*DMODEL+d]=__float2bfloat16(y-__bfloat162float(h));}}
}

// ---------------- launch ----------------
extern "C" void kernel_launch(void* const* d_in, const int* in_sizes, int n_in,
                              void* d_out, int out_size)
{
    const float* x   =(const float*)d_in[0];
    const int*  mask =(const int*)  d_in[1];
    const float* Wq=(const float*)d_in[2],  *bq=(const float*)d_in[3];
    const float* Wk=(const float*)d_in[4],  *bk=(const float*)d_in[5];
    const float* Wv=(const float*)d_in[6],  *bv=(const float*)d_in[7];
    const float* Wo=(const float*)d_in[8],  *bo=(const float*)d_in[9];
    const float* temp=(const float*)d_in[10], *tw=(const float*)d_in[11];
    const float* gW=(const float*)d_in[12], *gb=(const float*)d_in[13];
    const float* lag=(const float*)d_in[14],*lab=(const float*)d_in[15];
    const float* f1W=(const float*)d_in[16],*f1b=(const float*)d_in[17];
    const float* f2W=(const float*)d_in[18],*f2b=(const float*)d_in[19];
    const float* n1g=(const float*)d_in[20],*n1b=(const float*)d_in[21];
    const float* n2g=(const float*)d_in[22],*n2b=(const float*)d_in[23];
    float* out=(float*)d_out;

    float *t0,*x1,*attn,*gatep,*sc;
    bf16 *xh,*xl,*qh,*ql,*kh,*kl,*vh,*vl,*ch,*cl,*yh,*yl,*fh,*fl,*ph,*pl;
    bf16 *wqh,*wql,*wkh,*wkl,*wvh,*wvl,*woh,*wol,*w1h,*w1l,*w2h,*w2l;
    cudaGetSymbolAddress((void**)&t0,g_t0);   cudaGetSymbolAddress((void**)&x1,g_x1);
    cudaGetSymbolAddress((void**)&attn,g_attn);cudaGetSymbolAddress((void**)&gatep,g_gate);
    cudaGetSymbolAddress((void**)&sc,g_sc);
    cudaGetSymbolAddress((void**)&xh,g_xh); cudaGetSymbolAddress((void**)&xl,g_xl);
    cudaGetSymbolAddress((void**)&qh,g_qh); cudaGetSymbolAddress((void**)&ql,g_ql);
    cudaGetSymbolAddress((void**)&kh,g_kh); cudaGetSymbolAddress((void**)&kl,g_kl);
    cudaGetSymbolAddress((void**)&vh,g_vh); cudaGetSymbolAddress((void**)&vl,g_vl);
    cudaGetSymbolAddress((void**)&ch,g_ch); cudaGetSymbolAddress((void**)&cl,g_cl);
    cudaGetSymbolAddress((void**)&yh,g_yh); cudaGetSymbolAddress((void**)&yl,g_yl);
    cudaGetSymbolAddress((void**)&fh,g_fh); cudaGetSymbolAddress((void**)&fl,g_fl);
    cudaGetSymbolAddress((void**)&ph,g_ph); cudaGetSymbolAddress((void**)&pl,g_pl);
    cudaGetSymbolAddress((void**)&wqh,g_wqh);cudaGetSymbolAddress((void**)&wql,g_wql);
    cudaGetSymbolAddress((void**)&wkh,g_wkh);cudaGetSymbolAddress((void**)&wkl,g_wkl);
    cudaGetSymbolAddress((void**)&wvh,g_wvh);cudaGetSymbolAddress((void**)&wvl,g_wvl);
    cudaGetSymbolAddress((void**)&woh,g_woh);cudaGetSymbolAddress((void**)&wol,g_wol);
    cudaGetSymbolAddress((void**)&w1h,g_w1h);cudaGetSymbolAddress((void**)&w1l,g_w1l);
    cudaGetSymbolAddress((void**)&w2h,g_w2h);cudaGetSymbolAddress((void**)&w2l,g_w2l);

    const int SM128 = 2*(2*10240 + 2*128*80);   // 81920
    const int SM64  = 2*(2*10240 + 2*64*80);    // 61440
    cudaFuncSetAttribute((const void*)hgemm<128>,cudaFuncAttributeMaxDynamicSharedMemorySize,SM128);
    cudaFuncSetAttribute((const void*)hgemm<64>, cudaFuncAttributeMaxDynamicSharedMemorySize,SM64);

    // conversions
    split_vk<<<ROWS*DMODEL/4/256,256>>>(x,xh,xl,ROWS*DMODEL/4);
    dim3 tb(32,8);
    split_T<<<dim3(DMODEL/32,DMODEL/32),tb>>>(Wq,wqh,wql,DMODEL,DMODEL);
    split_T<<<dim3(DMODEL/32,DMODEL/32),tb>>>(Wk,wkh,wkl,DMODEL,DMODEL);
    split_T<<<dim3(DMODEL/32,DMODEL/32),tb>>>(Wv,wvh,wvl,DMODEL,DMODEL);
    split_T<<<dim3(DMODEL/32,DMODEL/32),tb>>>(Wo,woh,wol,DMODEL,DMODEL);
    split_T<<<dim3(DFF/32,DMODEL/32),tb>>>(f1W,w1h,w1l,DMODEL,DFF);
    split_T<<<dim3(DMODEL/32,DFF/32),tb>>>(f2W,w2h,w2l,DFF,DMODEL);

    // projections (Q bias2 = time_weights flattened [H*dk] = per-column add)
    dim3 gP(DMODEL/128,ROWS/128,1);
    hgemm<128><<<gP,256,SM128>>>(xh,xl,wqh,wql,DMODEL,DMODEL,DMODEL,DMODEL,
        0,0,0,0,0,0,nullptr,qh,ql,bq,tw,nullptr,nullptr,nullptr,0,1);
    hgemm<128><<<gP,256,SM128>>>(xh,xl,wkh,wkl,DMODEL,DMODEL,DMODEL,DMODEL,
        0,0,0,0,0,0,nullptr,kh,kl,bk,nullptr,nullptr,nullptr,nullptr,0,1);
    hgemm<128><<<gP,256,SM128>>>(xh,xl,wvh,wvl,DMODEL,DMODEL,DMODEL,DMODEL,
        0,0,0,0,0,0,nullptr,vh,vl,bv,nullptr,nullptr,nullptr,nullptr,0,2);

    gatek<<<(ROWS*NHEADS)/8,256>>>(qh,ql,gW,gb,gatep);

    // scores = gate * mask(QK^T / T)
    dim3 gS(SSEQ/128,SSEQ/128,ZTOT);
    hgemm<128><<<gS,256,SM128>>>(qh,ql,kh,kl,DKH,DMODEL,DMODEL,SSEQ,
        SD,DKH,SD,DKH,16*SSS,SSS,sc,nullptr,nullptr,nullptr,nullptr,mask,gatep,temp,2,0);

    softmax_split<<<ZTOT*SSEQ,256>>>(sc,ph,pl);

    // ctx = P @ V (V pre-transposed per head), split out in [B,S,D]
    dim3 gC(1,SSEQ/128,ZTOT);
    hgemm<64><<<gC,256,SM64>>>(ph,pl,vh,vl,SSEQ,SSEQ,SSEQ,DMODEL,
        16*SSS,SSS,16LL*DKH*SSEQ,(long long)DKH*SSEQ,SD,64,
        nullptr,ch,cl,nullptr,nullptr,nullptr,nullptr,nullptr,0,1);

    // Wo projection + LN chain
    hgemm<128><<<gP,256,SM128>>>(ch,cl,woh,wol,DMODEL,DMODEL,DMODEL,DMODEL,
        0,0,0,0,0,0,t0,nullptr,nullptr,bo,nullptr,nullptr,nullptr,nullptr,0,0);
    layernorm_k<<<ROWS,256>>>(t0,nullptr,lag,lab,attn,nullptr,nullptr);
    layernorm_k<<<ROWS,256>>>(x,attn,n1g,n1b,x1,yh,yl);

    // FFN
    dim3 gF(DFF/128,ROWS/128,1);
    hgemm<128><<<gF,256,SM128>>>(yh,yl,w1h,w1l,DMODEL,DMODEL,DMODEL,DFF,
        0,0,0,0,0,0,nullptr,fh,fl,f1b,nullptr,nullptr,nullptr,nullptr,1,1);
    hgemm<128><<<gP,256,SM128>>>(fh,fl,w2h,w2l,DFF,DFF,DFF,DMODEL,
        0,0,0,0,0,0,t0,nullptr,nullptr,f2b,nullptr,nullptr,nullptr,nullptr,0,0);

    layernorm_k<<<ROWS,256>>>(x1,t0,n2g,n2b,out,nullptr,nullptr);
}

// round 5
// speedup vs baseline: 4.8958x; 1.2295x over previous
#include <cuda_runtime.h>
#include <cuda_bf16.h>
#include <math.h>
#include <stdint.h>

#define SSEQ 2048
#define DMODEL 1024
#define NHEADS 16
#define DKH 64
#define DFF 4096
#define ROWS 4096
#define ZTOT 32
#define SD ((long long)SSEQ*DMODEL)
typedef __nv_bfloat16 bf16;

// ---------------- scratch ----------------
__device__ __align__(256) float g_t0[ROWS*DMODEL];
__device__ __align__(256) float g_x1[ROWS*DMODEL];
__device__ __align__(256) float g_attn[ROWS*DMODEL];
__device__ __align__(256) float g_gate[ZTOT*SSEQ];
__device__ __align__(256) bf16 g_xh[ROWS*DMODEL], g_xl[ROWS*DMODEL];
__device__ __align__(256) bf16 g_qh[ROWS*DMODEL], g_ql[ROWS*DMODEL];
__device__ __align__(256) bf16 g_kh[ROWS*DMODEL], g_kl[ROWS*DMODEL];
__device__ __align__(256) bf16 g_vh[ROWS*DMODEL], g_vl[ROWS*DMODEL];
__device__ __align__(256) bf16 g_ch[ROWS*DMODEL], g_cl[ROWS*DMODEL];
__device__ __align__(256) bf16 g_yh[ROWS*DMODEL], g_yl[ROWS*DMODEL];
__device__ __align__(256) bf16 g_fh[ROWS*DFF], g_fl[ROWS*DFF];
__device__ __align__(256) bf16 g_wqh[DMODEL*DMODEL], g_wql[DMODEL*DMODEL];
__device__ __align__(256) bf16 g_wkh[DMODEL*DMODEL], g_wkl[DMODEL*DMODEL];
__device__ __align__(256) bf16 g_wvh[DMODEL*DMODEL], g_wvl[DMODEL*DMODEL];
__device__ __align__(256) bf16 g_woh[DMODEL*DMODEL], g_wol[DMODEL*DMODEL];
__device__ __align__(256) bf16 g_w1h[DMODEL*DFF], g_w1l[DMODEL*DFF];
__device__ __align__(256) bf16 g_w2h[DMODEL*DFF], g_w2l[DMODEL*DFF];

// ---------------- helpers ----------------
__device__ __forceinline__ uint32_t su32(const void* p){uint32_t a;
    asm("{.reg .u64 t; cvta.to.shared.u64 t,%1; cvt.u32.u64 %0,t;}":"=r"(a):"l"(p));return a;}
__device__ __forceinline__ void cpa(uint32_t d,const void*s){
    asm volatile("cp.async.cg.shared.global [%0],[%1],16;"::"r"(d),"l"(s));}
#define CPCOMMIT() asm volatile("cp.async.commit_group;":::"memory")
#define LDM4(f,a) asm volatile("ldmatrix.sync.aligned.m8n8.x4.shared.b16 {%0,%1,%2,%3},[%4];" \
    :"=r"((f)[0]),"=r"((f)[1]),"=r"((f)[2]),"=r"((f)[3]):"r"(a))
#define LDM4B(b0,b1,b2,b3,a) asm volatile("ldmatrix.sync.aligned.m8n8.x4.shared.b16 {%0,%1,%2,%3},[%4];" \
    :"=r"(b0),"=r"(b1),"=r"(b2),"=r"(b3):"r"(a))
#define LDM4T(f,a) asm volatile("ldmatrix.sync.aligned.m8n8.x4.trans.shared.b16 {%0,%1,%2,%3},[%4];" \
    :"=r"((f)[0]),"=r"((f)[1]),"=r"((f)[2]),"=r"((f)[3]):"r"(a))
#define MMA(c,A,B) asm volatile( \
    "mma.sync.aligned.m16n8k16.row.col.f32.bf16.bf16.f32 {%0,%1,%2,%3},{%4,%5,%6,%7},{%8,%9},{%0,%1,%2,%3};" \
    :"+f"((c)[0]),"+f"((c)[1]),"+f"((c)[2]),"+f"((c)[3]) \
    :"r"((A)[0]),"r"((A)[1]),"r"((A)[2]),"r"((A)[3]),"r"((B)[0]),"r"((B)[1]))
#define MMAB(c,A,b0,b1) asm volatile( \
    "mma.sync.aligned.m16n8k16.row.col.f32.bf16.bf16.f32 {%0,%1,%2,%3},{%4,%5,%6,%7},{%8,%9},{%0,%1,%2,%3};" \
    :"+f"((c)[0]),"+f"((c)[1]),"+f"((c)[2]),"+f"((c)[3]) \
    :"r"((A)[0]),"r"((A)[1]),"r"((A)[2]),"r"((A)[3]),"r"(b0),"r"(b1))

__device__ __forceinline__ void pack2(uint32_t&h, uint32_t&l, float a, float b){
    bf16 ha=__float2bfloat16(a), hb=__float2bfloat16(b);
    __nv_bfloat162 hp, lp; hp.x=ha; hp.y=hb;
    lp.x=__float2bfloat16(a-__bfloat162float(ha));
    lp.y=__float2bfloat16(b-__bfloat162float(hb));
    h=*(uint32_t*)&hp; l=*(uint32_t*)&lp;
}

// ---------------- bf16-split HMMA GEMM (projections/FFN) ----------------
// C = (Ah+Al)[M,K] @ (Bh+Bl)[N,K]^T, 128x128 tile, BK=32, 2 stages.
// epi: 0 bias(+bias2), 1 bias+GELU ; outm: 0 fp32, 1 bf16 split
__global__ __launch_bounds__(256,2) void hgemm(
    const bf16* __restrict__ Ah_, const bf16* __restrict__ Al_,
    const bf16* __restrict__ Bh_, const bf16* __restrict__ Bl_,
    int K, int lda, int ldb, int ldc,
    float* __restrict__ Cf, bf16* __restrict__ Ch, bf16* __restrict__ Cl,
    const float* __restrict__ bias, const float* __restrict__ bias2,
    int epi, int outm)
{
    constexpr int STG = 4*10240;
    extern __shared__ char smraw[];
    uint32_t su = su32(smraw);
    int tid = threadIdx.x, wid = tid>>5, lane = tid&31;
    int wm = wid%2, wn = wid/2;
    int m0 = blockIdx.y*128, n0 = blockIdx.x*128;

    const bf16* pAh = Ah_ + (long long)m0*lda;
    const bf16* pAl = Al_ + (long long)m0*lda;
    const bf16* pBh = Bh_ + (long long)n0*ldb;
    const bf16* pBl = Bl_ + (long long)n0*ldb;
    int nk = K>>5;

    int r = tid>>2, sg = tid&3;
    auto loadstage = [&](int ci, int st){
        uint32_t b = su + (uint32_t)st*STG;
        int k0 = ci<<5;
        #pragma unroll
        for(int p=0;p<2;p++){
            int rr = r + p*64;
            uint32_t so = b + rr*80 + sg*16;
            cpa(so,       pAh + (long long)rr*lda + k0 + sg*8);
            cpa(so+10240, pAl + (long long)rr*lda + k0 + sg*8);
            uint32_t so2 = b + 20480 + rr*80 + sg*16;
            cpa(so2,      pBh + (long long)rr*ldb + k0 + sg*8);
            cpa(so2+10240,pBl + (long long)rr*ldb + k0 + sg*8);
        }
        CPCOMMIT();
    };

    float acc[4][4][4];
    #pragma unroll
    for(int a=0;a<4;a++)
        #pragma unroll
        for(int b=0;b<4;b++)
            #pragma unroll
            for(int c=0;c<4;c++) acc[a][b][c]=0.f;

    int quad = lane>>3, lq = lane&7;
    uint32_t aoff = (uint32_t)((wm*64 + (quad&1)*8 + lq)*80 + (quad>>1)*16);
    uint32_t boff = (uint32_t)(20480 + (wn*32 + (quad>>1)*8 + lq)*80 + (quad&1)*16);

    loadstage(0,0);
    if(nk>1) loadstage(1,1);

    for(int i=0;i<nk;i++){
        if(i+1<nk) asm volatile("cp.async.wait_group 1;":::"memory");
        else       asm volatile("cp.async.wait_group 0;":::"memory");
        __syncthreads();
        uint32_t sb = su + (uint32_t)(i&1)*STG;
        uint32_t pa_h = sb + aoff, pa_l = pa_h + 10240;
        uint32_t pb_h = sb + boff, pb_l = pb_h + 10240;
        uint32_t Af[4][4], Bf[4][2], Bt[4][2];
        #pragma unroll
        for(int ks=0;ks<2;ks++){
            uint32_t kso = ks*32;
            #pragma unroll
            for(int mt=0;mt<4;mt++) LDM4(Af[mt], pa_h + mt*1280 + kso);
            #pragma unroll
            for(int np=0;np<2;np++)
                LDM4B(Bf[2*np][0],Bf[2*np][1],Bf[2*np+1][0],Bf[2*np+1][1], pb_h + np*1280 + kso);
            #pragma unroll
            for(int mt=0;mt<4;mt++)
                #pragma unroll
                for(int nt=0;nt<4;nt++) MMA(acc[mt][nt],Af[mt],Bf[nt]);
            #pragma unroll
            for(int np=0;np<2;np++)
                LDM4B(Bt[2*np][0],Bt[2*np][1],Bt[2*np+1][0],Bt[2*np+1][1], pb_l + np*1280 + kso);
            #pragma unroll
            for(int mt=0;mt<4;mt++)
                #pragma unroll
                for(int nt=0;nt<4;nt++) MMA(acc[mt][nt],Af[mt],Bt[nt]);
            #pragma unroll
            for(int mt=0;mt<4;mt++) LDM4(Af[mt], pa_l + mt*1280 + kso);
            #pragma unroll
            for(int mt=0;mt<4;mt++)
                #pragma unroll
                for(int nt=0;nt<4;nt++) MMA(acc[mt][nt],Af[mt],Bf[nt]);
        }
        __syncthreads();
        if(i+2<nk) loadstage(i+2, i&1);
    }

    auto store2 = [&](int row,int col,float v0,float v1){
        if(bias){ v0+=bias[col]; v1+=bias[col+1]; }
        if(bias2){ v0+=bias2[col]; v1+=bias2[col+1]; }
        if(epi==1){
            v0 = 0.5f*v0*(1.0f+erff(v0*0.70710678118654752f));
            v1 = 0.5f*v1*(1.0f+erff(v1*0.70710678118654752f));
        }
        if(outm==0){
            *(float2*)&Cf[(long long)row*ldc+col] = make_float2(v0,v1);
        } else {
            long long ix = (long long)row*ldc+col;
            bf16 h0=__float2bfloat16(v0), h1=__float2bfloat16(v1);
            __nv_bfloat162 hp,lp; hp.x=h0; hp.y=h1;
            lp.x=__float2bfloat16(v0-__bfloat162float(h0));
            lp.y=__float2bfloat16(v1-__bfloat162float(h1));
            *(__nv_bfloat162*)(Ch+ix)=hp; *(__nv_bfloat162*)(Cl+ix)=lp;
        }
    };
    #pragma unroll
    for(int mt=0;mt<4;mt++){
        #pragma unroll
        for(int nt=0;nt<4;nt++){
            int row0 = m0 + wm*64 + mt*16 + (lane>>2);
            int col  = n0 + wn*32 + nt*8 + ((lane&3)<<1);
            store2(row0,   col, acc[mt][nt][0], acc[mt][nt][1]);
            store2(row0+8, col, acc[mt][nt][2], acc[mt][nt][3]);
        }
    }
}

// ---------------- flash attention ----------------
// per CTA: 128 q rows of one (b,h). S = (Qh+Ql)(Kh+Kl)^T (3 products),
// epi: /T, mask, *gate; online softmax; O += (Ph+Pl)(Vh+Vl) (3 products).
#define PITCH 144
__global__ __launch_bounds__(256,1) void flashattn(
    const bf16* __restrict__ qh_, const bf16* __restrict__ ql_,
    const bf16* __restrict__ kh_, const bf16* __restrict__ kl_,
    const bf16* __restrict__ vh_, const bf16* __restrict__ vl_,
    const int* __restrict__ mask, const float* __restrict__ gate,
    const float* __restrict__ temp,
    bf16* __restrict__ ch, bf16* __restrict__ cl)
{
    extern __shared__ char sm[];
    uint32_t su = su32(sm);
    const uint32_t QL=18432, ST=36864, STSZ=73728;
    int tid=threadIdx.x, wid=tid>>5, lane=tid&31;
    int quad=lane>>3, lq=lane&7;
    int z=blockIdx.y, zb=z>>4, zh=z&15;
    int q0=blockIdx.x*128;
    long long hoff=(long long)zb*SD + zh*64;
    const bf16* pq_h = qh_ + hoff + (long long)q0*DMODEL;
    const bf16* pq_l = ql_ + hoff + (long long)q0*DMODEL;

    int cc=tid&7, rr0=tid>>3;
    #pragma unroll
    for(int p=0;p<4;p++){
        int r=rr0+p*32;
        long long go=(long long)r*DMODEL + cc*8;
        uint32_t so=r*PITCH + cc*16;
        cpa(su+so, pq_h+go); cpa(su+QL+so, pq_l+go);
    }
    CPCOMMIT();

    auto ldstage=[&](int it,int st){
        uint32_t b=su+ST+(uint32_t)st*STSZ;
        long long kbase=hoff + (long long)(it*128)*DMODEL;
        #pragma unroll
        for(int p=0;p<4;p++){
            int r=rr0+p*32;
            long long go=kbase+(long long)r*DMODEL+cc*8;
            uint32_t so=r*PITCH+cc*16;
            cpa(b+so, kh_+go);        cpa(b+18432+so, kl_+go);
            cpa(b+36864+so, vh_+go);  cpa(b+55296+so, vl_+go);
        }
        CPCOMMIT();
    };
    ldstage(0,0); ldstage(1,1);
    asm volatile("cp.async.wait_group 2;":::"memory");
    __syncthreads();

    // Q fragments (resident in registers for the whole CTA lifetime)
    uint32_t qaddr = su + (uint32_t)((wid*16 + (quad&1)*8 + lq)*PITCH + (quad>>1)*16);
    uint32_t qfh[4][4], qfl[4][4];
    #pragma unroll
    for(int ks=0;ks<4;ks++){ LDM4(qfh[ks], qaddr+ks*32); LDM4(qfl[ks], qaddr+QL+ks*32); }

    int r0l = wid*16 + (lane>>2);              // local q row 0..127
    float g0 = gate[(long long)z*SSEQ + q0 + r0l];
    float g1 = gate[(long long)z*SSEQ + q0 + r0l + 8];
    float invT = 1.f/temp[0];
    float m0=-1e30f,m1=-1e30f,l0=0.f,l1=0.f;
    float oacc[8][4];
    #pragma unroll
    for(int d=0;d<8;d++){oacc[d][0]=0;oacc[d][1]=0;oacc[d][2]=0;oacc[d][3]=0;}

    for(int it=0; it<16; it++){
        if(it<15) asm volatile("cp.async.wait_group 1;":::"memory");
        else      asm volatile("cp.async.wait_group 0;":::"memory");
        __syncthreads();
        uint32_t sb = su+ST+(uint32_t)(it&1)*STSZ;

        // ---- S = Q K^T (3 products) ----
        float sacc[16][4];
        #pragma unroll
        for(int nt=0;nt<16;nt++){sacc[nt][0]=0;sacc[nt][1]=0;sacc[nt][2]=0;sacc[nt][3]=0;}
        uint32_t baddr = sb + (uint32_t)((lq + 8*(quad>>1))*PITCH + (quad&1)*16);
        #pragma unroll
        for(int ks=0;ks<4;ks++){
            uint32_t b[16][2];
            #pragma unroll
            for(int j=0;j<8;j++)
                LDM4B(b[2*j][0],b[2*j][1],b[2*j+1][0],b[2*j+1][1], baddr + j*(16*PITCH) + ks*32);
            #pragma unroll
            for(int nt=0;nt<16;nt++) MMA(sacc[nt], qfh[ks], b[nt]);
            #pragma unroll
            for(int nt=0;nt<16;nt++) MMA(sacc[nt], qfl[ks], b[nt]);
            #pragma unroll
            for(int j=0;j<8;j++)
                LDM4B(b[2*j][0],b[2*j][1],b[2*j+1][0],b[2*j+1][1], baddr + 18432 + j*(16*PITCH) + ks*32);
            #pragma unroll
            for(int nt=0;nt<16;nt++) MMA(sacc[nt], qfh[ks], b[nt]);
        }

        // ---- epilogue: /T, mask, *gate; row max ----
        long long mrow0 = (long long)(q0 + r0l)*SSEQ + it*128 + 2*(lane&3);
        long long mrow1 = mrow0 + 8LL*SSEQ;
        float rm0=-1e30f, rm1=-1e30f;
        #pragma unroll
        for(int nt=0;nt<16;nt++){
            int2 mA = *(const int2*)&mask[mrow0 + nt*8];
            int2 mB = *(const int2*)&mask[mrow1 + nt*8];
            float s0=sacc[nt][0]*invT, s1=sacc[nt][1]*invT;
            float s2=sacc[nt][2]*invT, s3=sacc[nt][3]*invT;
            if(mA.x==0)s0=-1e9f; if(mA.y==0)s1=-1e9f;
            if(mB.x==0)s2=-1e9f; if(mB.y==0)s3=-1e9f;
            s0*=g0;s1*=g0;s2*=g1;s3*=g1;
            sacc[nt][0]=s0;sacc[nt][1]=s1;sacc[nt][2]=s2;sacc[nt][3]=s3;
            rm0=fmaxf(rm0,fmaxf(s0,s1)); rm1=fmaxf(rm1,fmaxf(s2,s3));
        }
        rm0=fmaxf(rm0,__shfl_xor_sync(~0u,rm0,1)); rm0=fmaxf(rm0,__shfl_xor_sync(~0u,rm0,2));
        rm1=fmaxf(rm1,__shfl_xor_sync(~0u,rm1,1)); rm1=fmaxf(rm1,__shfl_xor_sync(~0u,rm1,2));
        float mn0=fmaxf(m0,rm0), mn1=fmaxf(m1,rm1);
        float sc0=__expf(m0-mn0), sc1=__expf(m1-mn1);
        m0=mn0; m1=mn1;

        // ---- P = exp(S - m); row sums ----
        float rs0=0.f, rs1=0.f;
        #pragma unroll
        for(int nt=0;nt<16;nt++){
            float p0=__expf(sacc[nt][0]-m0), p1=__expf(sacc[nt][1]-m0);
            float p2=__expf(sacc[nt][2]-m1), p3=__expf(sacc[nt][3]-m1);
            sacc[nt][0]=p0;sacc[nt][1]=p1;sacc[nt][2]=p2;sacc[nt][3]=p3;
            rs0+=p0+p1; rs1+=p2+p3;
        }
        rs0+=__shfl_xor_sync(~0u,rs0,1); rs0+=__shfl_xor_sync(~0u,rs0,2);
        rs1+=__shfl_xor_sync(~0u,rs1,1); rs1+=__shfl_xor_sync(~0u,rs1,2);
        l0 = l0*sc0 + rs0; l1 = l1*sc1 + rs1;
        #pragma unroll
        for(int d=0;d<8;d++){ oacc[d][0]*=sc0; oacc[d][1]*=sc0; oacc[d][2]*=sc1; oacc[d][3]*=sc1; }

        // ---- O += P V (3 products) ----
        #pragma unroll
        for(int kv=0;kv<8;kv++){
            uint32_t pa[4], pb[4];
            pack2(pa[0],pb[0], sacc[2*kv][0],   sacc[2*kv][1]);
            pack2(pa[1],pb[1], sacc[2*kv][2],   sacc[2*kv][3]);
            pack2(pa[2],pb[2], sacc[2*kv+1][0], sacc[2*kv+1][1]);
            pack2(pa[3],pb[3], sacc[2*kv+1][2], sacc[2*kv+1][3]);
            uint32_t vbase = sb + 36864 + (uint32_t)((16*kv + lq + 8*(quad&1))*PITCH + 16*(quad>>1));
            #pragma unroll
            for(int jp=0;jp<4;jp++){
                uint32_t vh4[4], vl4[4];
                LDM4T(vh4, vbase + jp*32);
                LDM4T(vl4, vbase + 18432 + jp*32);
                MMAB(oacc[2*jp],   pa, vh4[0], vh4[1]);
                MMAB(oacc[2*jp+1], pa, vh4[2], vh4[3]);
                MMAB(oacc[2*jp],   pa, vl4[0], vl4[1]);
                MMAB(oacc[2*jp+1], pa, vl4[2], vl4[3]);
                MMAB(oacc[2*jp],   pb, vh4[0], vh4[1]);
                MMAB(oacc[2*jp+1], pb, vh4[2], vh4[3]);
            }
        }
        __syncthreads();
        if(it+2<16) ldstage(it+2, it&1);
    }

    // ---- normalize + split store ----
    float inv0=1.f/l0, inv1=1.f/l1;
    long long orow0 = (long long)zb*SD + (long long)(q0+r0l)*DMODEL + zh*64;
    long long orow1 = orow0 + 8LL*DMODEL;
    #pragma unroll
    for(int d=0;d<8;d++){
        int col = d*8 + 2*(lane&3);
        float v0=oacc[d][0]*inv0, v1=oacc[d][1]*inv0;
        float v2=oacc[d][2]*inv1, v3=oacc[d][3]*inv1;
        uint32_t h,l;
        pack2(h,l,v0,v1);
        *(uint32_t*)(ch+orow0+col)=h; *(uint32_t*)(cl+orow0+col)=l;
        pack2(h,l,v2,v3);
        *(uint32_t*)(ch+orow1+col)=h; *(uint32_t*)(cl+orow1+col)=l;
    }
}

// ---------------- support kernels ----------------
__global__ void split_vk(const float* __restrict__ in, bf16* __restrict__ hi,
                         bf16* __restrict__ lo, int n4){
    int i=blockIdx.x*blockDim.x+threadIdx.x; if(i>=n4)return;
    float4 v=((const float4*)in)[i];
    bf16 h0=__float2bfloat16(v.x),h1=__float2bfloat16(v.y),h2=__float2bfloat16(v.z),h3=__float2bfloat16(v.w);
    __nv_bfloat162 a,b,c,d; a.x=h0;a.y=h1;b.x=h2;b.y=h3;
    c.x=__float2bfloat16(v.x-__bfloat162float(h0)); c.y=__float2bfloat16(v.y-__bfloat162float(h1));
    d.x=__float2bfloat16(v.z-__bfloat162float(h2)); d.y=__float2bfloat16(v.w-__bfloat162float(h3));
    ((__nv_bfloat162*)hi)[2*i]=a; ((__nv_bfloat162*)hi)[2*i+1]=b;
    ((__nv_bfloat162*)lo)[2*i]=c; ((__nv_bfloat162*)lo)[2*i+1]=d;
}
__global__ void split_T(const float* __restrict__ W, bf16* __restrict__ hi,
                        bf16* __restrict__ lo, int R, int C){
    __shared__ float t[32][33];
    int c0=blockIdx.x*32, r0=blockIdx.y*32, tx=threadIdx.x, ty=threadIdx.y;
    for(int i=ty;i<32;i+=8) t[i][tx]=W[(long long)(r0+i)*C+c0+tx];
    __syncthreads();
    for(int i=ty;i<32;i+=8){
        float v=t[tx][i]; long long ix=(long long)(c0+i)*R+r0+tx;
        bf16 h=__float2bfloat16(v); hi[ix]=h; lo[ix]=__float2bfloat16(v-__bfloat162float(h));
    }
}
__global__ void gatek(const bf16* __restrict__ qh,const bf16* __restrict__ ql,
                      const float* __restrict__ gW,const float* __restrict__ gb,
                      float* __restrict__ gate){
    int warp=(blockIdx.x*blockDim.x+threadIdx.x)>>5, lane=threadIdx.x&31;
    if(warp>=ROWS*NHEADS)return;
    int bs=warp>>4,h=warp&15;
    long long base=(long long)bs*DMODEL+h*DKH;
    float q0=__bfloat162float(qh[base+lane])+__bfloat162float(ql[base+lane]);
    float q1=__bfloat162float(qh[base+lane+32])+__bfloat162float(ql[base+lane+32]);
    float s=q0*gW[lane]+q1*gW[lane+32];
    #pragma unroll
    for(int o=16;o;o>>=1)s+=__shfl_xor_sync(~0u,s,o);
    if(lane==0){int b=bs>>11,sr=bs&2047;
        gate[(long long)(b*NHEADS+h)*SSEQ+sr]=1.f/(1.f+expf(-(s+gb[0])));}
}
__device__ __forceinline__ float wSum(float v){
    #pragma unroll
    for(int o=16;o;o>>=1)v+=__shfl_xor_sync(~0u,v,o); return v;}

__global__ void __launch_bounds__(256) layernorm_k(const float* __restrict__ a,
    const float* __restrict__ resid, const float* __restrict__ g, const float* __restrict__ b,
    float* __restrict__ outf, bf16* __restrict__ oh, bf16* __restrict__ ol){
    long long row=blockIdx.x;
    const float* pa=a+row*DMODEL;
    const float* pr=resid?resid+row*DMODEL:nullptr;
    int t=threadIdx.x,lane=t&31,wid=t>>5;
    __shared__ float s1[8],s2a[8]; __shared__ float bm,brs;
    float v[4],s=0.f,s2=0.f;
    #pragma unroll
    for(int i=0;i<4;i++){int d=t+i*256;float x=pa[d]+(pr?pr[d]:0.f);v[i]=x;s+=x;s2+=x*x;}
    s=wSum(s);s2=wSum(s2);
    if(lane==0){s1[wid]=s;s2a[wid]=s2;} __syncthreads();
    if(wid==0){float xs=(lane<8)?s1[lane]:0.f,x2=(lane<8)?s2a[lane]:0.f;
        xs=wSum(xs);x2=wSum(x2);
        if(lane==0){float mean=xs*(1.f/DMODEL);float var=fmaxf(x2*(1.f/DMODEL)-mean*mean,0.f);
            bm=mean;brs=rsqrtf(var+1e-5f);}}
    __syncthreads();
    float mean=bm,rstd=brs;
    #pragma unroll
    for(int i=0;i<4;i++){int d=t+i*256;float y=(v[i]-mean)*rstd*g[d]+b[d];
        if(outf)outf[row*DMODEL+d]=y;
        if(oh){bf16 h=__float2bfloat16(y);oh[row*DMODEL+d]=h;
               ol[row*DMODEL+d]=__float2bfloat16(y-__bfloat162float(h));}}
}

// ---------------- launch ----------------
extern "C" void kernel_launch(void* const* d_in, const int* in_sizes, int n_in,
                              void* d_out, int out_size)
{
    const float* x   =(const float*)d_in[0];
    const int*  mask =(const int*)  d_in[1];
    const float* Wq=(const float*)d_in[2],  *bq=(const float*)d_in[3];
    const float* Wk=(const float*)d_in[4],  *bk=(const float*)d_in[5];
    const float* Wv=(const float*)d_in[6],  *bv=(const float*)d_in[7];
    const float* Wo=(const float*)d_in[8],  *bo=(const float*)d_in[9];
    const float* temp=(const float*)d_in[10], *tw=(const float*)d_in[11];
    const float* gW=(const float*)d_in[12], *gb=(const float*)d_in[13];
    const float* lag=(const float*)d_in[14],*lab=(const float*)d_in[15];
    const float* f1W=(const float*)d_in[16],*f1b=(const float*)d_in[17];
    const float* f2W=(const float*)d_in[18],*f2b=(const float*)d_in[19];
    const float* n1g=(const float*)d_in[20],*n1b=(const float*)d_in[21];
    const float* n2g=(const float*)d_in[22],*n2b=(const float*)d_in[23];
    float* out=(float*)d_out;

    float *t0,*x1,*attn,*gatep;
    bf16 *xh,*xl,*qh,*ql,*kh,*kl,*vh,*vl,*ch,*cl,*yh,*yl,*fh,*fl;
    bf16 *wqh,*wql,*wkh,*wkl,*wvh,*wvl,*woh,*wol,*w1h,*w1l,*w2h,*w2l;
    cudaGetSymbolAddress((void**)&t0,g_t0);   cudaGetSymbolAddress((void**)&x1,g_x1);
    cudaGetSymbolAddress((void**)&attn,g_attn);cudaGetSymbolAddress((void**)&gatep,g_gate);
    cudaGetSymbolAddress((void**)&xh,g_xh); cudaGetSymbolAddress((void**)&xl,g_xl);
    cudaGetSymbolAddress((void**)&qh,g_qh); cudaGetSymbolAddress((void**)&ql,g_ql);
    cudaGetSymbolAddress((void**)&kh,g_kh); cudaGetSymbolAddress((void**)&kl,g_kl);
    cudaGetSymbolAddress((void**)&vh,g_vh); cudaGetSymbolAddress((void**)&vl,g_vl);
    cudaGetSymbolAddress((void**)&ch,g_ch); cudaGetSymbolAddress((void**)&cl,g_cl);
    cudaGetSymbolAddress((void**)&yh,g_yh); cudaGetSymbolAddress((void**)&yl,g_yl);
    cudaGetSymbolAddress((void**)&fh,g_fh); cudaGetSymbolAddress((void**)&fl,g_fl);
    cudaGetSymbolAddress((void**)&wqh,g_wqh);cudaGetSymbolAddress((void**)&wql,g_wql);
    cudaGetSymbolAddress((void**)&wkh,g_wkh);cudaGetSymbolAddress((void**)&wkl,g_wkl);
    cudaGetSymbolAddress((void**)&wvh,g_wvh);cudaGetSymbolAddress((void**)&wvl,g_wvl);
    cudaGetSymbolAddress((void**)&woh,g_woh);cudaGetSymbolAddress((void**)&wol,g_wol);
    cudaGetSymbolAddress((void**)&w1h,g_w1h);cudaGetSymbolAddress((void**)&w1l,g_w1l);
    cudaGetSymbolAddress((void**)&w2h,g_w2h);cudaGetSymbolAddress((void**)&w2l,g_w2l);

    const int SMG = 2*4*10240;                 // 81920
    const int SMF = 36864 + 2*73728;           // 184320
    cudaFuncSetAttribute((const void*)hgemm,    cudaFuncAttributeMaxDynamicSharedMemorySize,SMG);
    cudaFuncSetAttribute((const void*)flashattn,cudaFuncAttributeMaxDynamicSharedMemorySize,SMF);

    // conversions
    split_vk<<<ROWS*DMODEL/4/256,256>>>(x,xh,xl,ROWS*DMODEL/4);
    dim3 tb(32,8);
    split_T<<<dim3(DMODEL/32,DMODEL/32),tb>>>(Wq,wqh,wql,DMODEL,DMODEL);
    split_T<<<dim3(DMODEL/32,DMODEL/32),tb>>>(Wk,wkh,wkl,DMODEL,DMODEL);
    split_T<<<dim3(DMODEL/32,DMODEL/32),tb>>>(Wv,wvh,wvl,DMODEL,DMODEL);
    split_T<<<dim3(DMODEL/32,DMODEL/32),tb>>>(Wo,woh,wol,DMODEL,DMODEL);
    split_T<<<dim3(DFF/32,DMODEL/32),tb>>>(f1W,w1h,w1l,DMODEL,DFF);
    split_T<<<dim3(DMODEL/32,DFF/32),tb>>>(f2W,w2h,w2l,DFF,DMODEL);

    // projections (Q bias2 = time_weights flattened [H*dk])
    dim3 gP(DMODEL/128,ROWS/128,1);
    hgemm<<<gP,256,SMG>>>(xh,xl,wqh,wql,DMODEL,DMODEL,DMODEL,DMODEL,
        nullptr,qh,ql,bq,tw,0,1);
    hgemm<<<gP,256,SMG>>>(xh,xl,wkh,wkl,DMODEL,DMODEL,DMODEL,DMODEL,
        nullptr,kh,kl,bk,nullptr,0,1);
    hgemm<<<gP,256,SMG>>>(xh,xl,wvh,wvl,DMODEL,DMODEL,DMODEL,DMODEL,
        nullptr,vh,vl,bv,nullptr,0,1);

    gatek<<<(ROWS*NHEADS)/8,256>>>(qh,ql,gW,gb,gatep);

    // fused attention -> ctx split
    dim3 gA(SSEQ/128, ZTOT, 1);
    flashattn<<<gA,256,SMF>>>(qh,ql,kh,kl,vh,vl,mask,gatep,temp,ch,cl);

    // Wo projection + LN chain
    hgemm<<<gP,256,SMG>>>(ch,cl,woh,wol,DMODEL,DMODEL,DMODEL,DMODEL,
        t0,nullptr,nullptr,bo,nullptr,0,0);
    layernorm_k<<<ROWS,256>>>(t0,nullptr,lag,lab,attn,nullptr,nullptr);
    layernorm_k<<<ROWS,256>>>(x,attn,n1g,n1b,x1,yh,yl);

    // FFN
    dim3 gF(DFF/128,ROWS/128,1);
    hgemm<<<gF,256,SMG>>>(yh,yl,w1h,w1l,DMODEL,DMODEL,DMODEL,DFF,
        nullptr,fh,fl,f1b,nullptr,1,1);
    hgemm<<<gP,256,SMG>>>(fh,fl,w2h,w2l,DFF,DFF,DFF,DMODEL,
        t0,nullptr,nullptr,f2b,nullptr,0,0);

    layernorm_k<<<ROWS,256>>>(x1,t0,n2g,n2b,out,nullptr,nullptr);
}

// round 7
// speedup vs baseline: 5.8163x; 1.1880x over previous
#include <cuda_runtime.h>
#include <cuda_fp16.h>
#include <math.h>
#include <stdint.h>

#define SSEQ 2048
#define DMODEL 1024
#define NHEADS 16
#define DKH 64
#define DFF 4096
#define ROWS 4096
#define ZTOT 32
#define SD ((long long)SSEQ*DMODEL)
typedef __half hf;

// ---------------- scratch ----------------
__device__ __align__(256) float g_t0[ROWS*DMODEL];
__device__ __align__(256) float g_x1[ROWS*DMODEL];
__device__ __align__(256) float g_gate[ZTOT*SSEQ];
__device__ __align__(256) hf g_xh[ROWS*DMODEL], g_xl[ROWS*DMODEL];
__device__ __align__(256) hf g_qh[ROWS*DMODEL], g_ql[ROWS*DMODEL];
__device__ __align__(256) hf g_kh[ROWS*DMODEL], g_kl[ROWS*DMODEL];
__device__ __align__(256) hf g_vh[ROWS*DMODEL];
__device__ __align__(256) hf g_ch[ROWS*DMODEL], g_cl[ROWS*DMODEL];
__device__ __align__(256) hf g_yh[ROWS*DMODEL], g_yl[ROWS*DMODEL];
__device__ __align__(256) hf g_fh[ROWS*DFF], g_fl[ROWS*DFF];
__device__ __align__(256) hf g_wqh[DMODEL*DMODEL], g_wql[DMODEL*DMODEL];
__device__ __align__(256) hf g_wkh[DMODEL*DMODEL], g_wkl[DMODEL*DMODEL];
__device__ __align__(256) hf g_wvh[DMODEL*DMODEL], g_wvl[DMODEL*DMODEL];
__device__ __align__(256) hf g_woh[DMODEL*DMODEL], g_wol[DMODEL*DMODEL];
__device__ __align__(256) hf g_w1h[DMODEL*DFF], g_w1l[DMODEL*DFF];
__device__ __align__(256) hf g_w2h[DMODEL*DFF], g_w2l[DMODEL*DFF];

// ---------------- helpers ----------------
__device__ __forceinline__ uint32_t su32(const void* p){uint32_t a;
    asm("{.reg .u64 t; cvta.to.shared.u64 t,%1; cvt.u32.u64 %0,t;}":"=r"(a):"l"(p));return a;}
__device__ __forceinline__ void cpa(uint32_t d,const void*s){
    asm volatile("cp.async.cg.shared.global [%0],[%1],16;"::"r"(d),"l"(s));}
#define CPCOMMIT() asm volatile("cp.async.commit_group;":::"memory")
#define LDM4(f,a) asm volatile("ldmatrix.sync.aligned.m8n8.x4.shared.b16 {%0,%1,%2,%3},[%4];" \
    :"=r"((f)[0]),"=r"((f)[1]),"=r"((f)[2]),"=r"((f)[3]):"r"(a))
#define LDM4B(b0,b1,b2,b3,a) asm volatile("ldmatrix.sync.aligned.m8n8.x4.shared.b16 {%0,%1,%2,%3},[%4];" \
    :"=r"(b0),"=r"(b1),"=r"(b2),"=r"(b3):"r"(a))
#define LDM4T(f,a) asm volatile("ldmatrix.sync.aligned.m8n8.x4.trans.shared.b16 {%0,%1,%2,%3},[%4];" \
    :"=r"((f)[0]),"=r"((f)[1]),"=r"((f)[2]),"=r"((f)[3]):"r"(a))
#define MMA(c,A,B) asm volatile( \
    "mma.sync.aligned.m16n8k16.row.col.f32.f16.f16.f32 {%0,%1,%2,%3},{%4,%5,%6,%7},{%8,%9},{%0,%1,%2,%3};" \
    :"+f"((c)[0]),"+f"((c)[1]),"+f"((c)[2]),"+f"((c)[3]) \
    :"r"((A)[0]),"r"((A)[1]),"r"((A)[2]),"r"((A)[3]),"r"((B)[0]),"r"((B)[1]))
#define MMAB(c,A,b0,b1) asm volatile( \
    "mma.sync.aligned.m16n8k16.row.col.f32.f16.f16.f32 {%0,%1,%2,%3},{%4,%5,%6,%7},{%8,%9},{%0,%1,%2,%3};" \
    :"+f"((c)[0]),"+f"((c)[1]),"+f"((c)[2]),"+f"((c)[3]) \
    :"r"((A)[0]),"r"((A)[1]),"r"((A)[2]),"r"((A)[3]),"r"(b0),"r"(b1))

__device__ __forceinline__ void pack2(uint32_t&h, uint32_t&l, float a, float b){
    hf ha=__float2half_rn(a), hb=__float2half_rn(b);
    __half2 hp; hp.x=ha; hp.y=hb;
    __half2 lp=__floats2half2_rn(a-__half2float(ha), b-__half2float(hb));
    h=*(uint32_t*)&hp; l=*(uint32_t*)&lp;
}
__device__ __forceinline__ uint32_t pack2h(float a, float b){
    __half2 hp=__floats2half2_rn(a,b);
    return *(uint32_t*)&hp;
}

// ---------------- fp16-split HMMA GEMM ----------------
// C = (Ah+Al)[M,K] @ (Bh[+Bl])[N,K]^T. 128x128 tile, BK=32, 2 stages.
// Bl!=null: 3 products (hh + hl + lh). Bl==null: 2 products (hh + lh).
// epi: 0 bias(+bias2), 1 bias+GELU ; outm: 0 fp32, 1 split, 3 hi-only
__global__ __launch_bounds__(256,2) void hgemm(
    const hf* __restrict__ Ah_, const hf* __restrict__ Al_,
    const hf* __restrict__ Bh_, const hf* __restrict__ Bl_,
    int K, int lda, int ldb, int ldc,
    float* __restrict__ Cf, hf* __restrict__ Ch, hf* __restrict__ Cl,
    const float* __restrict__ bias, const float* __restrict__ bias2,
    int epi, int outm)
{
    constexpr int STG = 4*10240;
    extern __shared__ char smraw[];
    uint32_t su = su32(smraw);
    int tid = threadIdx.x, wid = tid>>5, lane = tid&31;
    int wm = wid%2, wn = wid/2;
    int m0 = blockIdx.y*128, n0 = blockIdx.x*128;

    const hf* pAh = Ah_ + (long long)m0*lda;
    const hf* pAl = Al_ + (long long)m0*lda;
    const hf* pBh = Bh_ + (long long)n0*ldb;
    const hf* pBl = Bl_ ? Bl_ + (long long)n0*ldb : nullptr;
    int nk = K>>5;

    int r = tid>>2, sg = tid&3;
    auto loadstage = [&](int ci, int st){
        uint32_t b = su + (uint32_t)st*STG;
        int k0 = ci<<5;
        #pragma unroll
        for(int p=0;p<2;p++){
            int rr = r + p*64;
            uint32_t so = b + rr*80 + sg*16;
            cpa(so,       pAh + (long long)rr*lda + k0 + sg*8);
            cpa(so+10240, pAl + (long long)rr*lda + k0 + sg*8);
            uint32_t so2 = b + 20480 + rr*80 + sg*16;
            cpa(so2,      pBh + (long long)rr*ldb + k0 + sg*8);
            if(pBl) cpa(so2+10240, pBl + (long long)rr*ldb + k0 + sg*8);
        }
        CPCOMMIT();
    };

    float acc[4][4][4];
    #pragma unroll
    for(int a=0;a<4;a++)
        #pragma unroll
        for(int b=0;b<4;b++)
            #pragma unroll
            for(int c=0;c<4;c++) acc[a][b][c]=0.f;

    int quad = lane>>3, lq = lane&7;
    uint32_t aoff = (uint32_t)((wm*64 + (quad&1)*8 + lq)*80 + (quad>>1)*16);
    uint32_t boff = (uint32_t)(20480 + (wn*32 + (quad>>1)*8 + lq)*80 + (quad&1)*16);

    loadstage(0,0);
    if(nk>1) loadstage(1,1);

    for(int i=0;i<nk;i++){
        if(i+1<nk) asm volatile("cp.async.wait_group 1;":::"memory");
        else       asm volatile("cp.async.wait_group 0;":::"memory");
        __syncthreads();
        uint32_t sb = su + (uint32_t)(i&1)*STG;
        uint32_t pa_h = sb + aoff, pa_l = pa_h + 10240;
        uint32_t pb_h = sb + boff, pb_l = pb_h + 10240;
        uint32_t Af[4][4], Bf[4][2], Bt[4][2];
        #pragma unroll
        for(int ks=0;ks<2;ks++){
            uint32_t kso = ks*32;
            #pragma unroll
            for(int mt=0;mt<4;mt++) LDM4(Af[mt], pa_h + mt*1280 + kso);
            #pragma unroll
            for(int np=0;np<2;np++)
                LDM4B(Bf[2*np][0],Bf[2*np][1],Bf[2*np+1][0],Bf[2*np+1][1], pb_h + np*1280 + kso);
            #pragma unroll
            for(int mt=0;mt<4;mt++)
                #pragma unroll
                for(int nt=0;nt<4;nt++) MMA(acc[mt][nt],Af[mt],Bf[nt]);
            if(Bl_){
                #pragma unroll
                for(int np=0;np<2;np++)
                    LDM4B(Bt[2*np][0],Bt[2*np][1],Bt[2*np+1][0],Bt[2*np+1][1], pb_l + np*1280 + kso);
                #pragma unroll
                for(int mt=0;mt<4;mt++)
                    #pragma unroll
                    for(int nt=0;nt<4;nt++) MMA(acc[mt][nt],Af[mt],Bt[nt]);
            }
            #pragma unroll
            for(int mt=0;mt<4;mt++) LDM4(Af[mt], pa_l + mt*1280 + kso);
            #pragma unroll
            for(int mt=0;mt<4;mt++)
                #pragma unroll
                for(int nt=0;nt<4;nt++) MMA(acc[mt][nt],Af[mt],Bf[nt]);
        }
        __syncthreads();
        if(i+2<nk) loadstage(i+2, i&1);
    }

    auto store2 = [&](int row,int col,float v0,float v1){
        if(bias){ v0+=bias[col]; v1+=bias[col+1]; }
        if(bias2){ v0+=bias2[col]; v1+=bias2[col+1]; }
        if(epi==1){
            v0 = 0.5f*v0*(1.0f+erff(v0*0.70710678118654752f));
            v1 = 0.5f*v1*(1.0f+erff(v1*0.70710678118654752f));
        }
        if(outm==0){
            *(float2*)&Cf[(long long)row*ldc+col] = make_float2(v0,v1);
        } else if(outm==1){
            long long ix = (long long)row*ldc+col;
            uint32_t h,l; pack2(h,l,v0,v1);
            *(uint32_t*)(Ch+ix)=h; *(uint32_t*)(Cl+ix)=l;
        } else {
            long long ix = (long long)row*ldc+col;
            *(uint32_t*)(Ch+ix) = pack2h(v0,v1);
        }
    };
    #pragma unroll
    for(int mt=0;mt<4;mt++){
        #pragma unroll
        for(int nt=0;nt<4;nt++){
            int row0 = m0 + wm*64 + mt*16 + (lane>>2);
            int col  = n0 + wn*32 + nt*8 + ((lane&3)<<1);
            store2(row0,   col, acc[mt][nt][0], acc[mt][nt][1]);
            store2(row0+8, col, acc[mt][nt][2], acc[mt][nt][3]);
        }
    }
}

// ---------------- flash attention ----------------
// S = (Qh+Ql)(Kh+Kl)^T (3 products); /T, mask, *gate; online softmax;
// O += (Ph+Pl)·Vh (2 products, V hi-only).
#define PITCH 144
__global__ __launch_bounds__(256,1) void flashattn(
    const hf* __restrict__ qh_, const hf* __restrict__ ql_,
    const hf* __restrict__ kh_, const hf* __restrict__ kl_,
    const hf* __restrict__ vh_,
    const int* __restrict__ mask, const float* __restrict__ gate,
    const float* __restrict__ temp,
    hf* __restrict__ ch, hf* __restrict__ cl)
{
    extern __shared__ char sm[];
    uint32_t su = su32(sm);
    const uint32_t QL=18432, ST=36864, STSZ=55296;
    int tid=threadIdx.x, wid=tid>>5, lane=tid&31;
    int quad=lane>>3, lq=lane&7;
    int z=blockIdx.y, zb=z>>4, zh=z&15;
    int q0=blockIdx.x*128;
    long long hoff=(long long)zb*SD + zh*64;
    const hf* pq_h = qh_ + hoff + (long long)q0*DMODEL;
    const hf* pq_l = ql_ + hoff + (long long)q0*DMODEL;

    int cc=tid&7, rr0=tid>>3;
    #pragma unroll
    for(int p=0;p<4;p++){
        int r=rr0+p*32;
        long long go=(long long)r*DMODEL + cc*8;
        uint32_t so=r*PITCH + cc*16;
        cpa(su+so, pq_h+go); cpa(su+QL+so, pq_l+go);
    }
    CPCOMMIT();

    auto ldstage=[&](int it,int st){
        uint32_t b=su+ST+(uint32_t)st*STSZ;
        long long kbase=hoff + (long long)(it*128)*DMODEL;
        #pragma unroll
        for(int p=0;p<4;p++){
            int r=rr0+p*32;
            long long go=kbase+(long long)r*DMODEL+cc*8;
            uint32_t so=r*PITCH+cc*16;
            cpa(b+so, kh_+go);        cpa(b+18432+so, kl_+go);
            cpa(b+36864+so, vh_+go);
        }
        CPCOMMIT();
    };
    ldstage(0,0); ldstage(1,1);
    asm volatile("cp.async.wait_group 2;":::"memory");
    __syncthreads();

    uint32_t qaddr = su + (uint32_t)((wid*16 + (quad&1)*8 + lq)*PITCH + (quad>>1)*16);
    uint32_t qfh[4][4], qfl[4][4];
    #pragma unroll
    for(int ks=0;ks<4;ks++){ LDM4(qfh[ks], qaddr+ks*32); LDM4(qfl[ks], qaddr+QL+ks*32); }

    int r0l = wid*16 + (lane>>2);
    float g0 = gate[(long long)z*SSEQ + q0 + r0l];
    float g1 = gate[(long long)z*SSEQ + q0 + r0l + 8];
    float invT = 1.f/temp[0];
    float m0=-1e30f,m1=-1e30f,l0=0.f,l1=0.f;
    float oacc[8][4];
    #pragma unroll
    for(int d=0;d<8;d++){oacc[d][0]=0;oacc[d][1]=0;oacc[d][2]=0;oacc[d][3]=0;}

    for(int it=0; it<16; it++){
        if(it<15) asm volatile("cp.async.wait_group 1;":::"memory");
        else      asm volatile("cp.async.wait_group 0;":::"memory");
        __syncthreads();
        uint32_t sb = su+ST+(uint32_t)(it&1)*STSZ;

        // ---- S = Q K^T (3 products) ----
        float sacc[16][4];
        #pragma unroll
        for(int nt=0;nt<16;nt++){sacc[nt][0]=0;sacc[nt][1]=0;sacc[nt][2]=0;sacc[nt][3]=0;}
        uint32_t baddr = sb + (uint32_t)((lq + 8*(quad>>1))*PITCH + (quad&1)*16);
        #pragma unroll
        for(int ks=0;ks<4;ks++){
            uint32_t b[16][2];
            #pragma unroll
            for(int j=0;j<8;j++)
                LDM4B(b[2*j][0],b[2*j][1],b[2*j+1][0],b[2*j+1][1], baddr + j*(16*PITCH) + ks*32);
            #pragma unroll
            for(int nt=0;nt<16;nt++) MMA(sacc[nt], qfh[ks], b[nt]);
            #pragma unroll
            for(int nt=0;nt<16;nt++) MMA(sacc[nt], qfl[ks], b[nt]);
            #pragma unroll
            for(int j=0;j<8;j++)
                LDM4B(b[2*j][0],b[2*j][1],b[2*j+1][0],b[2*j+1][1], baddr + 18432 + j*(16*PITCH) + ks*32);
            #pragma unroll
            for(int nt=0;nt<16;nt++) MMA(sacc[nt], qfh[ks], b[nt]);
        }

        // ---- epilogue: /T, mask, *gate; row max ----
        long long mrow0 = (long long)(q0 + r0l)*SSEQ + it*128 + 2*(lane&3);
        long long mrow1 = mrow0 + 8LL*SSEQ;
        float rm0=-1e30f, rm1=-1e30f;
        #pragma unroll
        for(int nt=0;nt<16;nt++){
            int2 mA = *(const int2*)&mask[mrow0 + nt*8];
            int2 mB = *(const int2*)&mask[mrow1 + nt*8];
            float s0=sacc[nt][0]*invT, s1=sacc[nt][1]*invT;
            float s2=sacc[nt][2]*invT, s3=sacc[nt][3]*invT;
            if(mA.x==0)s0=-1e9f; if(mA.y==0)s1=-1e9f;
            if(mB.x==0)s2=-1e9f; if(mB.y==0)s3=-1e9f;
            s0*=g0;s1*=g0;s2*=g1;s3*=g1;
            sacc[nt][0]=s0;sacc[nt][1]=s1;sacc[nt][2]=s2;sacc[nt][3]=s3;
            rm0=fmaxf(rm0,fmaxf(s0,s1)); rm1=fmaxf(rm1,fmaxf(s2,s3));
        }
        rm0=fmaxf(rm0,__shfl_xor_sync(~0u,rm0,1)); rm0=fmaxf(rm0,__shfl_xor_sync(~0u,rm0,2));
        rm1=fmaxf(rm1,__shfl_xor_sync(~0u,rm1,1)); rm1=fmaxf(rm1,__shfl_xor_sync(~0u,rm1,2));
        float mn0=fmaxf(m0,rm0), mn1=fmaxf(m1,rm1);
        float sc0=__expf(m0-mn0), sc1=__expf(m1-mn1);
        m0=mn0; m1=mn1;

        // ---- P = exp(S - m); row sums ----
        float rs0=0.f, rs1=0.f;
        #pragma unroll
        for(int nt=0;nt<16;nt++){
            float p0=__expf(sacc[nt][0]-m0), p1=__expf(sacc[nt][1]-m0);
            float p2=__expf(sacc[nt][2]-m1), p3=__expf(sacc[nt][3]-m1);
            sacc[nt][0]=p0;sacc[nt][1]=p1;sacc[nt][2]=p2;sacc[nt][3]=p3;
            rs0+=p0+p1; rs1+=p2+p3;
        }
        rs0+=__shfl_xor_sync(~0u,rs0,1); rs0+=__shfl_xor_sync(~0u,rs0,2);
        rs1+=__shfl_xor_sync(~0u,rs1,1); rs1+=__shfl_xor_sync(~0u,rs1,2);
        l0 = l0*sc0 + rs0; l1 = l1*sc1 + rs1;
        #pragma unroll
        for(int d=0;d<8;d++){ oacc[d][0]*=sc0; oacc[d][1]*=sc0; oacc[d][2]*=sc1; oacc[d][3]*=sc1; }

        // ---- O += (Ph+Pl) Vh (2 products) ----
        #pragma unroll
        for(int kv=0;kv<8;kv++){
            uint32_t pa[4], pb[4];
            pack2(pa[0],pb[0], sacc[2*kv][0],   sacc[2*kv][1]);
            pack2(pa[1],pb[1], sacc[2*kv][2],   sacc[2*kv][3]);
            pack2(pa[2],pb[2], sacc[2*kv+1][0], sacc[2*kv+1][1]);
            pack2(pa[3],pb[3], sacc[2*kv+1][2], sacc[2*kv+1][3]);
            uint32_t vbase = sb + 36864 + (uint32_t)((16*kv + lq + 8*(quad&1))*PITCH + 16*(quad>>1));
            #pragma unroll
            for(int jp=0;jp<4;jp++){
                uint32_t vh4[4];
                LDM4T(vh4, vbase + jp*32);
                MMAB(oacc[2*jp],   pa, vh4[0], vh4[1]);
                MMAB(oacc[2*jp+1], pa, vh4[2], vh4[3]);
                MMAB(oacc[2*jp],   pb, vh4[0], vh4[1]);
                MMAB(oacc[2*jp+1], pb, vh4[2], vh4[3]);
            }
        }
        __syncthreads();
        if(it+2<16) ldstage(it+2, it&1);
    }

    // ---- normalize + split store ----
    float inv0=1.f/l0, inv1=1.f/l1;
    long long orow0 = (long long)zb*SD + (long long)(q0+r0l)*DMODEL + zh*64;
    long long orow1 = orow0 + 8LL*DMODEL;
    #pragma unroll
    for(int d=0;d<8;d++){
        int col = d*8 + 2*(lane&3);
        float v0=oacc[d][0]*inv0, v1=oacc[d][1]*inv0;
        float v2=oacc[d][2]*inv1, v3=oacc[d][3]*inv1;
        uint32_t h,l;
        pack2(h,l,v0,v1);
        *(uint32_t*)(ch+orow0+col)=h; *(uint32_t*)(cl+orow0+col)=l;
        pack2(h,l,v2,v3);
        *(uint32_t*)(ch+orow1+col)=h; *(uint32_t*)(cl+orow1+col)=l;
    }
}

// ---------------- support kernels ----------------
__global__ void split_vk(const float* __restrict__ in, hf* __restrict__ hi,
                         hf* __restrict__ lo, int n4){
    int i=blockIdx.x*blockDim.x+threadIdx.x; if(i>=n4)return;
    float4 v=((const float4*)in)[i];
    uint32_t h0,l0,h1,l1;
    pack2(h0,l0,v.x,v.y); pack2(h1,l1,v.z,v.w);
    ((uint32_t*)hi)[2*i]=h0; ((uint32_t*)hi)[2*i+1]=h1;
    ((uint32_t*)lo)[2*i]=l0; ((uint32_t*)lo)[2*i+1]=l1;
}
__global__ void split_T(const float* __restrict__ W, hf* __restrict__ hi,
                        hf* __restrict__ lo, int R, int C){
    __shared__ float t[32][33];
    int c0=blockIdx.x*32, r0=blockIdx.y*32, tx=threadIdx.x, ty=threadIdx.y;
    for(int i=ty;i<32;i+=8) t[i][tx]=W[(long long)(r0+i)*C+c0+tx];
    __syncthreads();
    for(int i=ty;i<32;i+=8){
        float v=t[tx][i]; long long ix=(long long)(c0+i)*R+r0+tx;
        hf h=__float2half_rn(v); hi[ix]=h; lo[ix]=__float2half_rn(v-__half2float(h));
    }
}
__global__ void gatek(const hf* __restrict__ qh,const hf* __restrict__ ql,
                      const float* __restrict__ gW,const float* __restrict__ gb,
                      float* __restrict__ gate){
    int warp=(blockIdx.x*blockDim.x+threadIdx.x)>>5, lane=threadIdx.x&31;
    if(warp>=ROWS*NHEADS)return;
    int bs=warp>>4,h=warp&15;
    long long base=(long long)bs*DMODEL+h*DKH;
    float q0=__half2float(qh[base+lane])+__half2float(ql[base+lane]);
    float q1=__half2float(qh[base+lane+32])+__half2float(ql[base+lane+32]);
    float s=q0*gW[lane]+q1*gW[lane+32];
    #pragma unroll
    for(int o=16;o;o>>=1)s+=__shfl_xor_sync(~0u,s,o);
    if(lane==0){int b=bs>>11,sr=bs&2047;
        gate[(long long)(b*NHEADS+h)*SSEQ+sr]=1.f/(1.f+expf(-(s+gb[0])));}
}
__device__ __forceinline__ float wSum(float v){
    #pragma unroll
    for(int o=16;o;o>>=1)v+=__shfl_xor_sync(~0u,v,o); return v;}

__global__ void __launch_bounds__(256) layernorm_k(const float* __restrict__ a,
    const float* __restrict__ resid, const float* __restrict__ g, const float* __restrict__ b,
    float* __restrict__ outf, hf* __restrict__ oh, hf* __restrict__ ol){
    long long row=blockIdx.x;
    const float* pa=a+row*DMODEL;
    const float* pr=resid?resid+row*DMODEL:nullptr;
    int t=threadIdx.x,lane=t&31,wid=t>>5;
    __shared__ float s1[8],s2a[8]; __shared__ float bm,brs;
    float v[4],s=0.f,s2=0.f;
    #pragma unroll
    for(int i=0;i<4;i++){int d=t+i*256;float x=pa[d]+(pr?pr[d]:0.f);v[i]=x;s+=x;s2+=x*x;}
    s=wSum(s);s2=wSum(s2);
    if(lane==0){s1[wid]=s;s2a[wid]=s2;} __syncthreads();
    if(wid==0){float xs=(lane<8)?s1[lane]:0.f,x2=(lane<8)?s2a[lane]:0.f;
        xs=wSum(xs);x2=wSum(x2);
        if(lane==0){float mean=xs*(1.f/DMODEL);float var=fmaxf(x2*(1.f/DMODEL)-mean*mean,0.f);
            bm=mean;brs=rsqrtf(var+1e-5f);}}
    __syncthreads();
    float mean=bm,rstd=brs;
    #pragma unroll
    for(int i=0;i<4;i++){int d=t+i*256;float y=(v[i]-mean)*rstd*g[d]+b[d];
        if(outf)outf[row*DMODEL+d]=y;
        if(oh){hf h=__float2half_rn(y);oh[row*DMODEL+d]=h;
               ol[row*DMODEL+d]=__float2half_rn(y-__half2float(h));}}
}

// fused: attn = LN(t0)*lag+lab ; x1 = LN(x + attn)*n1g+n1b -> x1 fp32 + split
__global__ void __launch_bounds__(256) layernorm2_k(const float* __restrict__ t0,
    const float* __restrict__ x,
    const float* __restrict__ lag, const float* __restrict__ lab,
    const float* __restrict__ n1g, const float* __restrict__ n1b,
    float* __restrict__ x1, hf* __restrict__ oh, hf* __restrict__ ol){
    long long row=blockIdx.x;
    const float* pa=t0+row*DMODEL;
    const float* px=x+row*DMODEL;
    int t=threadIdx.x,lane=t&31,wid=t>>5;
    __shared__ float s1[8],s2a[8]; __shared__ float bm,brs;
    float v[4],s=0.f,s2=0.f;
    #pragma unroll
    for(int i=0;i<4;i++){int d=t+i*256;float xx=pa[d];v[i]=xx;s+=xx;s2+=xx*xx;}
    s=wSum(s);s2=wSum(s2);
    if(lane==0){s1[wid]=s;s2a[wid]=s2;} __syncthreads();
    if(wid==0){float xs=(lane<8)?s1[lane]:0.f,x2=(lane<8)?s2a[lane]:0.f;
        xs=wSum(xs);x2=wSum(x2);
        if(lane==0){float mean=xs*(1.f/DMODEL);float var=fmaxf(x2*(1.f/DMODEL)-mean*mean,0.f);
            bm=mean;brs=rsqrtf(var+1e-5f);}}
    __syncthreads();
    float mean=bm,rstd=brs;
    s=0.f; s2=0.f;
    #pragma unroll
    for(int i=0;i<4;i++){int d=t+i*256;
        float y=(v[i]-mean)*rstd*lag[d]+lab[d] + px[d];
        v[i]=y; s+=y; s2+=y*y;}
    __syncthreads();
    s=wSum(s);s2=wSum(s2);
    if(lane==0){s1[wid]=s;s2a[wid]=s2;} __syncthreads();
    if(wid==0){float xs=(lane<8)?s1[lane]:0.f,x2=(lane<8)?s2a[lane]:0.f;
        xs=wSum(xs);x2=wSum(x2);
        if(lane==0){float mean2=xs*(1.f/DMODEL);float var=fmaxf(x2*(1.f/DMODEL)-mean2*mean2,0.f);
            bm=mean2;brs=rsqrtf(var+1e-5f);}}
    __syncthreads();
    mean=bm; rstd=brs;
    #pragma unroll
    for(int i=0;i<4;i++){int d=t+i*256;
        float y=(v[i]-mean)*rstd*n1g[d]+n1b[d];
        x1[row*DMODEL+d]=y;
        hf h=__float2half_rn(y);
        oh[row*DMODEL+d]=h;
        ol[row*DMODEL+d]=__float2half_rn(y-__half2float(h));}
}

// ---------------- launch ----------------
extern "C" void kernel_launch(void* const* d_in, const int* in_sizes, int n_in,
                              void* d_out, int out_size)
{
    const float* x   =(const float*)d_in[0];
    const int*  mask =(const int*)  d_in[1];
    const float* Wq=(const float*)d_in[2],  *bq=(const float*)d_in[3];
    const float* Wk=(const float*)d_in[4],  *bk=(const float*)d_in[5];
    const float* Wv=(const float*)d_in[6],  *bv=(const float*)d_in[7];
    const float* Wo=(const float*)d_in[8],  *bo=(const float*)d_in[9];
    const float* temp=(const float*)d_in[10], *tw=(const float*)d_in[11];
    const float* gW=(const float*)d_in[12], *gb=(const float*)d_in[13];
    const float* lag=(const float*)d_in[14],*lab=(const float*)d_in[15];
    const float* f1W=(const float*)d_in[16],*f1b=(const float*)d_in[17];
    const float* f2W=(const float*)d_in[18],*f2b=(const float*)d_in[19];
    const float* n1g=(const float*)d_in[20],*n1b=(const float*)d_in[21];
    const float* n2g=(const float*)d_in[22],*n2b=(const float*)d_in[23];
    float* out=(float*)d_out;

    float *t0,*x1,*gatep;
    hf *xh,*xl,*qh,*ql,*kh,*kl,*vh,*ch,*cl,*yh,*yl,*fh,*fl;
    hf *wqh,*wql,*wkh,*wkl,*wvh,*wvl,*woh,*wol,*w1h,*w1l,*w2h,*w2l;
    cudaGetSymbolAddress((void**)&t0,g_t0);   cudaGetSymbolAddress((void**)&x1,g_x1);
    cudaGetSymbolAddress((void**)&gatep,g_gate);
    cudaGetSymbolAddress((void**)&xh,g_xh); cudaGetSymbolAddress((void**)&xl,g_xl);
    cudaGetSymbolAddress((void**)&qh,g_qh); cudaGetSymbolAddress((void**)&ql,g_ql);
    cudaGetSymbolAddress((void**)&kh,g_kh); cudaGetSymbolAddress((void**)&kl,g_kl);
    cudaGetSymbolAddress((void**)&vh,g_vh);
    cudaGetSymbolAddress((void**)&ch,g_ch); cudaGetSymbolAddress((void**)&cl,g_cl);
    cudaGetSymbolAddress((void**)&yh,g_yh); cudaGetSymbolAddress((void**)&yl,g_yl);
    cudaGetSymbolAddress((void**)&fh,g_fh); cudaGetSymbolAddress((void**)&fl,g_fl);
    cudaGetSymbolAddress((void**)&wqh,g_wqh);cudaGetSymbolAddress((void**)&wql,g_wql);
    cudaGetSymbolAddress((void**)&wkh,g_wkh);cudaGetSymbolAddress((void**)&wkl,g_wkl);
    cudaGetSymbolAddress((void**)&wvh,g_wvh);cudaGetSymbolAddress((void**)&wvl,g_wvl);
    cudaGetSymbolAddress((void**)&woh,g_woh);cudaGetSymbolAddress((void**)&wol,g_wol);
    cudaGetSymbolAddress((void**)&w1h,g_w1h);cudaGetSymbolAddress((void**)&w1l,g_w1l);
    cudaGetSymbolAddress((void**)&w2h,g_w2h);cudaGetSymbolAddress((void**)&w2l,g_w2l);

    const int SMG = 2*4*10240;                 // 81920
    const int SMF = 36864 + 2*55296;           // 147456
    cudaFuncSetAttribute((const void*)hgemm,    cudaFuncAttributeMaxDynamicSharedMemorySize,SMG);
    cudaFuncSetAttribute((const void*)flashattn,cudaFuncAttributeMaxDynamicSharedMemorySize,SMF);

    // conversions
    split_vk<<<ROWS*DMODEL/4/256,256>>>(x,xh,xl,ROWS*DMODEL/4);
    dim3 tb(32,8);
    split_T<<<dim3(DMODEL/32,DMODEL/32),tb>>>(Wq,wqh,wql,DMODEL,DMODEL);
    split_T<<<dim3(DMODEL/32,DMODEL/32),tb>>>(Wk,wkh,wkl,DMODEL,DMODEL);
    split_T<<<dim3(DMODEL/32,DMODEL/32),tb>>>(Wv,wvh,wvl,DMODEL,DMODEL);
    split_T<<<dim3(DMODEL/32,DMODEL/32),tb>>>(Wo,woh,wol,DMODEL,DMODEL);
    split_T<<<dim3(DFF/32,DMODEL/32),tb>>>(f1W,w1h,w1l,DMODEL,DFF);
    split_T<<<dim3(DMODEL/32,DFF/32),tb>>>(f2W,w2h,w2l,DFF,DMODEL);

    // projections (Q bias2 = time_weights flattened [H*dk]); 3-product
    dim3 gP(DMODEL/128,ROWS/128,1);
    hgemm<<<gP,256,SMG>>>(xh,xl,wqh,wql,DMODEL,DMODEL,DMODEL,DMODEL,
        nullptr,qh,ql,bq,tw,0,1);
    hgemm<<<gP,256,SMG>>>(xh,xl,wkh,wkl,DMODEL,DMODEL,DMODEL,DMODEL,
        nullptr,kh,kl,bk,nullptr,0,1);
    hgemm<<<gP,256,SMG>>>(xh,xl,wvh,wvl,DMODEL,DMODEL,DMODEL,DMODEL,
        nullptr,vh,nullptr,bv,nullptr,0,3);

    gatek<<<(ROWS*NHEADS)/8,256>>>(qh,ql,gW,gb,gatep);

    // fused attention -> ctx split
    dim3 gA(SSEQ/128, ZTOT, 1);
    flashattn<<<gA,256,SMF>>>(qh,ql,kh,kl,vh,mask,gatep,temp,ch,cl);

    // Wo projection (3-product) + fused double-LN
    hgemm<<<gP,256,SMG>>>(ch,cl,woh,wol,DMODEL,DMODEL,DMODEL,DMODEL,
        t0,nullptr,nullptr,bo,nullptr,0,0);
    layernorm2_k<<<ROWS,256>>>(t0,x,lag,lab,n1g,n1b,x1,yh,yl);

    // FFN: 2-product (weights hi-only)
    dim3 gF(DFF/128,ROWS/128,1);
    hgemm<<<gF,256,SMG>>>(yh,yl,w1h,nullptr,DMODEL,DMODEL,DMODEL,DFF,
        nullptr,fh,fl,f1b,nullptr,1,1);
    hgemm<<<gP,256,SMG>>>(fh,fl,w2h,nullptr,DFF,DFF,DFF,DMODEL,
        t0,nullptr,nullptr,f2b,nullptr,0,0);

    layernorm_k<<<ROWS,256>>>(x1,t0,n2g,n2b,out,nullptr,nullptr);
}

// round 8
// speedup vs baseline: 6.3141x; 1.0856x over previous
#include <cuda_runtime.h>
#include <cuda_fp16.h>
#include <math.h>
#include <stdint.h>

#define SSEQ 2048
#define DMODEL 1024
#define NHEADS 16
#define DKH 64
#define DFF 4096
#define ROWS 4096
#define ZTOT 32
#define SD ((long long)SSEQ*DMODEL)
typedef __half hf;

// ---------------- scratch ----------------
__device__ __align__(256) float g_t0[ROWS*DMODEL];
__device__ __align__(256) float g_x1[ROWS*DMODEL];
__device__ __align__(256) float g_gate[ZTOT*SSEQ];
__device__ __align__(256) hf g_xh[ROWS*DMODEL], g_xl[ROWS*DMODEL];
__device__ __align__(256) hf g_qh[ROWS*DMODEL], g_ql[ROWS*DMODEL];
__device__ __align__(256) hf g_kh[ROWS*DMODEL], g_kl[ROWS*DMODEL];
__device__ __align__(256) hf g_vh[ROWS*DMODEL];
__device__ __align__(256) hf g_ch[ROWS*DMODEL], g_cl[ROWS*DMODEL];
__device__ __align__(256) hf g_yh[ROWS*DMODEL], g_yl[ROWS*DMODEL];
__device__ __align__(256) hf g_fh[ROWS*DFF], g_fl[ROWS*DFF];
__device__ __align__(256) hf g_wqh[DMODEL*DMODEL];
__device__ __align__(256) hf g_wkh[DMODEL*DMODEL];
__device__ __align__(256) hf g_wvh[DMODEL*DMODEL];
__device__ __align__(256) hf g_woh[DMODEL*DMODEL];
__device__ __align__(256) hf g_w1h[DMODEL*DFF];
__device__ __align__(256) hf g_w2h[DMODEL*DFF];

// ---------------- helpers ----------------
__device__ __forceinline__ uint32_t su32(const void* p){uint32_t a;
    asm("{.reg .u64 t; cvta.to.shared.u64 t,%1; cvt.u32.u64 %0,t;}":"=r"(a):"l"(p));return a;}
__device__ __forceinline__ void cpa(uint32_t d,const void*s){
    asm volatile("cp.async.cg.shared.global [%0],[%1],16;"::"r"(d),"l"(s));}
#define CPCOMMIT() asm volatile("cp.async.commit_group;":::"memory")
#define LDM4(f,a) asm volatile("ldmatrix.sync.aligned.m8n8.x4.shared.b16 {%0,%1,%2,%3},[%4];" \
    :"=r"((f)[0]),"=r"((f)[1]),"=r"((f)[2]),"=r"((f)[3]):"r"(a))
#define LDM4B(b0,b1,b2,b3,a) asm volatile("ldmatrix.sync.aligned.m8n8.x4.shared.b16 {%0,%1,%2,%3},[%4];" \
    :"=r"(b0),"=r"(b1),"=r"(b2),"=r"(b3):"r"(a))
#define LDM4T(f,a) asm volatile("ldmatrix.sync.aligned.m8n8.x4.trans.shared.b16 {%0,%1,%2,%3},[%4];" \
    :"=r"((f)[0]),"=r"((f)[1]),"=r"((f)[2]),"=r"((f)[3]):"r"(a))
#define MMA(c,A,B) asm volatile( \
    "mma.sync.aligned.m16n8k16.row.col.f32.f16.f16.f32 {%0,%1,%2,%3},{%4,%5,%6,%7},{%8,%9},{%0,%1,%2,%3};" \
    :"+f"((c)[0]),"+f"((c)[1]),"+f"((c)[2]),"+f"((c)[3]) \
    :"r"((A)[0]),"r"((A)[1]),"r"((A)[2]),"r"((A)[3]),"r"((B)[0]),"r"((B)[1]))
#define MMAB(c,A,b0,b1) asm volatile( \
    "mma.sync.aligned.m16n8k16.row.col.f32.f16.f16.f32 {%0,%1,%2,%3},{%4,%5,%6,%7},{%8,%9},{%0,%1,%2,%3};" \
    :"+f"((c)[0]),"+f"((c)[1]),"+f"((c)[2]),"+f"((c)[3]) \
    :"r"((A)[0]),"r"((A)[1]),"r"((A)[2]),"r"((A)[3]),"r"(b0),"r"(b1))

__device__ __forceinline__ void pack2(uint32_t&h, uint32_t&l, float a, float b){
    hf ha=__float2half_rn(a), hb=__float2half_rn(b);
    __half2 hp; hp.x=ha; hp.y=hb;
    __half2 lp=__floats2half2_rn(a-__half2float(ha), b-__half2float(hb));
    h=*(uint32_t*)&hp; l=*(uint32_t*)&lp;
}
__device__ __forceinline__ uint32_t pack2h(float a, float b){
    __half2 hp=__floats2half2_rn(a,b);
    return *(uint32_t*)&hp;
}

// ---------------- fp16-split HMMA GEMM ----------------
// C = (Ah+Al)[M,K] @ (Bh[+Bl])[N,K]^T. 128x128 tile, BK=32, 2 stages.
// Bl!=null: 3 products. Bl==null: 2 products (hh + lh).
// epi: 0 bias(+bias2), 1 bias+GELU ; outm: 0 fp32, 1 split, 3 hi-only
__global__ __launch_bounds__(256,2) void hgemm(
    const hf* __restrict__ Ah_, const hf* __restrict__ Al_,
    const hf* __restrict__ Bh_, const hf* __restrict__ Bl_,
    int K, int lda, int ldb, int ldc,
    float* __restrict__ Cf, hf* __restrict__ Ch, hf* __restrict__ Cl,
    const float* __restrict__ bias, const float* __restrict__ bias2,
    int epi, int outm)
{
    constexpr int STG = 4*10240;
    extern __shared__ char smraw[];
    uint32_t su = su32(smraw);
    int tid = threadIdx.x, wid = tid>>5, lane = tid&31;
    int wm = wid%2, wn = wid/2;
    int m0 = blockIdx.y*128, n0 = blockIdx.x*128;

    const hf* pAh = Ah_ + (long long)m0*lda;
    const hf* pAl = Al_ + (long long)m0*lda;
    const hf* pBh = Bh_ + (long long)n0*ldb;
    const hf* pBl = Bl_ ? Bl_ + (long long)n0*ldb : nullptr;
    int nk = K>>5;

    int r = tid>>2, sg = tid&3;
    auto loadstage = [&](int ci, int st){
        uint32_t b = su + (uint32_t)st*STG;
        int k0 = ci<<5;
        #pragma unroll
        for(int p=0;p<2;p++){
            int rr = r + p*64;
            uint32_t so = b + rr*80 + sg*16;
            cpa(so,       pAh + (long long)rr*lda + k0 + sg*8);
            cpa(so+10240, pAl + (long long)rr*lda + k0 + sg*8);
            uint32_t so2 = b + 20480 + rr*80 + sg*16;
            cpa(so2,      pBh + (long long)rr*ldb + k0 + sg*8);
            if(pBl) cpa(so2+10240, pBl + (long long)rr*ldb + k0 + sg*8);
        }
        CPCOMMIT();
    };

    float acc[4][4][4];
    #pragma unroll
    for(int a=0;a<4;a++)
        #pragma unroll
        for(int b=0;b<4;b++)
            #pragma unroll
            for(int c=0;c<4;c++) acc[a][b][c]=0.f;

    int quad = lane>>3, lq = lane&7;
    uint32_t aoff = (uint32_t)((wm*64 + (quad&1)*8 + lq)*80 + (quad>>1)*16);
    uint32_t boff = (uint32_t)(20480 + (wn*32 + (quad>>1)*8 + lq)*80 + (quad&1)*16);

    loadstage(0,0);
    if(nk>1) loadstage(1,1);

    for(int i=0;i<nk;i++){
        if(i+1<nk) asm volatile("cp.async.wait_group 1;":::"memory");
        else       asm volatile("cp.async.wait_group 0;":::"memory");
        __syncthreads();
        uint32_t sb = su + (uint32_t)(i&1)*STG;
        uint32_t pa_h = sb + aoff, pa_l = pa_h + 10240;
        uint32_t pb_h = sb + boff, pb_l = pb_h + 10240;
        uint32_t Af[4][4], Bf[4][2], Bt[4][2];
        #pragma unroll
        for(int ks=0;ks<2;ks++){
            uint32_t kso = ks*32;
            #pragma unroll
            for(int mt=0;mt<4;mt++) LDM4(Af[mt], pa_h + mt*1280 + kso);
            #pragma unroll
            for(int np=0;np<2;np++)
                LDM4B(Bf[2*np][0],Bf[2*np][1],Bf[2*np+1][0],Bf[2*np+1][1], pb_h + np*1280 + kso);
            #pragma unroll
            for(int mt=0;mt<4;mt++)
                #pragma unroll
                for(int nt=0;nt<4;nt++) MMA(acc[mt][nt],Af[mt],Bf[nt]);
            if(Bl_){
                #pragma unroll
                for(int np=0;np<2;np++)
                    LDM4B(Bt[2*np][0],Bt[2*np][1],Bt[2*np+1][0],Bt[2*np+1][1], pb_l + np*1280 + kso);
                #pragma unroll
                for(int mt=0;mt<4;mt++)
                    #pragma unroll
                    for(int nt=0;nt<4;nt++) MMA(acc[mt][nt],Af[mt],Bt[nt]);
            }
            #pragma unroll
            for(int mt=0;mt<4;mt++) LDM4(Af[mt], pa_l + mt*1280 + kso);
            #pragma unroll
            for(int mt=0;mt<4;mt++)
                #pragma unroll
                for(int nt=0;nt<4;nt++) MMA(acc[mt][nt],Af[mt],Bf[nt]);
        }
        __syncthreads();
        if(i+2<nk) loadstage(i+2, i&1);
    }

    auto store2 = [&](int row,int col,float v0,float v1){
        if(bias){ v0+=bias[col]; v1+=bias[col+1]; }
        if(bias2){ v0+=bias2[col]; v1+=bias2[col+1]; }
        if(epi==1){
            v0 = 0.5f*v0*(1.0f+erff(v0*0.70710678118654752f));
            v1 = 0.5f*v1*(1.0f+erff(v1*0.70710678118654752f));
        }
        if(outm==0){
            *(float2*)&Cf[(long long)row*ldc+col] = make_float2(v0,v1);
        } else if(outm==1){
            long long ix = (long long)row*ldc+col;
            uint32_t h,l; pack2(h,l,v0,v1);
            *(uint32_t*)(Ch+ix)=h; *(uint32_t*)(Cl+ix)=l;
        } else {
            long long ix = (long long)row*ldc+col;
            *(uint32_t*)(Ch+ix) = pack2h(v0,v1);
        }
    };
    #pragma unroll
    for(int mt=0;mt<4;mt++){
        #pragma unroll
        for(int nt=0;nt<4;nt++){
            int row0 = m0 + wm*64 + mt*16 + (lane>>2);
            int col  = n0 + wn*32 + nt*8 + ((lane&3)<<1);
            store2(row0,   col, acc[mt][nt][0], acc[mt][nt][1]);
            store2(row0+8, col, acc[mt][nt][2], acc[mt][nt][3]);
        }
    }
}

// ---------------- flash attention ----------------
// S = (Qh+Ql)(Kh+Kl)^T (3 products); /T, mask, *gate; online softmax;
// O += (Ph+Pl)·Vh (2 products).
#define PITCH 144
__global__ __launch_bounds__(256,1) void flashattn(
    const hf* __restrict__ qh_, const hf* __restrict__ ql_,
    const hf* __restrict__ kh_, const hf* __restrict__ kl_,
    const hf* __restrict__ vh_,
    const int* __restrict__ mask, const float* __restrict__ gate,
    const float* __restrict__ temp,
    hf* __restrict__ ch, hf* __restrict__ cl)
{
    extern __shared__ char sm[];
    uint32_t su = su32(sm);
    const uint32_t QL=18432, ST=36864, STSZ=55296;
    int tid=threadIdx.x, wid=tid>>5, lane=tid&31;
    int quad=lane>>3, lq=lane&7;
    int z=blockIdx.y, zb=z>>4, zh=z&15;
    int q0=blockIdx.x*128;
    long long hoff=(long long)zb*SD + zh*64;
    const hf* pq_h = qh_ + hoff + (long long)q0*DMODEL;
    const hf* pq_l = ql_ + hoff + (long long)q0*DMODEL;

    int cc=tid&7, rr0=tid>>3;
    #pragma unroll
    for(int p=0;p<4;p++){
        int r=rr0+p*32;
        long long go=(long long)r*DMODEL + cc*8;
        uint32_t so=r*PITCH + cc*16;
        cpa(su+so, pq_h+go); cpa(su+QL+so, pq_l+go);
    }
    CPCOMMIT();

    auto ldstage=[&](int it,int st){
        uint32_t b=su+ST+(uint32_t)st*STSZ;
        long long kbase=hoff + (long long)(it*128)*DMODEL;
        #pragma unroll
        for(int p=0;p<4;p++){
            int r=rr0+p*32;
            long long go=kbase+(long long)r*DMODEL+cc*8;
            uint32_t so=r*PITCH+cc*16;
            cpa(b+so, kh_+go);        cpa(b+18432+so, kl_+go);
            cpa(b+36864+so, vh_+go);
        }
        CPCOMMIT();
    };
    ldstage(0,0); ldstage(1,1);
    asm volatile("cp.async.wait_group 2;":::"memory");
    __syncthreads();

    uint32_t qaddr = su + (uint32_t)((wid*16 + (quad&1)*8 + lq)*PITCH + (quad>>1)*16);
    uint32_t qfh[4][4], qfl[4][4];
    #pragma unroll
    for(int ks=0;ks<4;ks++){ LDM4(qfh[ks], qaddr+ks*32); LDM4(qfl[ks], qaddr+QL+ks*32); }

    int r0l = wid*16 + (lane>>2);
    float g0 = gate[(long long)z*SSEQ + q0 + r0l];
    float g1 = gate[(long long)z*SSEQ + q0 + r0l + 8];
    float invT = 1.f/temp[0];
    float m0=-1e30f,m1=-1e30f,l0=0.f,l1=0.f;
    float oacc[8][4];
    #pragma unroll
    for(int d=0;d<8;d++){oacc[d][0]=0;oacc[d][1]=0;oacc[d][2]=0;oacc[d][3]=0;}

    for(int it=0; it<16; it++){
        if(it<15) asm volatile("cp.async.wait_group 1;":::"memory");
        else      asm volatile("cp.async.wait_group 0;":::"memory");
        __syncthreads();
        uint32_t sb = su+ST+(uint32_t)(it&1)*STSZ;

        float sacc[16][4];
        #pragma unroll
        for(int nt=0;nt<16;nt++){sacc[nt][0]=0;sacc[nt][1]=0;sacc[nt][2]=0;sacc[nt][3]=0;}
        uint32_t baddr = sb + (uint32_t)((lq + 8*(quad>>1))*PITCH + (quad&1)*16);
        #pragma unroll
        for(int ks=0;ks<4;ks++){
            uint32_t b[16][2];
            #pragma unroll
            for(int j=0;j<8;j++)
                LDM4B(b[2*j][0],b[2*j][1],b[2*j+1][0],b[2*j+1][1], baddr + j*(16*PITCH) + ks*32);
            #pragma unroll
            for(int nt=0;nt<16;nt++) MMA(sacc[nt], qfh[ks], b[nt]);
            #pragma unroll
            for(int nt=0;nt<16;nt++) MMA(sacc[nt], qfl[ks], b[nt]);
            #pragma unroll
            for(int j=0;j<8;j++)
                LDM4B(b[2*j][0],b[2*j][1],b[2*j+1][0],b[2*j+1][1], baddr + 18432 + j*(16*PITCH) + ks*32);
            #pragma unroll
            for(int nt=0;nt<16;nt++) MMA(sacc[nt], qfh[ks], b[nt]);
        }

        long long mrow0 = (long long)(q0 + r0l)*SSEQ + it*128 + 2*(lane&3);
        long long mrow1 = mrow0 + 8LL*SSEQ;
        float rm0=-1e30f, rm1=-1e30f;
        #pragma unroll
        for(int nt=0;nt<16;nt++){
            int2 mA = *(const int2*)&mask[mrow0 + nt*8];
            int2 mB = *(const int2*)&mask[mrow1 + nt*8];
            float s0=sacc[nt][0]*invT, s1=sacc[nt][1]*invT;
            float s2=sacc[nt][2]*invT, s3=sacc[nt][3]*invT;
            if(mA.x==0)s0=-1e9f; if(mA.y==0)s1=-1e9f;
            if(mB.x==0)s2=-1e9f; if(mB.y==0)s3=-1e9f;
            s0*=g0;s1*=g0;s2*=g1;s3*=g1;
            sacc[nt][0]=s0;sacc[nt][1]=s1;sacc[nt][2]=s2;sacc[nt][3]=s3;
            rm0=fmaxf(rm0,fmaxf(s0,s1)); rm1=fmaxf(rm1,fmaxf(s2,s3));
        }
        rm0=fmaxf(rm0,__shfl_xor_sync(~0u,rm0,1)); rm0=fmaxf(rm0,__shfl_xor_sync(~0u,rm0,2));
        rm1=fmaxf(rm1,__shfl_xor_sync(~0u,rm1,1)); rm1=fmaxf(rm1,__shfl_xor_sync(~0u,rm1,2));
        float mn0=fmaxf(m0,rm0), mn1=fmaxf(m1,rm1);
        float sc0=__expf(m0-mn0), sc1=__expf(m1-mn1);
        m0=mn0; m1=mn1;

        float rs0=0.f, rs1=0.f;
        #pragma unroll
        for(int nt=0;nt<16;nt++){
            float p0=__expf(sacc[nt][0]-m0), p1=__expf(sacc[nt][1]-m0);
            float p2=__expf(sacc[nt][2]-m1), p3=__expf(sacc[nt][3]-m1);
            sacc[nt][0]=p0;sacc[nt][1]=p1;sacc[nt][2]=p2;sacc[nt][3]=p3;
            rs0+=p0+p1; rs1+=p2+p3;
        }
        rs0+=__shfl_xor_sync(~0u,rs0,1); rs0+=__shfl_xor_sync(~0u,rs0,2);
        rs1+=__shfl_xor_sync(~0u,rs1,1); rs1+=__shfl_xor_sync(~0u,rs1,2);
        l0 = l0*sc0 + rs0; l1 = l1*sc1 + rs1;
        #pragma unroll
        for(int d=0;d<8;d++){ oacc[d][0]*=sc0; oacc[d][1]*=sc0; oacc[d][2]*=sc1; oacc[d][3]*=sc1; }

        #pragma unroll
        for(int kv=0;kv<8;kv++){
            uint32_t pa[4], pb[4];
            pack2(pa[0],pb[0], sacc[2*kv][0],   sacc[2*kv][1]);
            pack2(pa[1],pb[1], sacc[2*kv][2],   sacc[2*kv][3]);
            pack2(pa[2],pb[2], sacc[2*kv+1][0], sacc[2*kv+1][1]);
            pack2(pa[3],pb[3], sacc[2*kv+1][2], sacc[2*kv+1][3]);
            uint32_t vbase = sb + 36864 + (uint32_t)((16*kv + lq + 8*(quad&1))*PITCH + 16*(quad>>1));
            #pragma unroll
            for(int jp=0;jp<4;jp++){
                uint32_t vh4[4];
                LDM4T(vh4, vbase + jp*32);
                MMAB(oacc[2*jp],   pa, vh4[0], vh4[1]);
                MMAB(oacc[2*jp+1], pa, vh4[2], vh4[3]);
                MMAB(oacc[2*jp],   pb, vh4[0], vh4[1]);
                MMAB(oacc[2*jp+1], pb, vh4[2], vh4[3]);
            }
        }
        __syncthreads();
        if(it+2<16) ldstage(it+2, it&1);
    }

    float inv0=1.f/l0, inv1=1.f/l1;
    long long orow0 = (long long)zb*SD + (long long)(q0+r0l)*DMODEL + zh*64;
    long long orow1 = orow0 + 8LL*DMODEL;
    #pragma unroll
    for(int d=0;d<8;d++){
        int col = d*8 + 2*(lane&3);
        float v0=oacc[d][0]*inv0, v1=oacc[d][1]*inv0;
        float v2=oacc[d][2]*inv1, v3=oacc[d][3]*inv1;
        uint32_t h,l;
        pack2(h,l,v0,v1);
        *(uint32_t*)(ch+orow0+col)=h; *(uint32_t*)(cl+orow0+col)=l;
        pack2(h,l,v2,v3);
        *(uint32_t*)(ch+orow1+col)=h; *(uint32_t*)(cl+orow1+col)=l;
    }
}

// ---------------- support kernels ----------------
__global__ void split_vk(const float* __restrict__ in, hf* __restrict__ hi,
                         hf* __restrict__ lo, int n4){
    int i=blockIdx.x*blockDim.x+threadIdx.x; if(i>=n4)return;
    float4 v=((const float4*)in)[i];
    uint32_t h0,l0,h1,l1;
    pack2(h0,l0,v.x,v.y); pack2(h1,l1,v.z,v.w);
    ((uint32_t*)hi)[2*i]=h0; ((uint32_t*)hi)[2*i+1]=h1;
    ((uint32_t*)lo)[2*i]=l0; ((uint32_t*)lo)[2*i+1]=l1;
}
// transpose + fp16 convert; lo optional
__global__ void split_T(const float* __restrict__ W, hf* __restrict__ hi,
                        hf* __restrict__ lo, int R, int C){
    __shared__ float t[32][33];
    int c0=blockIdx.x*32, r0=blockIdx.y*32, tx=threadIdx.x, ty=threadIdx.y;
    for(int i=ty;i<32;i+=8) t[i][tx]=W[(long long)(r0+i)*C+c0+tx];
    __syncthreads();
    for(int i=ty;i<32;i+=8){
        float v=t[tx][i]; long long ix=(long long)(c0+i)*R+r0+tx;
        hf h=__float2half_rn(v); hi[ix]=h;
        if(lo) lo[ix]=__float2half_rn(v-__half2float(h));
    }
}
__global__ void gatek(const hf* __restrict__ qh,const hf* __restrict__ ql,
                      const float* __restrict__ gW,const float* __restrict__ gb,
                      float* __restrict__ gate){
    int warp=(blockIdx.x*blockDim.x+threadIdx.x)>>5, lane=threadIdx.x&31;
    if(warp>=ROWS*NHEADS)return;
    int bs=warp>>4,h=warp&15;
    long long base=(long long)bs*DMODEL+h*DKH;
    float q0=__half2float(qh[base+lane])+__half2float(ql[base+lane]);
    float q1=__half2float(qh[base+lane+32])+__half2float(ql[base+lane+32]);
    float s=q0*gW[lane]+q1*gW[lane+32];
    #pragma unroll
    for(int o=16;o;o>>=1)s+=__shfl_xor_sync(~0u,s,o);
    if(lane==0){int b=bs>>11,sr=bs&2047;
        gate[(long long)(b*NHEADS+h)*SSEQ+sr]=1.f/(1.f+expf(-(s+gb[0])));}
}
__device__ __forceinline__ float wSum(float v){
    #pragma unroll
    for(int o=16;o;o>>=1)v+=__shfl_xor_sync(~0u,v,o); return v;}

__global__ void __launch_bounds__(256) layernorm_k(const float* __restrict__ a,
    const float* __restrict__ resid, const float* __restrict__ g, const float* __restrict__ b,
    float* __restrict__ outf, hf* __restrict__ oh, hf* __restrict__ ol){
    long long row=blockIdx.x;
    const float* pa=a+row*DMODEL;
    const float* pr=resid?resid+row*DMODEL:nullptr;
    int t=threadIdx.x,lane=t&31,wid=t>>5;
    __shared__ float s1[8],s2a[8]; __shared__ float bm,brs;
    float v[4],s=0.f,s2=0.f;
    #pragma unroll
    for(int i=0;i<4;i++){int d=t+i*256;float x=pa[d]+(pr?pr[d]:0.f);v[i]=x;s+=x;s2+=x*x;}
    s=wSum(s);s2=wSum(s2);
    if(lane==0){s1[wid]=s;s2a[wid]=s2;} __syncthreads();
    if(wid==0){float xs=(lane<8)?s1[lane]:0.f,x2=(lane<8)?s2a[lane]:0.f;
        xs=wSum(xs);x2=wSum(x2);
        if(lane==0){float mean=xs*(1.f/DMODEL);float var=fmaxf(x2*(1.f/DMODEL)-mean*mean,0.f);
            bm=mean;brs=rsqrtf(var+1e-5f);}}
    __syncthreads();
    float mean=bm,rstd=brs;
    #pragma unroll
    for(int i=0;i<4;i++){int d=t+i*256;float y=(v[i]-mean)*rstd*g[d]+b[d];
        if(outf)outf[row*DMODEL+d]=y;
        if(oh){hf h=__float2half_rn(y);oh[row*DMODEL+d]=h;
               ol[row*DMODEL+d]=__float2half_rn(y-__half2float(h));}}
}

__global__ void __launch_bounds__(256) layernorm2_k(const float* __restrict__ t0,
    const float* __restrict__ x,
    const float* __restrict__ lag, const float* __restrict__ lab,
    const float* __restrict__ n1g, const float* __restrict__ n1b,
    float* __restrict__ x1, hf* __restrict__ oh, hf* __restrict__ ol){
    long long row=blockIdx.x;
    const float* pa=t0+row*DMODEL;
    const float* px=x+row*DMODEL;
    int t=threadIdx.x,lane=t&31,wid=t>>5;
    __shared__ float s1[8],s2a[8]; __shared__ float bm,brs;
    float v[4],s=0.f,s2=0.f;
    #pragma unroll
    for(int i=0;i<4;i++){int d=t+i*256;float xx=pa[d];v[i]=xx;s+=xx;s2+=xx*xx;}
    s=wSum(s);s2=wSum(s2);
    if(lane==0){s1[wid]=s;s2a[wid]=s2;} __syncthreads();
    if(wid==0){float xs=(lane<8)?s1[lane]:0.f,x2=(lane<8)?s2a[lane]:0.f;
        xs=wSum(xs);x2=wSum(x2);
        if(lane==0){float mean=xs*(1.f/DMODEL);float var=fmaxf(x2*(1.f/DMODEL)-mean*mean,0.f);
            bm=mean;brs=rsqrtf(var+1e-5f);}}
    __syncthreads();
    float mean=bm,rstd=brs;
    s=0.f; s2=0.f;
    #pragma unroll
    for(int i=0;i<4;i++){int d=t+i*256;
        float y=(v[i]-mean)*rstd*lag[d]+lab[d] + px[d];
        v[i]=y; s+=y; s2+=y*y;}
    __syncthreads();
    s=wSum(s);s2=wSum(s2);
    if(lane==0){s1[wid]=s;s2a[wid]=s2;} __syncthreads();
    if(wid==0){float xs=(lane<8)?s1[lane]:0.f,x2=(lane<8)?s2a[lane]:0.f;
        xs=wSum(xs);x2=wSum(x2);
        if(lane==0){float mean2=xs*(1.f/DMODEL);float var=fmaxf(x2*(1.f/DMODEL)-mean2*mean2,0.f);
            bm=mean2;brs=rsqrtf(var+1e-5f);}}
    __syncthreads();
    mean=bm; rstd=brs;
    #pragma unroll
    for(int i=0;i<4;i++){int d=t+i*256;
        float y=(v[i]-mean)*rstd*n1g[d]+n1b[d];
        x1[row*DMODEL+d]=y;
        hf h=__float2half_rn(y);
        oh[row*DMODEL+d]=h;
        ol[row*DMODEL+d]=__float2half_rn(y-__half2float(h));}
}

// ---------------- launch ----------------
extern "C" void kernel_launch(void* const* d_in, const int* in_sizes, int n_in,
                              void* d_out, int out_size)
{
    const float* x   =(const float*)d_in[0];
    const int*  mask =(const int*)  d_in[1];
    const float* Wq=(const float*)d_in[2],  *bq=(const float*)d_in[3];
    const float* Wk=(const float*)d_in[4],  *bk=(const float*)d_in[5];
    const float* Wv=(const float*)d_in[6],  *bv=(const float*)d_in[7];
    const float* Wo=(const float*)d_in[8],  *bo=(const float*)d_in[9];
    const float* temp=(const float*)d_in[10], *tw=(const float*)d_in[11];
    const float* gW=(const float*)d_in[12], *gb=(const float*)d_in[13];
    const float* lag=(const float*)d_in[14],*lab=(const float*)d_in[15];
    const float* f1W=(const float*)d_in[16],*f1b=(const float*)d_in[17];
    const float* f2W=(const float*)d_in[18],*f2b=(const float*)d_in[19];
    const float* n1g=(const float*)d_in[20],*n1b=(const float*)d_in[21];
    const float* n2g=(const float*)d_in[22],*n2b=(const float*)d_in[23];
    float* out=(float*)d_out;

    float *t0,*x1,*gatep;
    hf *xh,*xl,*qh,*ql,*kh,*kl,*vh,*ch,*cl,*yh,*yl,*fh,*fl;
    hf *wqh,*wkh,*wvh,*woh,*w1h,*w2h;
    cudaGetSymbolAddress((void**)&t0,g_t0);   cudaGetSymbolAddress((void**)&x1,g_x1);
    cudaGetSymbolAddress((void**)&gatep,g_gate);
    cudaGetSymbolAddress((void**)&xh,g_xh); cudaGetSymbolAddress((void**)&xl,g_xl);
    cudaGetSymbolAddress((void**)&qh,g_qh); cudaGetSymbolAddress((void**)&ql,g_ql);
    cudaGetSymbolAddress((void**)&kh,g_kh); cudaGetSymbolAddress((void**)&kl,g_kl);
    cudaGetSymbolAddress((void**)&vh,g_vh);
    cudaGetSymbolAddress((void**)&ch,g_ch); cudaGetSymbolAddress((void**)&cl,g_cl);
    cudaGetSymbolAddress((void**)&yh,g_yh); cudaGetSymbolAddress((void**)&yl,g_yl);
    cudaGetSymbolAddress((void**)&fh,g_fh); cudaGetSymbolAddress((void**)&fl,g_fl);
    cudaGetSymbolAddress((void**)&wqh,g_wqh); cudaGetSymbolAddress((void**)&wkh,g_wkh);
    cudaGetSymbolAddress((void**)&wvh,g_wvh); cudaGetSymbolAddress((void**)&woh,g_woh);
    cudaGetSymbolAddress((void**)&w1h,g_w1h); cudaGetSymbolAddress((void**)&w2h,g_w2h);

    const int SMG = 2*4*10240;                 // 81920
    const int SMF = 36864 + 2*55296;           // 147456
    cudaFuncSetAttribute((const void*)hgemm,    cudaFuncAttributeMaxDynamicSharedMemorySize,SMG);
    cudaFuncSetAttribute((const void*)flashattn,cudaFuncAttributeMaxDynamicSharedMemorySize,SMF);

    dim3 tb(32,8);
    // launches 0-4: conversions needed for Q/K/V projections
    split_vk<<<ROWS*DMODEL/4/256,256>>>(x,xh,xl,ROWS*DMODEL/4);          // 0
    split_T<<<dim3(DMODEL/32,DMODEL/32),tb>>>(Wq,wqh,nullptr,DMODEL,DMODEL); // 1
    split_T<<<dim3(DMODEL/32,DMODEL/32),tb>>>(Wk,wkh,nullptr,DMODEL,DMODEL); // 2
    split_T<<<dim3(DMODEL/32,DMODEL/32),tb>>>(Wv,wvh,nullptr,DMODEL,DMODEL); // 3
    split_T<<<dim3(DMODEL/32,DMODEL/32),tb>>>(Wo,woh,nullptr,DMODEL,DMODEL); // 4

    // launch 5 (ncu capture target): Q projection hgemm
    dim3 gP(DMODEL/128,ROWS/128,1);
    hgemm<<<gP,256,SMG>>>(xh,xl,wqh,nullptr,DMODEL,DMODEL,DMODEL,DMODEL,
        nullptr,qh,ql,bq,tw,0,1);                                        // 5
    hgemm<<<gP,256,SMG>>>(xh,xl,wkh,nullptr,DMODEL,DMODEL,DMODEL,DMODEL,
        nullptr,kh,kl,bk,nullptr,0,1);
    hgemm<<<gP,256,SMG>>>(xh,xl,wvh,nullptr,DMODEL,DMODEL,DMODEL,DMODEL,
        nullptr,vh,nullptr,bv,nullptr,0,3);

    gatek<<<(ROWS*NHEADS)/8,256>>>(qh,ql,gW,gb,gatep);

    dim3 gA(SSEQ/128, ZTOT, 1);
    flashattn<<<gA,256,SMF>>>(qh,ql,kh,kl,vh,mask,gatep,temp,ch,cl);

    hgemm<<<gP,256,SMG>>>(ch,cl,woh,nullptr,DMODEL,DMODEL,DMODEL,DMODEL,
        t0,nullptr,nullptr,bo,nullptr,0,0);
    layernorm2_k<<<ROWS,256>>>(t0,x,lag,lab,n1g,n1b,x1,yh,yl);

    // FFN weight splits deferred here (keeps launch 5 = hgemm)
    split_T<<<dim3(DFF/32,DMODEL/32),tb>>>(f1W,w1h,nullptr,DMODEL,DFF);
    split_T<<<dim3(DMODEL/32,DFF/32),tb>>>(f2W,w2h,nullptr,DFF,DMODEL);

    dim3 gF(DFF/128,ROWS/128,1);
    hgemm<<<gF,256,SMG>>>(yh,yl,w1h,nullptr,DMODEL,DMODEL,DMODEL,DFF,
        nullptr,fh,fl,f1b,nullptr,1,1);
    hgemm<<<gP,256,SMG>>>(fh,fl,w2h,nullptr,DFF,DFF,DFF,DMODEL,
        t0,nullptr,nullptr,f2b,nullptr,0,0);

    layernorm_k<<<ROWS,256>>>(x1,t0,n2g,n2b,out,nullptr,nullptr);
}

// round 9
// speedup vs baseline: 9.4116x; 1.4906x over previous
#include <cuda_runtime.h>
#include <cuda_fp16.h>
#include <math.h>
#include <stdint.h>

#define SSEQ 2048
#define DMODEL 1024
#define NHEADS 16
#define DKH 64
#define DFF 4096
#define ROWS 4096
#define ZTOT 32
#define SD ((long long)SSEQ*DMODEL)
typedef __half hf;

// ---------------- scratch ----------------
__device__ __align__(256) float g_t0[ROWS*DMODEL];
__device__ __align__(256) float g_x1[ROWS*DMODEL];
__device__ __align__(256) float g_gate[ZTOT*SSEQ];
__device__ __align__(256) hf g_xh[ROWS*DMODEL];
__device__ __align__(256) hf g_qh[ROWS*DMODEL];
__device__ __align__(256) hf g_kh[ROWS*DMODEL];
__device__ __align__(256) hf g_vh[ROWS*DMODEL];
__device__ __align__(256) hf g_ch[ROWS*DMODEL];
__device__ __align__(256) hf g_yh[ROWS*DMODEL];
__device__ __align__(256) hf g_fh[ROWS*DFF];
__device__ __align__(256) hf g_wqh[DMODEL*DMODEL];
__device__ __align__(256) hf g_wkh[DMODEL*DMODEL];
__device__ __align__(256) hf g_wvh[DMODEL*DMODEL];
__device__ __align__(256) hf g_woh[DMODEL*DMODEL];
__device__ __align__(256) hf g_w1h[DMODEL*DFF];
__device__ __align__(256) hf g_w2h[DMODEL*DFF];

// ---------------- helpers ----------------
__device__ __forceinline__ uint32_t su32(const void* p){uint32_t a;
    asm("{.reg .u64 t; cvta.to.shared.u64 t,%1; cvt.u32.u64 %0,t;}":"=r"(a):"l"(p));return a;}
__device__ __forceinline__ void cpa(uint32_t d,const void*s){
    asm volatile("cp.async.cg.shared.global [%0],[%1],16;"::"r"(d),"l"(s));}
#define CPCOMMIT() asm volatile("cp.async.commit_group;":::"memory")
#define LDM4(f,a) asm volatile("ldmatrix.sync.aligned.m8n8.x4.shared.b16 {%0,%1,%2,%3},[%4];" \
    :"=r"((f)[0]),"=r"((f)[1]),"=r"((f)[2]),"=r"((f)[3]):"r"(a))
#define LDM4B(b0,b1,b2,b3,a) asm volatile("ldmatrix.sync.aligned.m8n8.x4.shared.b16 {%0,%1,%2,%3},[%4];" \
    :"=r"(b0),"=r"(b1),"=r"(b2),"=r"(b3):"r"(a))
#define LDM4T(f,a) asm volatile("ldmatrix.sync.aligned.m8n8.x4.trans.shared.b16 {%0,%1,%2,%3},[%4];" \
    :"=r"((f)[0]),"=r"((f)[1]),"=r"((f)[2]),"=r"((f)[3]):"r"(a))
#define MMA(c,A,B) asm volatile( \
    "mma.sync.aligned.m16n8k16.row.col.f32.f16.f16.f32 {%0,%1,%2,%3},{%4,%5,%6,%7},{%8,%9},{%0,%1,%2,%3};" \
    :"+f"((c)[0]),"+f"((c)[1]),"+f"((c)[2]),"+f"((c)[3]) \
    :"r"((A)[0]),"r"((A)[1]),"r"((A)[2]),"r"((A)[3]),"r"((B)[0]),"r"((B)[1]))
#define MMAB(c,A,b0,b1) asm volatile( \
    "mma.sync.aligned.m16n8k16.row.col.f32.f16.f16.f32 {%0,%1,%2,%3},{%4,%5,%6,%7},{%8,%9},{%0,%1,%2,%3};" \
    :"+f"((c)[0]),"+f"((c)[1]),"+f"((c)[2]),"+f"((c)[3]) \
    :"r"((A)[0]),"r"((A)[1]),"r"((A)[2]),"r"((A)[3]),"r"(b0),"r"(b1))

__device__ __forceinline__ uint32_t pack2h(float a, float b){
    __half2 hp=__floats2half2_rn(a,b);
    return *(uint32_t*)&hp;
}

// ---------------- fp16 HMMA GEMM ----------------
// C = A[M,K] @ B[N,K]^T. 128x128 tile, BK=32, 2 stages, 256 thr, occ 2.
// epi: 0 bias(+bias2), 1 bias+GELU ; outm: 0 fp32, 1 fp16
__global__ __launch_bounds__(256,2) void hgemm(
    const hf* __restrict__ A_, const hf* __restrict__ B_,
    int K, int lda, int ldb, int ldc,
    float* __restrict__ Cf, hf* __restrict__ Ch,
    const float* __restrict__ bias, const float* __restrict__ bias2,
    int epi, int outm)
{
    constexpr int STG = 2*10240;
    extern __shared__ char smraw[];
    uint32_t su = su32(smraw);
    int tid = threadIdx.x, wid = tid>>5, lane = tid&31;
    int wm = wid%2, wn = wid/2;
    int m0 = blockIdx.y*128, n0 = blockIdx.x*128;

    const hf* pA = A_ + (long long)m0*lda;
    const hf* pB = B_ + (long long)n0*ldb;
    int nk = K>>5;

    int r = tid>>2, sg = tid&3;
    auto loadstage = [&](int ci, int st){
        uint32_t b = su + (uint32_t)st*STG;
        int k0 = ci<<5;
        #pragma unroll
        for(int p=0;p<2;p++){
            int rr = r + p*64;
            cpa(b + rr*80 + sg*16,         pA + (long long)rr*lda + k0 + sg*8);
            cpa(b + 10240 + rr*80 + sg*16, pB + (long long)rr*ldb + k0 + sg*8);
        }
        CPCOMMIT();
    };

    float acc[4][4][4];
    #pragma unroll
    for(int a=0;a<4;a++)
        #pragma unroll
        for(int b=0;b<4;b++)
            #pragma unroll
            for(int c=0;c<4;c++) acc[a][b][c]=0.f;

    int quad = lane>>3, lq = lane&7;
    uint32_t aoff = (uint32_t)((wm*64 + (quad&1)*8 + lq)*80 + (quad>>1)*16);
    uint32_t boff = (uint32_t)(10240 + (wn*32 + (quad>>1)*8 + lq)*80 + (quad&1)*16);

    loadstage(0,0);
    if(nk>1) loadstage(1,1);

    for(int i=0;i<nk;i++){
        if(i+1<nk) asm volatile("cp.async.wait_group 1;":::"memory");
        else       asm volatile("cp.async.wait_group 0;":::"memory");
        __syncthreads();
        uint32_t sb = su + (uint32_t)(i&1)*STG;
        uint32_t pa = sb + aoff, pb = sb + boff;
        uint32_t Af[4][4], Bf[4][2];
        #pragma unroll
        for(int ks=0;ks<2;ks++){
            uint32_t kso = ks*32;
            #pragma unroll
            for(int mt=0;mt<4;mt++) LDM4(Af[mt], pa + mt*1280 + kso);
            #pragma unroll
            for(int np=0;np<2;np++)
                LDM4B(Bf[2*np][0],Bf[2*np][1],Bf[2*np+1][0],Bf[2*np+1][1], pb + np*1280 + kso);
            #pragma unroll
            for(int mt=0;mt<4;mt++)
                #pragma unroll
                for(int nt=0;nt<4;nt++) MMA(acc[mt][nt],Af[mt],Bf[nt]);
        }
        __syncthreads();
        if(i+2<nk) loadstage(i+2, i&1);
    }

    auto store2 = [&](int row,int col,float v0,float v1){
        if(bias){ v0+=bias[col]; v1+=bias[col+1]; }
        if(bias2){ v0+=bias2[col]; v1+=bias2[col+1]; }
        if(epi==1){
            v0 = 0.5f*v0*(1.0f+erff(v0*0.70710678118654752f));
            v1 = 0.5f*v1*(1.0f+erff(v1*0.70710678118654752f));
        }
        if(outm==0){
            *(float2*)&Cf[(long long)row*ldc+col] = make_float2(v0,v1);
        } else {
            *(uint32_t*)(Ch+(long long)row*ldc+col) = pack2h(v0,v1);
        }
    };
    #pragma unroll
    for(int mt=0;mt<4;mt++){
        #pragma unroll
        for(int nt=0;nt<4;nt++){
            int row0 = m0 + wm*64 + mt*16 + (lane>>2);
            int col  = n0 + wn*32 + nt*8 + ((lane&3)<<1);
            store2(row0,   col, acc[mt][nt][0], acc[mt][nt][1]);
            store2(row0+8, col, acc[mt][nt][2], acc[mt][nt][3]);
        }
    }
}

// ---------------- flash attention (pure fp16 operands) ----------------
// S = Q K^T; /T, mask, *gate; online softmax; O += P V.
#define PITCH 144
__global__ __launch_bounds__(256,1) void flashattn(
    const hf* __restrict__ qh_, const hf* __restrict__ kh_, const hf* __restrict__ vh_,
    const int* __restrict__ mask, const float* __restrict__ gate,
    const float* __restrict__ temp, hf* __restrict__ ch)
{
    extern __shared__ char sm[];
    uint32_t su = su32(sm);
    const uint32_t ST=18432, STSZ=36864;
    int tid=threadIdx.x, wid=tid>>5, lane=tid&31;
    int quad=lane>>3, lq=lane&7;
    int z=blockIdx.y, zb=z>>4, zh=z&15;
    int q0=blockIdx.x*128;
    long long hoff=(long long)zb*SD + zh*64;
    const hf* pq = qh_ + hoff + (long long)q0*DMODEL;

    int cc=tid&7, rr0=tid>>3;
    #pragma unroll
    for(int p=0;p<4;p++){
        int r=rr0+p*32;
        cpa(su + r*PITCH + cc*16, pq + (long long)r*DMODEL + cc*8);
    }
    CPCOMMIT();

    auto ldstage=[&](int it,int st){
        uint32_t b=su+ST+(uint32_t)st*STSZ;
        long long kbase=hoff + (long long)(it*128)*DMODEL;
        #pragma unroll
        for(int p=0;p<4;p++){
            int r=rr0+p*32;
            long long go=kbase+(long long)r*DMODEL+cc*8;
            uint32_t so=r*PITCH+cc*16;
            cpa(b+so, kh_+go);
            cpa(b+18432+so, vh_+go);
        }
        CPCOMMIT();
    };
    ldstage(0,0); ldstage(1,1);
    asm volatile("cp.async.wait_group 2;":::"memory");
    __syncthreads();

    uint32_t qaddr = su + (uint32_t)((wid*16 + (quad&1)*8 + lq)*PITCH + (quad>>1)*16);
    uint32_t qf[4][4];
    #pragma unroll
    for(int ks=0;ks<4;ks++) LDM4(qf[ks], qaddr+ks*32);

    int r0l = wid*16 + (lane>>2);
    float g0 = gate[(long long)z*SSEQ + q0 + r0l];
    float g1 = gate[(long long)z*SSEQ + q0 + r0l + 8];
    float invT = 1.f/temp[0];
    float m0=-1e30f,m1=-1e30f,l0=0.f,l1=0.f;
    float oacc[8][4];
    #pragma unroll
    for(int d=0;d<8;d++){oacc[d][0]=0;oacc[d][1]=0;oacc[d][2]=0;oacc[d][3]=0;}

    for(int it=0; it<16; it++){
        if(it<15) asm volatile("cp.async.wait_group 1;":::"memory");
        else      asm volatile("cp.async.wait_group 0;":::"memory");
        __syncthreads();
        uint32_t sb = su+ST+(uint32_t)(it&1)*STSZ;

        float sacc[16][4];
        #pragma unroll
        for(int nt=0;nt<16;nt++){sacc[nt][0]=0;sacc[nt][1]=0;sacc[nt][2]=0;sacc[nt][3]=0;}
        uint32_t baddr = sb + (uint32_t)((lq + 8*(quad>>1))*PITCH + (quad&1)*16);
        #pragma unroll
        for(int ks=0;ks<4;ks++){
            uint32_t b[16][2];
            #pragma unroll
            for(int j=0;j<8;j++)
                LDM4B(b[2*j][0],b[2*j][1],b[2*j+1][0],b[2*j+1][1], baddr + j*(16*PITCH) + ks*32);
            #pragma unroll
            for(int nt=0;nt<16;nt++) MMA(sacc[nt], qf[ks], b[nt]);
        }

        long long mrow0 = (long long)(q0 + r0l)*SSEQ + it*128 + 2*(lane&3);
        long long mrow1 = mrow0 + 8LL*SSEQ;
        float rm0=-1e30f, rm1=-1e30f;
        #pragma unroll
        for(int nt=0;nt<16;nt++){
            int2 mA = *(const int2*)&mask[mrow0 + nt*8];
            int2 mB = *(const int2*)&mask[mrow1 + nt*8];
            float s0=sacc[nt][0]*invT, s1=sacc[nt][1]*invT;
            float s2=sacc[nt][2]*invT, s3=sacc[nt][3]*invT;
            if(mA.x==0)s0=-1e9f; if(mA.y==0)s1=-1e9f;
            if(mB.x==0)s2=-1e9f; if(mB.y==0)s3=-1e9f;
            s0*=g0;s1*=g0;s2*=g1;s3*=g1;
            sacc[nt][0]=s0;sacc[nt][1]=s1;sacc[nt][2]=s2;sacc[nt][3]=s3;
            rm0=fmaxf(rm0,fmaxf(s0,s1)); rm1=fmaxf(rm1,fmaxf(s2,s3));
        }
        rm0=fmaxf(rm0,__shfl_xor_sync(~0u,rm0,1)); rm0=fmaxf(rm0,__shfl_xor_sync(~0u,rm0,2));
        rm1=fmaxf(rm1,__shfl_xor_sync(~0u,rm1,1)); rm1=fmaxf(rm1,__shfl_xor_sync(~0u,rm1,2));
        float mn0=fmaxf(m0,rm0), mn1=fmaxf(m1,rm1);
        float sc0=__expf(m0-mn0), sc1=__expf(m1-mn1);
        m0=mn0; m1=mn1;

        float rs0=0.f, rs1=0.f;
        #pragma unroll
        for(int nt=0;nt<16;nt++){
            float p0=__expf(sacc[nt][0]-m0), p1=__expf(sacc[nt][1]-m0);
            float p2=__expf(sacc[nt][2]-m1), p3=__expf(sacc[nt][3]-m1);
            sacc[nt][0]=p0;sacc[nt][1]=p1;sacc[nt][2]=p2;sacc[nt][3]=p3;
            rs0+=p0+p1; rs1+=p2+p3;
        }
        rs0+=__shfl_xor_sync(~0u,rs0,1); rs0+=__shfl_xor_sync(~0u,rs0,2);
        rs1+=__shfl_xor_sync(~0u,rs1,1); rs1+=__shfl_xor_sync(~0u,rs1,2);
        l0 = l0*sc0 + rs0; l1 = l1*sc1 + rs1;
        #pragma unroll
        for(int d=0;d<8;d++){ oacc[d][0]*=sc0; oacc[d][1]*=sc0; oacc[d][2]*=sc1; oacc[d][3]*=sc1; }

        #pragma unroll
        for(int kv=0;kv<8;kv++){
            uint32_t pa[4];
            pa[0]=pack2h(sacc[2*kv][0],   sacc[2*kv][1]);
            pa[1]=pack2h(sacc[2*kv][2],   sacc[2*kv][3]);
            pa[2]=pack2h(sacc[2*kv+1][0], sacc[2*kv+1][1]);
            pa[3]=pack2h(sacc[2*kv+1][2], sacc[2*kv+1][3]);
            uint32_t vbase = sb + 18432 + (uint32_t)((16*kv + lq + 8*(quad&1))*PITCH + 16*(quad>>1));
            #pragma unroll
            for(int jp=0;jp<4;jp++){
                uint32_t vh4[4];
                LDM4T(vh4, vbase + jp*32);
                MMAB(oacc[2*jp],   pa, vh4[0], vh4[1]);
                MMAB(oacc[2*jp+1], pa, vh4[2], vh4[3]);
            }
        }
        __syncthreads();
        if(it+2<16) ldstage(it+2, it&1);
    }

    float inv0=1.f/l0, inv1=1.f/l1;
    long long orow0 = (long long)zb*SD + (long long)(q0+r0l)*DMODEL + zh*64;
    long long orow1 = orow0 + 8LL*DMODEL;
    #pragma unroll
    for(int d=0;d<8;d++){
        int col = d*8 + 2*(lane&3);
        *(uint32_t*)(ch+orow0+col)=pack2h(oacc[d][0]*inv0, oacc[d][1]*inv0);
        *(uint32_t*)(ch+orow1+col)=pack2h(oacc[d][2]*inv1, oacc[d][3]*inv1);
    }
}

// ---------------- support kernels ----------------
__global__ void cvt_h(const float* __restrict__ in, hf* __restrict__ hi, int n4){
    int i=blockIdx.x*blockDim.x+threadIdx.x; if(i>=n4)return;
    float4 v=((const float4*)in)[i];
    ((uint32_t*)hi)[2*i]  =pack2h(v.x,v.y);
    ((uint32_t*)hi)[2*i+1]=pack2h(v.z,v.w);
}
__global__ void split_T(const float* __restrict__ W, hf* __restrict__ hi, int R, int C){
    __shared__ float t[32][33];
    int c0=blockIdx.x*32, r0=blockIdx.y*32, tx=threadIdx.x, ty=threadIdx.y;
    for(int i=ty;i<32;i+=8) t[i][tx]=W[(long long)(r0+i)*C+c0+tx];
    __syncthreads();
    for(int i=ty;i<32;i+=8)
        hi[(long long)(c0+i)*R+r0+tx]=__float2half_rn(t[tx][i]);
}
__global__ void gatek(const hf* __restrict__ qh,
                      const float* __restrict__ gW,const float* __restrict__ gb,
                      float* __restrict__ gate){
    int warp=(blockIdx.x*blockDim.x+threadIdx.x)>>5, lane=threadIdx.x&31;
    if(warp>=ROWS*NHEADS)return;
    int bs=warp>>4,h=warp&15;
    long long base=(long long)bs*DMODEL+h*DKH;
    float q0=__half2float(qh[base+lane]);
    float q1=__half2float(qh[base+lane+32]);
    float s=q0*gW[lane]+q1*gW[lane+32];
    #pragma unroll
    for(int o=16;o;o>>=1)s+=__shfl_xor_sync(~0u,s,o);
    if(lane==0){int b=bs>>11,sr=bs&2047;
        gate[(long long)(b*NHEADS+h)*SSEQ+sr]=1.f/(1.f+expf(-(s+gb[0])));}
}
__device__ __forceinline__ float wSum(float v){
    #pragma unroll
    for(int o=16;o;o>>=1)v+=__shfl_xor_sync(~0u,v,o); return v;}

__global__ void __launch_bounds__(256) layernorm_k(const float* __restrict__ a,
    const float* __restrict__ resid, const float* __restrict__ g, const float* __restrict__ b,
    float* __restrict__ outf, hf* __restrict__ oh){
    long long row=blockIdx.x;
    const float* pa=a+row*DMODEL;
    const float* pr=resid?resid+row*DMODEL:nullptr;
    int t=threadIdx.x,lane=t&31,wid=t>>5;
    __shared__ float s1[8],s2a[8]; __shared__ float bm,brs;
    float v[4],s=0.f,s2=0.f;
    #pragma unroll
    for(int i=0;i<4;i++){int d=t+i*256;float x=pa[d]+(pr?pr[d]:0.f);v[i]=x;s+=x;s2+=x*x;}
    s=wSum(s);s2=wSum(s2);
    if(lane==0){s1[wid]=s;s2a[wid]=s2;} __syncthreads();
    if(wid==0){float xs=(lane<8)?s1[lane]:0.f,x2=(lane<8)?s2a[lane]:0.f;
        xs=wSum(xs);x2=wSum(x2);
        if(lane==0){float mean=xs*(1.f/DMODEL);float var=fmaxf(x2*(1.f/DMODEL)-mean*mean,0.f);
            bm=mean;brs=rsqrtf(var+1e-5f);}}
    __syncthreads();
    float mean=bm,rstd=brs;
    #pragma unroll
    for(int i=0;i<4;i++){int d=t+i*256;float y=(v[i]-mean)*rstd*g[d]+b[d];
        if(outf)outf[row*DMODEL+d]=y;
        if(oh)oh[row*DMODEL+d]=__float2half_rn(y);}
}

// fused: attn = LN(t0)*lag+lab ; x1 = LN(x + attn)*n1g+n1b -> x1 fp32 + fp16
__global__ void __launch_bounds__(256) layernorm2_k(const float* __restrict__ t0,
    const float* __restrict__ x,
    const float* __restrict__ lag, const float* __restrict__ lab,
    const float* __restrict__ n1g, const float* __restrict__ n1b,
    float* __restrict__ x1, hf* __restrict__ oh){
    long long row=blockIdx.x;
    const float* pa=t0+row*DMODEL;
    const float* px=x+row*DMODEL;
    int t=threadIdx.x,lane=t&31,wid=t>>5;
    __shared__ float s1[8],s2a[8]; __shared__ float bm,brs;
    float v[4],s=0.f,s2=0.f;
    #pragma unroll
    for(int i=0;i<4;i++){int d=t+i*256;float xx=pa[d];v[i]=xx;s+=xx;s2+=xx*xx;}
    s=wSum(s);s2=wSum(s2);
    if(lane==0){s1[wid]=s;s2a[wid]=s2;} __syncthreads();
    if(wid==0){float xs=(lane<8)?s1[lane]:0.f,x2=(lane<8)?s2a[lane]:0.f;
        xs=wSum(xs);x2=wSum(x2);
        if(lane==0){float mean=xs*(1.f/DMODEL);float var=fmaxf(x2*(1.f/DMODEL)-mean*mean,0.f);
            bm=mean;brs=rsqrtf(var+1e-5f);}}
    __syncthreads();
    float mean=bm,rstd=brs;
    s=0.f; s2=0.f;
    #pragma unroll
    for(int i=0;i<4;i++){int d=t+i*256;
        float y=(v[i]-mean)*rstd*lag[d]+lab[d] + px[d];
        v[i]=y; s+=y; s2+=y*y;}
    __syncthreads();
    s=wSum(s);s2=wSum(s2);
    if(lane==0){s1[wid]=s;s2a[wid]=s2;} __syncthreads();
    if(wid==0){float xs=(lane<8)?s1[lane]:0.f,x2=(lane<8)?s2a[lane]:0.f;
        xs=wSum(xs);x2=wSum(x2);
        if(lane==0){float mean2=xs*(1.f/DMODEL);float var=fmaxf(x2*(1.f/DMODEL)-mean2*mean2,0.f);
            bm=mean2;brs=rsqrtf(var+1e-5f);}}
    __syncthreads();
    mean=bm; rstd=brs;
    #pragma unroll
    for(int i=0;i<4;i++){int d=t+i*256;
        float y=(v[i]-mean)*rstd*n1g[d]+n1b[d];
        x1[row*DMODEL+d]=y;
        oh[row*DMODEL+d]=__float2half_rn(y);}
}

// ---------------- launch ----------------
extern "C" void kernel_launch(void* const* d_in, const int* in_sizes, int n_in,
                              void* d_out, int out_size)
{
    const float* x   =(const float*)d_in[0];
    const int*  mask =(const int*)  d_in[1];
    const float* Wq=(const float*)d_in[2],  *bq=(const float*)d_in[3];
    const float* Wk=(const float*)d_in[4],  *bk=(const float*)d_in[5];
    const float* Wv=(const float*)d_in[6],  *bv=(const float*)d_in[7];
    const float* Wo=(const float*)d_in[8],  *bo=(const float*)d_in[9];
    const float* temp=(const float*)d_in[10], *tw=(const float*)d_in[11];
    const float* gW=(const float*)d_in[12], *gb=(const float*)d_in[13];
    const float* lag=(const float*)d_in[14],*lab=(const float*)d_in[15];
    const float* f1W=(const float*)d_in[16],*f1b=(const float*)d_in[17];
    const float* f2W=(const float*)d_in[18],*f2b=(const float*)d_in[19];
    const float* n1g=(const float*)d_in[20],*n1b=(const float*)d_in[21];
    const float* n2g=(const float*)d_in[22],*n2b=(const float*)d_in[23];
    float* out=(float*)d_out;

    float *t0,*x1,*gatep;
    hf *xh,*qh,*kh,*vh,*ch,*yh,*fh;
    hf *wqh,*wkh,*wvh,*woh,*w1h,*w2h;
    cudaGetSymbolAddress((void**)&t0,g_t0);   cudaGetSymbolAddress((void**)&x1,g_x1);
    cudaGetSymbolAddress((void**)&gatep,g_gate);
    cudaGetSymbolAddress((void**)&xh,g_xh);
    cudaGetSymbolAddress((void**)&qh,g_qh); cudaGetSymbolAddress((void**)&kh,g_kh);
    cudaGetSymbolAddress((void**)&vh,g_vh); cudaGetSymbolAddress((void**)&ch,g_ch);
    cudaGetSymbolAddress((void**)&yh,g_yh); cudaGetSymbolAddress((void**)&fh,g_fh);
    cudaGetSymbolAddress((void**)&wqh,g_wqh); cudaGetSymbolAddress((void**)&wkh,g_wkh);
    cudaGetSymbolAddress((void**)&wvh,g_wvh); cudaGetSymbolAddress((void**)&woh,g_woh);
    cudaGetSymbolAddress((void**)&w1h,g_w1h); cudaGetSymbolAddress((void**)&w2h,g_w2h);

    const int SMG = 2*2*10240;                 // 40960
    const int SMF = 18432 + 2*36864;           // 92160
    cudaFuncSetAttribute((const void*)hgemm,    cudaFuncAttributeMaxDynamicSharedMemorySize,SMG);
    cudaFuncSetAttribute((const void*)flashattn,cudaFuncAttributeMaxDynamicSharedMemorySize,SMF);

    dim3 tb(32,8);
    // launches 0-4
    cvt_h<<<ROWS*DMODEL/4/256,256>>>(x,xh,ROWS*DMODEL/4);                    // 0
    split_T<<<dim3(DMODEL/32,DMODEL/32),tb>>>(Wq,wqh,DMODEL,DMODEL);         // 1
    split_T<<<dim3(DMODEL/32,DMODEL/32),tb>>>(Wk,wkh,DMODEL,DMODEL);         // 2
    split_T<<<dim3(DMODEL/32,DMODEL/32),tb>>>(Wv,wvh,DMODEL,DMODEL);         // 3
    split_T<<<dim3(DMODEL/32,DMODEL/32),tb>>>(Wo,woh,DMODEL,DMODEL);         // 4

    // launch 5 (ncu capture target): Q projection
    dim3 gP(DMODEL/128,ROWS/128,1);
    hgemm<<<gP,256,SMG>>>(xh,wqh,DMODEL,DMODEL,DMODEL,DMODEL,
        nullptr,qh,bq,tw,0,1);                                               // 5
    hgemm<<<gP,256,SMG>>>(xh,wkh,DMODEL,DMODEL,DMODEL,DMODEL,
        nullptr,kh,bk,nullptr,0,1);
    hgemm<<<gP,256,SMG>>>(xh,wvh,DMODEL,DMODEL,DMODEL,DMODEL,
        nullptr,vh,bv,nullptr,0,1);

    gatek<<<(ROWS*NHEADS)/8,256>>>(qh,gW,gb,gatep);

    dim3 gA(SSEQ/128, ZTOT, 1);
    flashattn<<<gA,256,SMF>>>(qh,kh,vh,mask,gatep,temp,ch);

    hgemm<<<gP,256,SMG>>>(ch,woh,DMODEL,DMODEL,DMODEL,DMODEL,
        t0,nullptr,bo,nullptr,0,0);
    layernorm2_k<<<ROWS,256>>>(t0,x,lag,lab,n1g,n1b,x1,yh);

    split_T<<<dim3(DFF/32,DMODEL/32),tb>>>(f1W,w1h,DMODEL,DFF);
    split_T<<<dim3(DMODEL/32,DFF/32),tb>>>(f2W,w2h,DFF,DMODEL);

    dim3 gF(DFF/128,ROWS/128,1);
    hgemm<<<gF,256,SMG>>>(yh,w1h,DMODEL,DMODEL,DMODEL,DFF,
        nullptr,fh,f1b,nullptr,1,1);
    hgemm<<<gP,256,SMG>>>(fh,w2h,DFF,DFF,DFF,DMODEL,
        t0,nullptr,f2b,nullptr,0,0);

    layernorm_k<<<ROWS,256>>>(x1,t0,n2g,n2b,out,nullptr);
}

// round 10
// speedup vs baseline: 9.7832x; 1.0395x over previous
#include <cuda_runtime.h>
#include <cuda_fp16.h>
#include <math.h>
#include <stdint.h>

#define SSEQ 2048
#define DMODEL 1024
#define NHEADS 16
#define DKH 64
#define DFF 4096
#define ROWS 4096
#define ZTOT 32
#define SD ((long long)SSEQ*DMODEL)
typedef __half hf;

// ---------------- scratch ----------------
__device__ __align__(256) float g_t0[ROWS*DMODEL];
__device__ __align__(256) float g_x1[ROWS*DMODEL];
__device__ __align__(256) float g_gate[ZTOT*SSEQ];
__device__ __align__(256) hf g_xh[ROWS*DMODEL];
__device__ __align__(256) hf g_qh[ROWS*DMODEL];
__device__ __align__(256) hf g_kh[ROWS*DMODEL];
__device__ __align__(256) hf g_vh[ROWS*DMODEL];
__device__ __align__(256) hf g_ch[ROWS*DMODEL];
__device__ __align__(256) hf g_yh[ROWS*DMODEL];
__device__ __align__(256) hf g_fh[ROWS*DFF];
__device__ __align__(256) hf g_wqh[DMODEL*DMODEL];
__device__ __align__(256) hf g_wkh[DMODEL*DMODEL];
__device__ __align__(256) hf g_wvh[DMODEL*DMODEL];
__device__ __align__(256) hf g_woh[DMODEL*DMODEL];
__device__ __align__(256) hf g_w1h[DMODEL*DFF];
__device__ __align__(256) hf g_w2h[DMODEL*DFF];

// ---------------- helpers ----------------
__device__ __forceinline__ uint32_t su32(const void* p){uint32_t a;
    asm("{.reg .u64 t; cvta.to.shared.u64 t,%1; cvt.u32.u64 %0,t;}":"=r"(a):"l"(p));return a;}
__device__ __forceinline__ void cpa(uint32_t d,const void*s){
    asm volatile("cp.async.cg.shared.global [%0],[%1],16;"::"r"(d),"l"(s));}
#define CPCOMMIT() asm volatile("cp.async.commit_group;":::"memory")
#define LDM4(f,a) asm volatile("ldmatrix.sync.aligned.m8n8.x4.shared.b16 {%0,%1,%2,%3},[%4];" \
    :"=r"((f)[0]),"=r"((f)[1]),"=r"((f)[2]),"=r"((f)[3]):"r"(a))
#define LDM4B(b0,b1,b2,b3,a) asm volatile("ldmatrix.sync.aligned.m8n8.x4.shared.b16 {%0,%1,%2,%3},[%4];" \
    :"=r"(b0),"=r"(b1),"=r"(b2),"=r"(b3):"r"(a))
#define LDM4T(f,a) asm volatile("ldmatrix.sync.aligned.m8n8.x4.trans.shared.b16 {%0,%1,%2,%3},[%4];" \
    :"=r"((f)[0]),"=r"((f)[1]),"=r"((f)[2]),"=r"((f)[3]):"r"(a))
#define MMA(c,A,B) asm volatile( \
    "mma.sync.aligned.m16n8k16.row.col.f32.f16.f16.f32 {%0,%1,%2,%3},{%4,%5,%6,%7},{%8,%9},{%0,%1,%2,%3};" \
    :"+f"((c)[0]),"+f"((c)[1]),"+f"((c)[2]),"+f"((c)[3]) \
    :"r"((A)[0]),"r"((A)[1]),"r"((A)[2]),"r"((A)[3]),"r"((B)[0]),"r"((B)[1]))
#define MMAB(c,A,b0,b1) asm volatile( \
    "mma.sync.aligned.m16n8k16.row.col.f32.f16.f16.f32 {%0,%1,%2,%3},{%4,%5,%6,%7},{%8,%9},{%0,%1,%2,%3};" \
    :"+f"((c)[0]),"+f"((c)[1]),"+f"((c)[2]),"+f"((c)[3]) \
    :"r"((A)[0]),"r"((A)[1]),"r"((A)[2]),"r"((A)[3]),"r"(b0),"r"(b1))

__device__ __forceinline__ uint32_t pack2h(float a, float b){
    __half2 hp=__floats2half2_rn(a,b);
    return *(uint32_t*)&hp;
}

// ---------------- fp16 HMMA GEMM ----------------
// C = A[M,K] @ B[N,K]^T. 128x128 tile, BK=32, 3-stage cp.async ring, occ 2.
// One __syncthreads per K-chunk; prefetch issued before compute.
__global__ __launch_bounds__(256,2) void hgemm(
    const hf* __restrict__ A_, const hf* __restrict__ B_,
    int K, int lda, int ldb, int ldc,
    float* __restrict__ Cf, hf* __restrict__ Ch,
    const float* __restrict__ bias, const float* __restrict__ bias2,
    int epi, int outm)
{
    constexpr int STG = 2*10240;
    extern __shared__ char smraw[];
    uint32_t su = su32(smraw);
    int tid = threadIdx.x, wid = tid>>5, lane = tid&31;
    int wm = wid%2, wn = wid/2;
    int m0 = blockIdx.y*128, n0 = blockIdx.x*128;

    const hf* pA = A_ + (long long)m0*lda;
    const hf* pB = B_ + (long long)n0*ldb;
    int nk = K>>5;

    int r = tid>>2, sg = tid&3;
    auto loadstage = [&](int ci, int st){
        uint32_t b = su + (uint32_t)st*STG;
        int k0 = ci<<5;
        #pragma unroll
        for(int p=0;p<2;p++){
            int rr = r + p*64;
            cpa(b + rr*80 + sg*16,         pA + (long long)rr*lda + k0 + sg*8);
            cpa(b + 10240 + rr*80 + sg*16, pB + (long long)rr*ldb + k0 + sg*8);
        }
        CPCOMMIT();
    };

    float acc[4][4][4];
    #pragma unroll
    for(int a=0;a<4;a++)
        #pragma unroll
        for(int b=0;b<4;b++)
            #pragma unroll
            for(int c=0;c<4;c++) acc[a][b][c]=0.f;

    int quad = lane>>3, lq = lane&7;
    uint32_t aoff = (uint32_t)((wm*64 + (quad&1)*8 + lq)*80 + (quad>>1)*16);
    uint32_t boff = (uint32_t)(10240 + (wn*32 + (quad>>1)*8 + lq)*80 + (quad&1)*16);

    loadstage(0,0);
    if(nk>1) loadstage(1,1);

    int st = 0;
    for(int i=0;i<nk;i++){
        if(i+1<nk) asm volatile("cp.async.wait_group 1;":::"memory");
        else       asm volatile("cp.async.wait_group 0;":::"memory");
        __syncthreads();
        if(i+2<nk){
            int st2 = st+2; if(st2>=3) st2-=3;
            loadstage(i+2, st2);
        }
        uint32_t sb = su + (uint32_t)st*STG;
        uint32_t pa = sb + aoff, pb = sb + boff;
        uint32_t Af[4][4], Bf[4][2];
        #pragma unroll
        for(int ks=0;ks<2;ks++){
            uint32_t kso = ks*32;
            #pragma unroll
            for(int mt=0;mt<4;mt++) LDM4(Af[mt], pa + mt*1280 + kso);
            #pragma unroll
            for(int np=0;np<2;np++)
                LDM4B(Bf[2*np][0],Bf[2*np][1],Bf[2*np+1][0],Bf[2*np+1][1], pb + np*1280 + kso);
            #pragma unroll
            for(int mt=0;mt<4;mt++)
                #pragma unroll
                for(int nt=0;nt<4;nt++) MMA(acc[mt][nt],Af[mt],Bf[nt]);
        }
        if(++st==3) st=0;
    }

    auto store2 = [&](int row,int col,float v0,float v1){
        if(bias){ v0+=bias[col]; v1+=bias[col+1]; }
        if(bias2){ v0+=bias2[col]; v1+=bias2[col+1]; }
        if(epi==1){
            v0 = 0.5f*v0*(1.0f+erff(v0*0.70710678118654752f));
            v1 = 0.5f*v1*(1.0f+erff(v1*0.70710678118654752f));
        }
        if(outm==0){
            *(float2*)&Cf[(long long)row*ldc+col] = make_float2(v0,v1);
        } else {
            *(uint32_t*)(Ch+(long long)row*ldc+col) = pack2h(v0,v1);
        }
    };
    #pragma unroll
    for(int mt=0;mt<4;mt++){
        #pragma unroll
        for(int nt=0;nt<4;nt++){
            int row0 = m0 + wm*64 + mt*16 + (lane>>2);
            int col  = n0 + wn*32 + nt*8 + ((lane&3)<<1);
            store2(row0,   col, acc[mt][nt][0], acc[mt][nt][1]);
            store2(row0+8, col, acc[mt][nt][2], acc[mt][nt][3]);
        }
    }
}

// ---------------- flash attention (fp16, 3-stage K/V ring) ----------------
#define PITCH 144
__global__ __launch_bounds__(256,1) void flashattn(
    const hf* __restrict__ qh_, const hf* __restrict__ kh_, const hf* __restrict__ vh_,
    const int* __restrict__ mask, const float* __restrict__ gate,
    const float* __restrict__ temp, hf* __restrict__ ch)
{
    extern __shared__ char sm[];
    uint32_t su = su32(sm);
    const uint32_t ST=18432, STSZ=36864;
    int tid=threadIdx.x, wid=tid>>5, lane=tid&31;
    int quad=lane>>3, lq=lane&7;
    int z=blockIdx.y, zb=z>>4, zh=z&15;
    int q0=blockIdx.x*128;
    long long hoff=(long long)zb*SD + zh*64;
    const hf* pq = qh_ + hoff + (long long)q0*DMODEL;

    int cc=tid&7, rr0=tid>>3;
    #pragma unroll
    for(int p=0;p<4;p++){
        int r=rr0+p*32;
        cpa(su + r*PITCH + cc*16, pq + (long long)r*DMODEL + cc*8);
    }
    CPCOMMIT();

    auto ldstage=[&](int it,int st){
        uint32_t b=su+ST+(uint32_t)st*STSZ;
        long long kbase=hoff + (long long)(it*128)*DMODEL;
        #pragma unroll
        for(int p=0;p<4;p++){
            int r=rr0+p*32;
            long long go=kbase+(long long)r*DMODEL+cc*8;
            uint32_t so=r*PITCH+cc*16;
            cpa(b+so, kh_+go);
            cpa(b+18432+so, vh_+go);
        }
        CPCOMMIT();
    };
    ldstage(0,0); ldstage(1,1);
    asm volatile("cp.async.wait_group 2;":::"memory");  // Q group done
    __syncthreads();

    uint32_t qaddr = su + (uint32_t)((wid*16 + (quad&1)*8 + lq)*PITCH + (quad>>1)*16);
    uint32_t qf[4][4];
    #pragma unroll
    for(int ks=0;ks<4;ks++) LDM4(qf[ks], qaddr+ks*32);

    int r0l = wid*16 + (lane>>2);
    float g0 = gate[(long long)z*SSEQ + q0 + r0l];
    float g1 = gate[(long long)z*SSEQ + q0 + r0l + 8];
    float invT = 1.f/temp[0];
    float m0=-1e30f,m1=-1e30f,l0=0.f,l1=0.f;
    float oacc[8][4];
    #pragma unroll
    for(int d=0;d<8;d++){oacc[d][0]=0;oacc[d][1]=0;oacc[d][2]=0;oacc[d][3]=0;}

    int st = 0;
    for(int it=0; it<16; it++){
        if(it<15) asm volatile("cp.async.wait_group 1;":::"memory");
        else      asm volatile("cp.async.wait_group 0;":::"memory");
        __syncthreads();
        if(it+2<16){
            int st2 = st+2; if(st2>=3) st2-=3;
            ldstage(it+2, st2);
        }
        uint32_t sb = su+ST+(uint32_t)st*STSZ;

        float sacc[16][4];
        #pragma unroll
        for(int nt=0;nt<16;nt++){sacc[nt][0]=0;sacc[nt][1]=0;sacc[nt][2]=0;sacc[nt][3]=0;}
        uint32_t baddr = sb + (uint32_t)((lq + 8*(quad>>1))*PITCH + (quad&1)*16);
        #pragma unroll
        for(int ks=0;ks<4;ks++){
            uint32_t b[16][2];
            #pragma unroll
            for(int j=0;j<8;j++)
                LDM4B(b[2*j][0],b[2*j][1],b[2*j+1][0],b[2*j+1][1], baddr + j*(16*PITCH) + ks*32);
            #pragma unroll
            for(int nt=0;nt<16;nt++) MMA(sacc[nt], qf[ks], b[nt]);
        }

        long long mrow0 = (long long)(q0 + r0l)*SSEQ + it*128 + 2*(lane&3);
        long long mrow1 = mrow0 + 8LL*SSEQ;
        float rm0=-1e30f, rm1=-1e30f;
        #pragma unroll
        for(int nt=0;nt<16;nt++){
            int2 mA = *(const int2*)&mask[mrow0 + nt*8];
            int2 mB = *(const int2*)&mask[mrow1 + nt*8];
            float s0=sacc[nt][0]*invT, s1=sacc[nt][1]*invT;
            float s2=sacc[nt][2]*invT, s3=sacc[nt][3]*invT;
            if(mA.x==0)s0=-1e9f; if(mA.y==0)s1=-1e9f;
            if(mB.x==0)s2=-1e9f; if(mB.y==0)s3=-1e9f;
            s0*=g0;s1*=g0;s2*=g1;s3*=g1;
            sacc[nt][0]=s0;sacc[nt][1]=s1;sacc[nt][2]=s2;sacc[nt][3]=s3;
            rm0=fmaxf(rm0,fmaxf(s0,s1)); rm1=fmaxf(rm1,fmaxf(s2,s3));
        }
        rm0=fmaxf(rm0,__shfl_xor_sync(~0u,rm0,1)); rm0=fmaxf(rm0,__shfl_xor_sync(~0u,rm0,2));
        rm1=fmaxf(rm1,__shfl_xor_sync(~0u,rm1,1)); rm1=fmaxf(rm1,__shfl_xor_sync(~0u,rm1,2));
        float mn0=fmaxf(m0,rm0), mn1=fmaxf(m1,rm1);
        float sc0=__expf(m0-mn0), sc1=__expf(m1-mn1);
        m0=mn0; m1=mn1;

        float rs0=0.f, rs1=0.f;
        #pragma unroll
        for(int nt=0;nt<16;nt++){
            float p0=__expf(sacc[nt][0]-m0), p1=__expf(sacc[nt][1]-m0);
            float p2=__expf(sacc[nt][2]-m1), p3=__expf(sacc[nt][3]-m1);
            sacc[nt][0]=p0;sacc[nt][1]=p1;sacc[nt][2]=p2;sacc[nt][3]=p3;
            rs0+=p0+p1; rs1+=p2+p3;
        }
        rs0+=__shfl_xor_sync(~0u,rs0,1); rs0+=__shfl_xor_sync(~0u,rs0,2);
        rs1+=__shfl_xor_sync(~0u,rs1,1); rs1+=__shfl_xor_sync(~0u,rs1,2);
        l0 = l0*sc0 + rs0; l1 = l1*sc1 + rs1;
        #pragma unroll
        for(int d=0;d<8;d++){ oacc[d][0]*=sc0; oacc[d][1]*=sc0; oacc[d][2]*=sc1; oacc[d][3]*=sc1; }

        #pragma unroll
        for(int kv=0;kv<8;kv++){
            uint32_t pa[4];
            pa[0]=pack2h(sacc[2*kv][0],   sacc[2*kv][1]);
            pa[1]=pack2h(sacc[2*kv][2],   sacc[2*kv][3]);
            pa[2]=pack2h(sacc[2*kv+1][0], sacc[2*kv+1][1]);
            pa[3]=pack2h(sacc[2*kv+1][2], sacc[2*kv+1][3]);
            uint32_t vbase = sb + 18432 + (uint32_t)((16*kv + lq + 8*(quad&1))*PITCH + 16*(quad>>1));
            #pragma unroll
            for(int jp=0;jp<4;jp++){
                uint32_t vh4[4];
                LDM4T(vh4, vbase + jp*32);
                MMAB(oacc[2*jp],   pa, vh4[0], vh4[1]);
                MMAB(oacc[2*jp+1], pa, vh4[2], vh4[3]);
            }
        }
        if(++st==3) st=0;
    }

    float inv0=1.f/l0, inv1=1.f/l1;
    long long orow0 = (long long)zb*SD + (long long)(q0+r0l)*DMODEL + zh*64;
    long long orow1 = orow0 + 8LL*DMODEL;
    #pragma unroll
    for(int d=0;d<8;d++){
        int col = d*8 + 2*(lane&3);
        *(uint32_t*)(ch+orow0+col)=pack2h(oacc[d][0]*inv0, oacc[d][1]*inv0);
        *(uint32_t*)(ch+orow1+col)=pack2h(oacc[d][2]*inv1, oacc[d][3]*inv1);
    }
}

// ---------------- support kernels ----------------
__global__ void cvt_h(const float* __restrict__ in, hf* __restrict__ hi, int n4){
    int i=blockIdx.x*blockDim.x+threadIdx.x; if(i>=n4)return;
    float4 v=((const float4*)in)[i];
    ((uint32_t*)hi)[2*i]  =pack2h(v.x,v.y);
    ((uint32_t*)hi)[2*i+1]=pack2h(v.z,v.w);
}
__global__ void split_T(const float* __restrict__ W, hf* __restrict__ hi, int R, int C){
    __shared__ float t[32][33];
    int c0=blockIdx.x*32, r0=blockIdx.y*32, tx=threadIdx.x, ty=threadIdx.y;
    for(int i=ty;i<32;i+=8) t[i][tx]=W[(long long)(r0+i)*C+c0+tx];
    __syncthreads();
    for(int i=ty;i<32;i+=8)
        hi[(long long)(c0+i)*R+r0+tx]=__float2half_rn(t[tx][i]);
}
__global__ void gatek(const hf* __restrict__ qh,
                      const float* __restrict__ gW,const float* __restrict__ gb,
                      float* __restrict__ gate){
    int warp=(blockIdx.x*blockDim.x+threadIdx.x)>>5, lane=threadIdx.x&31;
    if(warp>=ROWS*NHEADS)return;
    int bs=warp>>4,h=warp&15;
    long long base=(long long)bs*DMODEL+h*DKH;
    float q0=__half2float(qh[base+lane]);
    float q1=__half2float(qh[base+lane+32]);
    float s=q0*gW[lane]+q1*gW[lane+32];
    #pragma unroll
    for(int o=16;o;o>>=1)s+=__shfl_xor_sync(~0u,s,o);
    if(lane==0){int b=bs>>11,sr=bs&2047;
        gate[(long long)(b*NHEADS+h)*SSEQ+sr]=1.f/(1.f+expf(-(s+gb[0])));}
}
__device__ __forceinline__ float wSum(float v){
    #pragma unroll
    for(int o=16;o;o>>=1)v+=__shfl_xor_sync(~0u,v,o); return v;}

__global__ void __launch_bounds__(256) layernorm_k(const float* __restrict__ a,
    const float* __restrict__ resid, const float* __restrict__ g, const float* __restrict__ b,
    float* __restrict__ outf, hf* __restrict__ oh){
    long long row=blockIdx.x;
    const float* pa=a+row*DMODEL;
    const float* pr=resid?resid+row*DMODEL:nullptr;
    int t=threadIdx.x,lane=t&31,wid=t>>5;
    __shared__ float s1[8],s2a[8]; __shared__ float bm,brs;
    float v[4],s=0.f,s2=0.f;
    #pragma unroll
    for(int i=0;i<4;i++){int d=t+i*256;float x=pa[d]+(pr?pr[d]:0.f);v[i]=x;s+=x;s2+=x*x;}
    s=wSum(s);s2=wSum(s2);
    if(lane==0){s1[wid]=s;s2a[wid]=s2;} __syncthreads();
    if(wid==0){float xs=(lane<8)?s1[lane]:0.f,x2=(lane<8)?s2a[lane]:0.f;
        xs=wSum(xs);x2=wSum(x2);
        if(lane==0){float mean=xs*(1.f/DMODEL);float var=fmaxf(x2*(1.f/DMODEL)-mean*mean,0.f);
            bm=mean;brs=rsqrtf(var+1e-5f);}}
    __syncthreads();
    float mean=bm,rstd=brs;
    #pragma unroll
    for(int i=0;i<4;i++){int d=t+i*256;float y=(v[i]-mean)*rstd*g[d]+b[d];
        if(outf)outf[row*DMODEL+d]=y;
        if(oh)oh[row*DMODEL+d]=__float2half_rn(y);}
}

__global__ void __launch_bounds__(256) layernorm2_k(const float* __restrict__ t0,
    const float* __restrict__ x,
    const float* __restrict__ lag, const float* __restrict__ lab,
    const float* __restrict__ n1g, const float* __restrict__ n1b,
    float* __restrict__ x1, hf* __restrict__ oh){
    long long row=blockIdx.x;
    const float* pa=t0+row*DMODEL;
    const float* px=x+row*DMODEL;
    int t=threadIdx.x,lane=t&31,wid=t>>5;
    __shared__ float s1[8],s2a[8]; __shared__ float bm,brs;
    float v[4],s=0.f,s2=0.f;
    #pragma unroll
    for(int i=0;i<4;i++){int d=t+i*256;float xx=pa[d];v[i]=xx;s+=xx;s2+=xx*xx;}
    s=wSum(s);s2=wSum(s2);
    if(lane==0){s1[wid]=s;s2a[wid]=s2;} __syncthreads();
    if(wid==0){float xs=(lane<8)?s1[lane]:0.f,x2=(lane<8)?s2a[lane]:0.f;
        xs=wSum(xs);x2=wSum(x2);
        if(lane==0){float mean=xs*(1.f/DMODEL);float var=fmaxf(x2*(1.f/DMODEL)-mean*mean,0.f);
            bm=mean;brs=rsqrtf(var+1e-5f);}}
    __syncthreads();
    float mean=bm,rstd=brs;
    s=0.f; s2=0.f;
    #pragma unroll
    for(int i=0;i<4;i++){int d=t+i*256;
        float y=(v[i]-mean)*rstd*lag[d]+lab[d] + px[d];
        v[i]=y; s+=y; s2+=y*y;}
    __syncthreads();
    s=wSum(s);s2=wSum(s2);
    if(lane==0){s1[wid]=s;s2a[wid]=s2;} __syncthreads();
    if(wid==0){float xs=(lane<8)?s1[lane]:0.f,x2=(lane<8)?s2a[lane]:0.f;
        xs=wSum(xs);x2=wSum(x2);
        if(lane==0){float mean2=xs*(1.f/DMODEL);float var=fmaxf(x2*(1.f/DMODEL)-mean2*mean2,0.f);
            bm=mean2;brs=rsqrtf(var+1e-5f);}}
    __syncthreads();
    mean=bm; rstd=brs;
    #pragma unroll
    for(int i=0;i<4;i++){int d=t+i*256;
        float y=(v[i]-mean)*rstd*n1g[d]+n1b[d];
        x1[row*DMODEL+d]=y;
        oh[row*DMODEL+d]=__float2half_rn(y);}
}

// ---------------- launch ----------------
extern "C" void kernel_launch(void* const* d_in, const int* in_sizes, int n_in,
                              void* d_out, int out_size)
{
    const float* x   =(const float*)d_in[0];
    const int*  mask =(const int*)  d_in[1];
    const float* Wq=(const float*)d_in[2],  *bq=(const float*)d_in[3];
    const float* Wk=(const float*)d_in[4],  *bk=(const float*)d_in[5];
    const float* Wv=(const float*)d_in[6],  *bv=(const float*)d_in[7];
    const float* Wo=(const float*)d_in[8],  *bo=(const float*)d_in[9];
    const float* temp=(const float*)d_in[10], *tw=(const float*)d_in[11];
    const float* gW=(const float*)d_in[12], *gb=(const float*)d_in[13];
    const float* lag=(const float*)d_in[14],*lab=(const float*)d_in[15];
    const float* f1W=(const float*)d_in[16],*f1b=(const float*)d_in[17];
    const float* f2W=(const float*)d_in[18],*f2b=(const float*)d_in[19];
    const float* n1g=(const float*)d_in[20],*n1b=(const float*)d_in[21];
    const float* n2g=(const float*)d_in[22],*n2b=(const float*)d_in[23];
    float* out=(float*)d_out;

    float *t0,*x1,*gatep;
    hf *xh,*qh,*kh,*vh,*ch,*yh,*fh;
    hf *wqh,*wkh,*wvh,*woh,*w1h,*w2h;
    cudaGetSymbolAddress((void**)&t0,g_t0);   cudaGetSymbolAddress((void**)&x1,g_x1);
    cudaGetSymbolAddress((void**)&gatep,g_gate);
    cudaGetSymbolAddress((void**)&xh,g_xh);
    cudaGetSymbolAddress((void**)&qh,g_qh); cudaGetSymbolAddress((void**)&kh,g_kh);
    cudaGetSymbolAddress((void**)&vh,g_vh); cudaGetSymbolAddress((void**)&ch,g_ch);
    cudaGetSymbolAddress((void**)&yh,g_yh); cudaGetSymbolAddress((void**)&fh,g_fh);
    cudaGetSymbolAddress((void**)&wqh,g_wqh); cudaGetSymbolAddress((void**)&wkh,g_wkh);
    cudaGetSymbolAddress((void**)&wvh,g_wvh); cudaGetSymbolAddress((void**)&woh,g_woh);
    cudaGetSymbolAddress((void**)&w1h,g_w1h); cudaGetSymbolAddress((void**)&w2h,g_w2h);

    const int SMG = 3*2*10240;                 // 61440
    const int SMF = 18432 + 3*36864;           // 129024
    cudaFuncSetAttribute((const void*)hgemm,    cudaFuncAttributeMaxDynamicSharedMemorySize,SMG);
    cudaFuncSetAttribute((const void*)flashattn,cudaFuncAttributeMaxDynamicSharedMemorySize,SMF);

    dim3 tb(32,8);
    // my launches 0-3 (+1 harness pre-launch = ncu idx 1-4)
    cvt_h<<<ROWS*DMODEL/4/256,256>>>(x,xh,ROWS*DMODEL/4);                    // 0
    split_T<<<dim3(DMODEL/32,DMODEL/32),tb>>>(Wq,wqh,DMODEL,DMODEL);         // 1
    split_T<<<dim3(DMODEL/32,DMODEL/32),tb>>>(Wk,wkh,DMODEL,DMODEL);         // 2
    split_T<<<dim3(DMODEL/32,DMODEL/32),tb>>>(Wv,wvh,DMODEL,DMODEL);         // 3

    // my launch 4 -> ncu launch index 5: Q projection hgemm
    dim3 gP(DMODEL/128,ROWS/128,1);
    hgemm<<<gP,256,SMG>>>(xh,wqh,DMODEL,DMODEL,DMODEL,DMODEL,
        nullptr,qh,bq,tw,0,1);                                               // 4
    hgemm<<<gP,256,SMG>>>(xh,wkh,DMODEL,DMODEL,DMODEL,DMODEL,
        nullptr,kh,bk,nullptr,0,1);
    hgemm<<<gP,256,SMG>>>(xh,wvh,DMODEL,DMODEL,DMODEL,DMODEL,
        nullptr,vh,bv,nullptr,0,1);

    gatek<<<(ROWS*NHEADS)/8,256>>>(qh,gW,gb,gatep);

    dim3 gA(SSEQ/128, ZTOT, 1);
    flashattn<<<gA,256,SMF>>>(qh,kh,vh,mask,gatep,temp,ch);

    split_T<<<dim3(DMODEL/32,DMODEL/32),tb>>>(Wo,woh,DMODEL,DMODEL);
    hgemm<<<gP,256,SMG>>>(ch,woh,DMODEL,DMODEL,DMODEL,DMODEL,
        t0,nullptr,bo,nullptr,0,0);
    layernorm2_k<<<ROWS,256>>>(t0,x,lag,lab,n1g,n1b,x1,yh);

    split_T<<<dim3(DFF/32,DMODEL/32),tb>>>(f1W,w1h,DMODEL,DFF);
    split_T<<<dim3(DMODEL/32,DFF/32),tb>>>(f2W,w2h,DFF,DMODEL);

    dim3 gF(DFF/128,ROWS/128,1);
    hgemm<<<gF,256,SMG>>>(yh,w1h,DMODEL,DMODEL,DMODEL,DFF,
        nullptr,fh,f1b,nullptr,1,1);
    hgemm<<<gP,256,SMG>>>(fh,w2h,DFF,DFF,DFF,DMODEL,
        t0,nullptr,f2b,nullptr,0,0);

    layernorm_k<<<ROWS,256>>>(x1,t0,n2g,n2b,out,nullptr);
}

// round 11
// speedup vs baseline: 11.0874x; 1.1333x over previous
#include <cuda_runtime.h>
#include <cuda_fp16.h>
#include <math.h>
#include <stdint.h>

#define SSEQ 2048
#define DMODEL 1024
#define NHEADS 16
#define DKH 64
#define DFF 4096
#define ROWS 4096
#define ZTOT 32
#define SD ((long long)SSEQ*DMODEL)
typedef __half hf;

// ---------------- scratch ----------------
__device__ __align__(256) float g_t0[ROWS*DMODEL];
__device__ __align__(256) float g_x1[ROWS*DMODEL];
__device__ __align__(256) float g_gate[ZTOT*SSEQ];
__device__ __align__(256) unsigned char g_mflag[256];   // [qtile][ktile] all-ones flags
__device__ __align__(256) hf g_xh[ROWS*DMODEL];
__device__ __align__(256) hf g_qh[ROWS*DMODEL];
__device__ __align__(256) hf g_kh[ROWS*DMODEL];
__device__ __align__(256) hf g_vh[ROWS*DMODEL];
__device__ __align__(256) hf g_ch[ROWS*DMODEL];
__device__ __align__(256) hf g_yh[ROWS*DMODEL];
__device__ __align__(256) hf g_fh[ROWS*DFF];
__device__ __align__(256) hf g_wqh[DMODEL*DMODEL];
__device__ __align__(256) hf g_wkh[DMODEL*DMODEL];
__device__ __align__(256) hf g_wvh[DMODEL*DMODEL];
__device__ __align__(256) hf g_woh[DMODEL*DMODEL];
__device__ __align__(256) hf g_w1h[DMODEL*DFF];
__device__ __align__(256) hf g_w2h[DMODEL*DFF];

// ---------------- helpers ----------------
__device__ __forceinline__ uint32_t su32(const void* p){uint32_t a;
    asm("{.reg .u64 t; cvta.to.shared.u64 t,%1; cvt.u32.u64 %0,t;}":"=r"(a):"l"(p));return a;}
__device__ __forceinline__ void cpa(uint32_t d,const void*s){
    asm volatile("cp.async.cg.shared.global [%0],[%1],16;"::"r"(d),"l"(s));}
#define CPCOMMIT() asm volatile("cp.async.commit_group;":::"memory")
#define LDM4(f,a) asm volatile("ldmatrix.sync.aligned.m8n8.x4.shared.b16 {%0,%1,%2,%3},[%4];" \
    :"=r"((f)[0]),"=r"((f)[1]),"=r"((f)[2]),"=r"((f)[3]):"r"(a))
#define LDM4B(b0,b1,b2,b3,a) asm volatile("ldmatrix.sync.aligned.m8n8.x4.shared.b16 {%0,%1,%2,%3},[%4];" \
    :"=r"(b0),"=r"(b1),"=r"(b2),"=r"(b3):"r"(a))
#define LDM4T(f,a) asm volatile("ldmatrix.sync.aligned.m8n8.x4.trans.shared.b16 {%0,%1,%2,%3},[%4];" \
    :"=r"((f)[0]),"=r"((f)[1]),"=r"((f)[2]),"=r"((f)[3]):"r"(a))
#define MMA(c,A,B) asm volatile( \
    "mma.sync.aligned.m16n8k16.row.col.f32.f16.f16.f32 {%0,%1,%2,%3},{%4,%5,%6,%7},{%8,%9},{%0,%1,%2,%3};" \
    :"+f"((c)[0]),"+f"((c)[1]),"+f"((c)[2]),"+f"((c)[3]) \
    :"r"((A)[0]),"r"((A)[1]),"r"((A)[2]),"r"((A)[3]),"r"((B)[0]),"r"((B)[1]))
#define MMAB(c,A,b0,b1) asm volatile( \
    "mma.sync.aligned.m16n8k16.row.col.f32.f16.f16.f32 {%0,%1,%2,%3},{%4,%5,%6,%7},{%8,%9},{%0,%1,%2,%3};" \
    :"+f"((c)[0]),"+f"((c)[1]),"+f"((c)[2]),"+f"((c)[3]) \
    :"r"((A)[0]),"r"((A)[1]),"r"((A)[2]),"r"((A)[3]),"r"(b0),"r"(b1))

__device__ __forceinline__ uint32_t pack2h(float a, float b){
    __half2 hp=__floats2half2_rn(a,b);
    return *(uint32_t*)&hp;
}

// ---------------- fp16 HMMA GEMM core (shared by hgemm / hgemm3) ----------
template<bool QKV3>
__device__ __forceinline__ void hgemm_body(
    const hf* __restrict__ A_, const hf* __restrict__ B_,
    int K, int lda, int ldb, int ldc,
    float* __restrict__ Cf, hf* __restrict__ Ch,
    const float* __restrict__ bias, const float* __restrict__ bias2,
    int epi, int outm)
{
    constexpr int STG = 2*10240;
    extern __shared__ char smraw[];
    uint32_t su = su32(smraw);
    int tid = threadIdx.x, wid = tid>>5, lane = tid&31;
    int wm = wid%2, wn = wid/2;
    int m0 = blockIdx.y*128, n0 = blockIdx.x*128;

    const hf* pA = A_ + (long long)m0*lda;
    const hf* pB = B_ + (long long)n0*ldb;
    int nk = K>>5;

    int r = tid>>2, sg = tid&3;
    auto loadstage = [&](int ci, int st){
        uint32_t b = su + (uint32_t)st*STG;
        int k0 = ci<<5;
        #pragma unroll
        for(int p=0;p<2;p++){
            int rr = r + p*64;
            cpa(b + rr*80 + sg*16,         pA + (long long)rr*lda + k0 + sg*8);
            cpa(b + 10240 + rr*80 + sg*16, pB + (long long)rr*ldb + k0 + sg*8);
        }
        CPCOMMIT();
    };

    float acc[4][4][4];
    #pragma unroll
    for(int a=0;a<4;a++)
        #pragma unroll
        for(int b=0;b<4;b++)
            #pragma unroll
            for(int c=0;c<4;c++) acc[a][b][c]=0.f;

    int quad = lane>>3, lq = lane&7;
    uint32_t aoff = (uint32_t)((wm*64 + (quad&1)*8 + lq)*80 + (quad>>1)*16);
    uint32_t boff = (uint32_t)(10240 + (wn*32 + (quad>>1)*8 + lq)*80 + (quad&1)*16);

    loadstage(0,0);
    if(nk>1) loadstage(1,1);

    int st = 0;
    for(int i=0;i<nk;i++){
        if(i+1<nk) asm volatile("cp.async.wait_group 1;":::"memory");
        else       asm volatile("cp.async.wait_group 0;":::"memory");
        __syncthreads();
        if(i+2<nk){
            int st2 = st+2; if(st2>=3) st2-=3;
            loadstage(i+2, st2);
        }
        uint32_t sb = su + (uint32_t)st*STG;
        uint32_t pa = sb + aoff, pb = sb + boff;
        uint32_t Af[4][4], Bf[4][2];
        #pragma unroll
        for(int ks=0;ks<2;ks++){
            uint32_t kso = ks*32;
            #pragma unroll
            for(int mt=0;mt<4;mt++) LDM4(Af[mt], pa + mt*1280 + kso);
            #pragma unroll
            for(int np=0;np<2;np++)
                LDM4B(Bf[2*np][0],Bf[2*np][1],Bf[2*np+1][0],Bf[2*np+1][1], pb + np*1280 + kso);
            #pragma unroll
            for(int mt=0;mt<4;mt++)
                #pragma unroll
                for(int nt=0;nt<4;nt++) MMA(acc[mt][nt],Af[mt],Bf[nt]);
        }
        if(++st==3) st=0;
    }

    auto store2 = [&](int row,int col,float v0,float v1){
        if(bias){ v0+=bias[col]; v1+=bias[col+1]; }
        if(bias2){ v0+=bias2[col]; v1+=bias2[col+1]; }
        if(epi==1){
            v0 = 0.5f*v0*(1.0f+erff(v0*0.70710678118654752f));
            v1 = 0.5f*v1*(1.0f+erff(v1*0.70710678118654752f));
        }
        if(outm==0){
            *(float2*)&Cf[(long long)row*ldc+col] = make_float2(v0,v1);
        } else {
            *(uint32_t*)(Ch+(long long)row*ldc+col) = pack2h(v0,v1);
        }
    };
    #pragma unroll
    for(int mt=0;mt<4;mt++){
        #pragma unroll
        for(int nt=0;nt<4;nt++){
            int row0 = m0 + wm*64 + mt*16 + (lane>>2);
            int col  = n0 + wn*32 + nt*8 + ((lane&3)<<1);
            store2(row0,   col, acc[mt][nt][0], acc[mt][nt][1]);
            store2(row0+8, col, acc[mt][nt][2], acc[mt][nt][3]);
        }
    }
}

__global__ __launch_bounds__(256,2) void hgemm(
    const hf* __restrict__ A_, const hf* __restrict__ B_,
    int K, int lda, int ldb, int ldc,
    float* __restrict__ Cf, hf* __restrict__ Ch,
    const float* __restrict__ bias, const float* __restrict__ bias2,
    int epi, int outm)
{
    hgemm_body<false>(A_,B_,K,lda,ldb,ldc,Cf,Ch,bias,bias2,epi,outm);
}

// fused Q/K/V projections: blockIdx.z selects weight/output/bias
__global__ __launch_bounds__(256,2) void hgemm3(
    const hf* __restrict__ A_,
    const hf* __restrict__ Bq, const hf* __restrict__ Bk, const hf* __restrict__ Bv,
    hf* __restrict__ Cq, hf* __restrict__ Ck, hf* __restrict__ Cv,
    const float* __restrict__ bq, const float* __restrict__ bk, const float* __restrict__ bv,
    const float* __restrict__ tw)
{
    int z = blockIdx.z;
    const hf* B = (z==0)?Bq:(z==1)?Bk:Bv;
    hf* C = (z==0)?Cq:(z==1)?Ck:Cv;
    const float* bias = (z==0)?bq:(z==1)?bk:bv;
    const float* bias2 = (z==0)?tw:nullptr;
    hgemm_body<true>(A_,B,DMODEL,DMODEL,DMODEL,DMODEL,nullptr,C,bias,bias2,0,1);
}

// ---------------- flash attention (fp16, 3-stage K/V ring, mask flags) ----
#define PITCH 144
__global__ __launch_bounds__(256,1) void flashattn(
    const hf* __restrict__ qh_, const hf* __restrict__ kh_, const hf* __restrict__ vh_,
    const int* __restrict__ mask, const unsigned char* __restrict__ mflag,
    const float* __restrict__ gate,
    const float* __restrict__ temp, hf* __restrict__ ch)
{
    extern __shared__ char sm[];
    uint32_t su = su32(sm);
    const uint32_t ST=18432, STSZ=36864;
    int tid=threadIdx.x, wid=tid>>5, lane=tid&31;
    int quad=lane>>3, lq=lane&7;
    int z=blockIdx.y, zb=z>>4, zh=z&15;
    int q0=blockIdx.x*128;
    long long hoff=(long long)zb*SD + zh*64;
    const hf* pq = qh_ + hoff + (long long)q0*DMODEL;

    int cc=tid&7, rr0=tid>>3;
    #pragma unroll
    for(int p=0;p<4;p++){
        int r=rr0+p*32;
        cpa(su + r*PITCH + cc*16, pq + (long long)r*DMODEL + cc*8);
    }
    CPCOMMIT();

    auto ldstage=[&](int it,int st){
        uint32_t b=su+ST+(uint32_t)st*STSZ;
        long long kbase=hoff + (long long)(it*128)*DMODEL;
        #pragma unroll
        for(int p=0;p<4;p++){
            int r=rr0+p*32;
            long long go=kbase+(long long)r*DMODEL+cc*8;
            uint32_t so=r*PITCH+cc*16;
            cpa(b+so, kh_+go);
            cpa(b+18432+so, vh_+go);
        }
        CPCOMMIT();
    };
    ldstage(0,0); ldstage(1,1);
    asm volatile("cp.async.wait_group 2;":::"memory");
    __syncthreads();

    uint32_t qaddr = su + (uint32_t)((wid*16 + (quad&1)*8 + lq)*PITCH + (quad>>1)*16);
    uint32_t qf[4][4];
    #pragma unroll
    for(int ks=0;ks<4;ks++) LDM4(qf[ks], qaddr+ks*32);

    int r0l = wid*16 + (lane>>2);
    float g0 = gate[(long long)z*SSEQ + q0 + r0l];
    float g1 = gate[(long long)z*SSEQ + q0 + r0l + 8];
    float invT = 1.f/temp[0];
    float m0=-1e30f,m1=-1e30f,l0=0.f,l1=0.f;
    float oacc[8][4];
    #pragma unroll
    for(int d=0;d<8;d++){oacc[d][0]=0;oacc[d][1]=0;oacc[d][2]=0;oacc[d][3]=0;}

    int st = 0;
    for(int it=0; it<16; it++){
        if(it<15) asm volatile("cp.async.wait_group 1;":::"memory");
        else      asm volatile("cp.async.wait_group 0;":::"memory");
        __syncthreads();
        if(it+2<16){
            int st2 = st+2; if(st2>=3) st2-=3;
            ldstage(it+2, st2);
        }
        uint32_t sb = su+ST+(uint32_t)st*STSZ;

        float sacc[16][4];
        #pragma unroll
        for(int nt=0;nt<16;nt++){sacc[nt][0]=0;sacc[nt][1]=0;sacc[nt][2]=0;sacc[nt][3]=0;}
        uint32_t baddr = sb + (uint32_t)((lq + 8*(quad>>1))*PITCH + (quad&1)*16);
        #pragma unroll
        for(int ks=0;ks<4;ks++){
            uint32_t b[16][2];
            #pragma unroll
            for(int j=0;j<8;j++)
                LDM4B(b[2*j][0],b[2*j][1],b[2*j+1][0],b[2*j+1][1], baddr + j*(16*PITCH) + ks*32);
            #pragma unroll
            for(int nt=0;nt<16;nt++) MMA(sacc[nt], qf[ks], b[nt]);
        }

        float rm0=-1e30f, rm1=-1e30f;
        if(mflag[(q0>>7)*16 + it]){
            // all-ones tile: no mask loads; same op order (s*invT, then *g)
            #pragma unroll
            for(int nt=0;nt<16;nt++){
                float s0=sacc[nt][0]*invT, s1=sacc[nt][1]*invT;
                float s2=sacc[nt][2]*invT, s3=sacc[nt][3]*invT;
                s0*=g0;s1*=g0;s2*=g1;s3*=g1;
                sacc[nt][0]=s0;sacc[nt][1]=s1;sacc[nt][2]=s2;sacc[nt][3]=s3;
                rm0=fmaxf(rm0,fmaxf(s0,s1)); rm1=fmaxf(rm1,fmaxf(s2,s3));
            }
        } else {
            long long mrow0 = (long long)(q0 + r0l)*SSEQ + it*128 + 2*(lane&3);
            long long mrow1 = mrow0 + 8LL*SSEQ;
            #pragma unroll
            for(int nt=0;nt<16;nt++){
                int2 mA = *(const int2*)&mask[mrow0 + nt*8];
                int2 mB = *(const int2*)&mask[mrow1 + nt*8];
                float s0=sacc[nt][0]*invT, s1=sacc[nt][1]*invT;
                float s2=sacc[nt][2]*invT, s3=sacc[nt][3]*invT;
                if(mA.x==0)s0=-1e9f; if(mA.y==0)s1=-1e9f;
                if(mB.x==0)s2=-1e9f; if(mB.y==0)s3=-1e9f;
                s0*=g0;s1*=g0;s2*=g1;s3*=g1;
                sacc[nt][0]=s0;sacc[nt][1]=s1;sacc[nt][2]=s2;sacc[nt][3]=s3;
                rm0=fmaxf(rm0,fmaxf(s0,s1)); rm1=fmaxf(rm1,fmaxf(s2,s3));
            }
        }
        rm0=fmaxf(rm0,__shfl_xor_sync(~0u,rm0,1)); rm0=fmaxf(rm0,__shfl_xor_sync(~0u,rm0,2));
        rm1=fmaxf(rm1,__shfl_xor_sync(~0u,rm1,1)); rm1=fmaxf(rm1,__shfl_xor_sync(~0u,rm1,2));
        float mn0=fmaxf(m0,rm0), mn1=fmaxf(m1,rm1);
        float sc0=__expf(m0-mn0), sc1=__expf(m1-mn1);
        m0=mn0; m1=mn1;

        float rs0=0.f, rs1=0.f;
        #pragma unroll
        for(int nt=0;nt<16;nt++){
            float p0=__expf(sacc[nt][0]-m0), p1=__expf(sacc[nt][1]-m0);
            float p2=__expf(sacc[nt][2]-m1), p3=__expf(sacc[nt][3]-m1);
            sacc[nt][0]=p0;sacc[nt][1]=p1;sacc[nt][2]=p2;sacc[nt][3]=p3;
            rs0+=p0+p1; rs1+=p2+p3;
        }
        rs0+=__shfl_xor_sync(~0u,rs0,1); rs0+=__shfl_xor_sync(~0u,rs0,2);
        rs1+=__shfl_xor_sync(~0u,rs1,1); rs1+=__shfl_xor_sync(~0u,rs1,2);
        l0 = l0*sc0 + rs0; l1 = l1*sc1 + rs1;
        #pragma unroll
        for(int d=0;d<8;d++){ oacc[d][0]*=sc0; oacc[d][1]*=sc0; oacc[d][2]*=sc1; oacc[d][3]*=sc1; }

        #pragma unroll
        for(int kv=0;kv<8;kv++){
            uint32_t pa[4];
            pa[0]=pack2h(sacc[2*kv][0],   sacc[2*kv][1]);
            pa[1]=pack2h(sacc[2*kv][2],   sacc[2*kv][3]);
            pa[2]=pack2h(sacc[2*kv+1][0], sacc[2*kv+1][1]);
            pa[3]=pack2h(sacc[2*kv+1][2], sacc[2*kv+1][3]);
            uint32_t vbase = sb + 18432 + (uint32_t)((16*kv + lq + 8*(quad&1))*PITCH + 16*(quad>>1));
            #pragma unroll
            for(int jp=0;jp<4;jp++){
                uint32_t vh4[4];
                LDM4T(vh4, vbase + jp*32);
                MMAB(oacc[2*jp],   pa, vh4[0], vh4[1]);
                MMAB(oacc[2*jp+1], pa, vh4[2], vh4[3]);
            }
        }
        if(++st==3) st=0;
    }

    float inv0=1.f/l0, inv1=1.f/l1;
    long long orow0 = (long long)zb*SD + (long long)(q0+r0l)*DMODEL + zh*64;
    long long orow1 = orow0 + 8LL*DMODEL;
    #pragma unroll
    for(int d=0;d<8;d++){
        int col = d*8 + 2*(lane&3);
        *(uint32_t*)(ch+orow0+col)=pack2h(oacc[d][0]*inv0, oacc[d][1]*inv0);
        *(uint32_t*)(ch+orow1+col)=pack2h(oacc[d][2]*inv1, oacc[d][3]*inv1);
    }
}

// ---------------- support kernels ----------------
// per-128x128-tile all-ones flag for the mask
__global__ void maskflag_k(const int* __restrict__ mask, unsigned char* __restrict__ flag){
    __shared__ int ok;
    if(threadIdx.x==0) ok=1;
    __syncthreads();
    int ty = blockIdx.x>>4, tx = blockIdx.x&15;
    int row = ty*128 + (threadIdx.x>>1);
    int c0  = tx*128 + (threadIdx.x&1)*64;
    const int4* p = (const int4*)&mask[(long long)row*SSEQ + c0];
    int good = 1;
    #pragma unroll
    for(int i=0;i<16;i++){
        int4 v = p[i];
        good &= (v.x!=0)&(v.y!=0)&(v.z!=0)&(v.w!=0);
    }
    if(!good) atomicAnd(&ok, 0);
    __syncthreads();
    if(threadIdx.x==0) flag[blockIdx.x]=(unsigned char)ok;
}
__global__ void cvt_h(const float* __restrict__ in, hf* __restrict__ hi, int n4){
    int i=blockIdx.x*blockDim.x+threadIdx.x; if(i>=n4)return;
    float4 v=((const float4*)in)[i];
    ((uint32_t*)hi)[2*i]  =pack2h(v.x,v.y);
    ((uint32_t*)hi)[2*i+1]=pack2h(v.z,v.w);
}
// 4-way fused weight transpose (all 1024x1024)
__global__ void split_T4(const float* __restrict__ W0,const float* __restrict__ W1,
                         const float* __restrict__ W2,const float* __restrict__ W3,
                         hf* __restrict__ H0,hf* __restrict__ H1,
                         hf* __restrict__ H2,hf* __restrict__ H3){
    const float* W = (blockIdx.z==0)?W0:(blockIdx.z==1)?W1:(blockIdx.z==2)?W2:W3;
    hf* H = (blockIdx.z==0)?H0:(blockIdx.z==1)?H1:(blockIdx.z==2)?H2:H3;
    __shared__ float t[32][33];
    int c0=blockIdx.x*32, r0=blockIdx.y*32, tx=threadIdx.x, ty=threadIdx.y;
    for(int i=ty;i<32;i+=8) t[i][tx]=W[(long long)(r0+i)*DMODEL+c0+tx];
    __syncthreads();
    for(int i=ty;i<32;i+=8)
        H[(long long)(c0+i)*DMODEL+r0+tx]=__float2half_rn(t[tx][i]);
}
__global__ void split_T(const float* __restrict__ W, hf* __restrict__ hi, int R, int C){
    __shared__ float t[32][33];
    int c0=blockIdx.x*32, r0=blockIdx.y*32, tx=threadIdx.x, ty=threadIdx.y;
    for(int i=ty;i<32;i+=8) t[i][tx]=W[(long long)(r0+i)*C+c0+tx];
    __syncthreads();
    for(int i=ty;i<32;i+=8)
        hi[(long long)(c0+i)*R+r0+tx]=__float2half_rn(t[tx][i]);
}
__global__ void gatek(const hf* __restrict__ qh,
                      const float* __restrict__ gW,const float* __restrict__ gb,
                      float* __restrict__ gate){
    int warp=(blockIdx.x*blockDim.x+threadIdx.x)>>5, lane=threadIdx.x&31;
    if(warp>=ROWS*NHEADS)return;
    int bs=warp>>4,h=warp&15;
    long long base=(long long)bs*DMODEL+h*DKH;
    float q0=__half2float(qh[base+lane]);
    float q1=__half2float(qh[base+lane+32]);
    float s=q0*gW[lane]+q1*gW[lane+32];
    #pragma unroll
    for(int o=16;o;o>>=1)s+=__shfl_xor_sync(~0u,s,o);
    if(lane==0){int b=bs>>11,sr=bs&2047;
        gate[(long long)(b*NHEADS+h)*SSEQ+sr]=1.f/(1.f+expf(-(s+gb[0])));}
}
__device__ __forceinline__ float wSum(float v){
    #pragma unroll
    for(int o=16;o;o>>=1)v+=__shfl_xor_sync(~0u,v,o); return v;}

__global__ void __launch_bounds__(256) layernorm_k(const float* __restrict__ a,
    const float* __restrict__ resid, const float* __restrict__ g, const float* __restrict__ b,
    float* __restrict__ outf, hf* __restrict__ oh){
    long long row=blockIdx.x;
    const float* pa=a+row*DMODEL;
    const float* pr=resid?resid+row*DMODEL:nullptr;
    int t=threadIdx.x,lane=t&31,wid=t>>5;
    __shared__ float s1[8],s2a[8]; __shared__ float bm,brs;
    float v[4],s=0.f,s2=0.f;
    #pragma unroll
    for(int i=0;i<4;i++){int d=t+i*256;float x=pa[d]+(pr?pr[d]:0.f);v[i]=x;s+=x;s2+=x*x;}
    s=wSum(s);s2=wSum(s2);
    if(lane==0){s1[wid]=s;s2a[wid]=s2;} __syncthreads();
    if(wid==0){float xs=(lane<8)?s1[lane]:0.f,x2=(lane<8)?s2a[lane]:0.f;
        xs=wSum(xs);x2=wSum(x2);
        if(lane==0){float mean=xs*(1.f/DMODEL);float var=fmaxf(x2*(1.f/DMODEL)-mean*mean,0.f);
            bm=mean;brs=rsqrtf(var+1e-5f);}}
    __syncthreads();
    float mean=bm,rstd=brs;
    #pragma unroll
    for(int i=0;i<4;i++){int d=t+i*256;float y=(v[i]-mean)*rstd*g[d]+b[d];
        if(outf)outf[row*DMODEL+d]=y;
        if(oh)oh[row*DMODEL+d]=__float2half_rn(y);}
}

__global__ void __launch_bounds__(256) layernorm2_k(const float* __restrict__ t0,
    const float* __restrict__ x,
    const float* __restrict__ lag, const float* __restrict__ lab,
    const float* __restrict__ n1g, const float* __restrict__ n1b,
    float* __restrict__ x1, hf* __restrict__ oh){
    long long row=blockIdx.x;
    const float* pa=t0+row*DMODEL;
    const float* px=x+row*DMODEL;
    int t=threadIdx.x,lane=t&31,wid=t>>5;
    __shared__ float s1[8],s2a[8]; __shared__ float bm,brs;
    float v[4],s=0.f,s2=0.f;
    #pragma unroll
    for(int i=0;i<4;i++){int d=t+i*256;float xx=pa[d];v[i]=xx;s+=xx;s2+=xx*xx;}
    s=wSum(s);s2=wSum(s2);
    if(lane==0){s1[wid]=s;s2a[wid]=s2;} __syncthreads();
    if(wid==0){float xs=(lane<8)?s1[lane]:0.f,x2=(lane<8)?s2a[lane]:0.f;
        xs=wSum(xs);x2=wSum(x2);
        if(lane==0){float mean=xs*(1.f/DMODEL);float var=fmaxf(x2*(1.f/DMODEL)-mean*mean,0.f);
            bm=mean;brs=rsqrtf(var+1e-5f);}}
    __syncthreads();
    float mean=bm,rstd=brs;
    s=0.f; s2=0.f;
    #pragma unroll
    for(int i=0;i<4;i++){int d=t+i*256;
        float y=(v[i]-mean)*rstd*lag[d]+lab[d] + px[d];
        v[i]=y; s+=y; s2+=y*y;}
    __syncthreads();
    s=wSum(s);s2=wSum(s2);
    if(lane==0){s1[wid]=s;s2a[wid]=s2;} __syncthreads();
    if(wid==0){float xs=(lane<8)?s1[lane]:0.f,x2=(lane<8)?s2a[lane]:0.f;
        xs=wSum(xs);x2=wSum(x2);
        if(lane==0){float mean2=xs*(1.f/DMODEL);float var=fmaxf(x2*(1.f/DMODEL)-mean2*mean2,0.f);
            bm=mean2;brs=rsqrtf(var+1e-5f);}}
    __syncthreads();
    mean=bm; rstd=brs;
    #pragma unroll
    for(int i=0;i<4;i++){int d=t+i*256;
        float y=(v[i]-mean)*rstd*n1g[d]+n1b[d];
        x1[row*DMODEL+d]=y;
        oh[row*DMODEL+d]=__float2half_rn(y);}
}

// ---------------- launch ----------------
extern "C" void kernel_launch(void* const* d_in, const int* in_sizes, int n_in,
                              void* d_out, int out_size)
{
    const float* x   =(const float*)d_in[0];
    const int*  mask =(const int*)  d_in[1];
    const float* Wq=(const float*)d_in[2],  *bq=(const float*)d_in[3];
    const float* Wk=(const float*)d_in[4],  *bk=(const float*)d_in[5];
    const float* Wv=(const float*)d_in[6],  *bv=(const float*)d_in[7];
    const float* Wo=(const float*)d_in[8],  *bo=(const float*)d_in[9];
    const float* temp=(const float*)d_in[10], *tw=(const float*)d_in[11];
    const float* gW=(const float*)d_in[12], *gb=(const float*)d_in[13];
    const float* lag=(const float*)d_in[14],*lab=(const float*)d_in[15];
    const float* f1W=(const float*)d_in[16],*f1b=(const float*)d_in[17];
    const float* f2W=(const float*)d_in[18],*f2b=(const float*)d_in[19];
    const float* n1g=(const float*)d_in[20],*n1b=(const float*)d_in[21];
    const float* n2g=(const float*)d_in[22],*n2b=(const float*)d_in[23];
    float* out=(float*)d_out;

    float *t0,*x1,*gatep;
    unsigned char* mflag;
    hf *xh,*qh,*kh,*vh,*ch,*yh,*fh;
    hf *wqh,*wkh,*wvh,*woh,*w1h,*w2h;
    cudaGetSymbolAddress((void**)&t0,g_t0);   cudaGetSymbolAddress((void**)&x1,g_x1);
    cudaGetSymbolAddress((void**)&gatep,g_gate);
    cudaGetSymbolAddress((void**)&mflag,g_mflag);
    cudaGetSymbolAddress((void**)&xh,g_xh);
    cudaGetSymbolAddress((void**)&qh,g_qh); cudaGetSymbolAddress((void**)&kh,g_kh);
    cudaGetSymbolAddress((void**)&vh,g_vh); cudaGetSymbolAddress((void**)&ch,g_ch);
    cudaGetSymbolAddress((void**)&yh,g_yh); cudaGetSymbolAddress((void**)&fh,g_fh);
    cudaGetSymbolAddress((void**)&wqh,g_wqh); cudaGetSymbolAddress((void**)&wkh,g_wkh);
    cudaGetSymbolAddress((void**)&wvh,g_wvh); cudaGetSymbolAddress((void**)&woh,g_woh);
    cudaGetSymbolAddress((void**)&w1h,g_w1h); cudaGetSymbolAddress((void**)&w2h,g_w2h);

    const int SMG = 3*2*10240;                 // 61440
    const int SMF = 18432 + 3*36864;           // 129024
    cudaFuncSetAttribute((const void*)hgemm,    cudaFuncAttributeMaxDynamicSharedMemorySize,SMG);
    cudaFuncSetAttribute((const void*)hgemm3,   cudaFuncAttributeMaxDynamicSharedMemorySize,SMG);
    cudaFuncSetAttribute((const void*)flashattn,cudaFuncAttributeMaxDynamicSharedMemorySize,SMF);

    dim3 tb(32,8);
    cvt_h<<<ROWS*DMODEL/4/256,256>>>(x,xh,ROWS*DMODEL/4);
    maskflag_k<<<256,256>>>(mask,mflag);
    split_T4<<<dim3(DMODEL/32,DMODEL/32,4),tb>>>(Wq,Wk,Wv,Wo,wqh,wkh,wvh,woh);

    // fused Q/K/V projections
    dim3 gP3(DMODEL/128,ROWS/128,3);
    hgemm3<<<gP3,256,SMG>>>(xh,wqh,wkh,wvh,qh,kh,vh,bq,bk,bv,tw);

    gatek<<<(ROWS*NHEADS)/8,256>>>(qh,gW,gb,gatep);

    dim3 gA(SSEQ/128, ZTOT, 1);
    flashattn<<<gA,256,SMF>>>(qh,kh,vh,mask,mflag,gatep,temp,ch);

    dim3 gP(DMODEL/128,ROWS/128,1);
    hgemm<<<gP,256,SMG>>>(ch,woh,DMODEL,DMODEL,DMODEL,DMODEL,
        t0,nullptr,bo,nullptr,0,0);
    layernorm2_k<<<ROWS,256>>>(t0,x,lag,lab,n1g,n1b,x1,yh);

    split_T<<<dim3(DFF/32,DMODEL/32),tb>>>(f1W,w1h,DMODEL,DFF);
    split_T<<<dim3(DMODEL/32,DFF/32),tb>>>(f2W,w2h,DFF,DMODEL);

    dim3 gF(DFF/128,ROWS/128,1);
    hgemm<<<gF,256,SMG>>>(yh,w1h,DMODEL,DMODEL,DMODEL,DFF,
        nullptr,fh,f1b,nullptr,1,1);
    hgemm<<<gP,256,SMG>>>(fh,w2h,DFF,DFF,DFF,DMODEL,
        t0,nullptr,f2b,nullptr,0,0);

    layernorm_k<<<ROWS,256>>>(x1,t0,n2g,n2b,out,nullptr);
}